// round 7
// baseline (speedup 1.0000x reference)
#include <cuda_runtime.h>
#include <cuda_bf16.h>
#include <math.h>
#include <stdint.h>

// ---------------- problem constants ----------------
constexpr int T    = 2048;
constexpr int HID  = 4096;
constexpr int NH   = 32;
constexpr int DQ   = 256;
constexpr int DN   = 192;
constexpr int DR   = 64;
constexpr int DV   = 256;
constexpr int DKV  = 512;
constexpr int QLORA= 2048;
constexpr int HDQ  = NH * DQ;        // 8192
constexpr int KVW  = NH * (DN + DV); // 14336
constexpr int LATW = DKV + DR;       // 576

// ---------------- fp32 scratch ----------------
__device__ float g_qlora[(size_t)T * QLORA];
__device__ float g_latent[(size_t)T * LATW];
__device__ float g_q[(size_t)T * HDQ];
__device__ float g_kv[(size_t)T * KVW];
__device__ float g_O[(size_t)T * HDQ];

// ---------------- split-bf16 planes ----------------
__device__ __nv_bfloat16 g_hid_p [2][(size_t)T * HID];
__device__ __nv_bfloat16 g_wqaT  [2][(size_t)QLORA * HID];
__device__ __nv_bfloat16 g_wkvaT [2][(size_t)LATW * HID];
__device__ __nv_bfloat16 g_wqbT  [2][(size_t)HDQ * QLORA];
__device__ __nv_bfloat16 g_wkvbT [2][(size_t)KVW * DKV];
__device__ __nv_bfloat16 g_woT   [2][(size_t)HID * HDQ];
__device__ __nv_bfloat16 g_qlo_p [2][(size_t)T * QLORA];
__device__ __nv_bfloat16 g_lat_p [2][(size_t)T * DKV];
__device__ __nv_bfloat16 g_q_p   [2][(size_t)T * HDQ];
__device__ __nv_bfloat16 g_Kc_p  [2][(size_t)T * HDQ];
__device__ __nv_bfloat16 g_Vt_p  [2][(size_t)NH * DV * T];
__device__ __nv_bfloat16 g_O_p   [2][(size_t)T * HDQ];

// ---------------- helpers ----------------
__device__ __forceinline__ void splitf(float v, __nv_bfloat16& h, __nv_bfloat16& l) {
    h = __float2bfloat16_rn(v);
    l = __float2bfloat16_rn(v - __bfloat162float(h));
}

__device__ __forceinline__ uint32_t pack2(__nv_bfloat16 a, __nv_bfloat16 b) {
    return ((uint32_t)__bfloat16_as_ushort(b) << 16) | (uint32_t)__bfloat16_as_ushort(a);
}

__device__ __forceinline__ void mma_bf16(float* c, const uint32_t* a, const uint32_t* b) {
    asm volatile(
        "mma.sync.aligned.m16n8k16.row.col.f32.bf16.bf16.f32 "
        "{%0,%1,%2,%3}, {%4,%5,%6,%7}, {%8,%9}, {%0,%1,%2,%3};\n"
        : "+f"(c[0]), "+f"(c[1]), "+f"(c[2]), "+f"(c[3])
        : "r"(a[0]), "r"(a[1]), "r"(a[2]), "r"(a[3]), "r"(b[0]), "r"(b[1]));
}

__device__ __forceinline__ void ldsm4(uint32_t& r0, uint32_t& r1, uint32_t& r2, uint32_t& r3, uint32_t a) {
    asm volatile("ldmatrix.sync.aligned.m8n8.x4.shared.b16 {%0,%1,%2,%3}, [%4];"
        : "=r"(r0), "=r"(r1), "=r"(r2), "=r"(r3) : "r"(a));
}

__device__ __forceinline__ void cp16(uint32_t d, const void* s) {
    asm volatile("cp.async.cg.shared.global [%0], [%1], 16;" :: "r"(d), "l"(s));
}

// ============================================================================
// Split-bf16 GEMM v2: C = A @ B^T on hi/lo planes.
// Block 128x128, BK=32, 128 threads (4 warps, warp tile 64x64), 2 CTAs/SM.
// Per ks-step: 16 ldsm4 -> 96 HMMA (6:1).  smem identical to R3 layout.
// ============================================================================
constexpr int TILE_B   = 128 * 80;
constexpr int STAGE_B  = 4 * TILE_B;
constexpr int SMEM_GEMM = 2 * STAGE_B;   // 81920

__global__ __launch_bounds__(128, 2) void tgemm_pl(
    const __nv_bfloat16* __restrict__ Ah, const __nv_bfloat16* __restrict__ Al,
    const __nv_bfloat16* __restrict__ Bh, const __nv_bfloat16* __restrict__ Bl,
    float* __restrict__ C,
    int M, int N, int K, int lda, int ldb, int ldc,
    long sA, long sB, long sC)
{
    const int bx = blockIdx.x, by = blockIdx.y;
    Ah += (long)blockIdx.z * sA;  Al += (long)blockIdx.z * sA;
    Bh += (long)blockIdx.z * sB;  Bl += (long)blockIdx.z * sB;
    C  += (long)blockIdx.z * sC;

    extern __shared__ char smem[];
    const uint32_t sb = (uint32_t)__cvta_generic_to_shared(smem);

    const int tid = threadIdx.x, lane = tid & 31, warp = tid >> 5;
    const int wm = warp & 1, wn = warp >> 1;          // 2 x 2 warp grid
    const int g = lane >> 2, t4 = lane & 3;

    const int r0 = tid >> 2, c4 = tid & 3;            // loader coords
    const int Nm1 = N - 1;

    const int lr  = (lane & 7) + ((lane >> 3) & 1) * 8;
    const int lkb = (lane >> 4) * 16;
    const uint32_t aBase = sb + (uint32_t)((wm * 64 + lr) * 80 + lkb);
    const uint32_t bBase = sb + (uint32_t)(2 * TILE_B + (wn * 64 + lr) * 80 + lkb);

    float acc[4][8][4] = {};
    const int nchunks = K / 32;

    auto load_chunk = [&](int k0, uint32_t st) {
        #pragma unroll
        for (int c = 0; c < 4; c++) {
            int row = r0 + c * 32;
            uint32_t ds = sb + st + (uint32_t)(row * 80 + c4 * 16);
            long aoff = (long)(by * 128 + row) * lda + k0 + c4 * 8;
            cp16(ds,              Ah + aoff);
            cp16(ds + TILE_B,     Al + aoff);
            int nr = bx * 128 + row; if (nr > Nm1) nr = Nm1;
            long boff = (long)nr * ldb + k0 + c4 * 8;
            cp16(ds + 2 * TILE_B, Bh + boff);
            cp16(ds + 3 * TILE_B, Bl + boff);
        }
    };

    load_chunk(0, 0);
    asm volatile("cp.async.commit_group;");

    for (int i = 0; i < nchunks; i++) {
        if (i + 1 < nchunks)
            load_chunk((i + 1) * 32, (uint32_t)(((i + 1) & 1) * STAGE_B));
        asm volatile("cp.async.commit_group;");
        asm volatile("cp.async.wait_group 1;");
        __syncthreads();

        const uint32_t sof = (uint32_t)((i & 1) * STAGE_B);
        #pragma unroll
        for (int ks = 0; ks < 2; ks++) {
            uint32_t ah[4][4], al[4][4];
            #pragma unroll
            for (int mt = 0; mt < 4; mt++) {
                uint32_t ad = aBase + sof + (uint32_t)(mt * 16 * 80 + ks * 32);
                ldsm4(ah[mt][0], ah[mt][1], ah[mt][2], ah[mt][3], ad);
                ldsm4(al[mt][0], al[mt][1], al[mt][2], al[mt][3], ad + TILE_B);
            }
            #pragma unroll
            for (int hf = 0; hf < 2; hf++) {
                uint32_t bh[4][2], bl[4][2];
                #pragma unroll
                for (int p = 0; p < 2; p++) {
                    uint32_t bd = bBase + sof + (uint32_t)((hf * 32 + p * 16) * 80 + ks * 32);
                    uint32_t x0, x1, x2, x3;
                    ldsm4(x0, x1, x2, x3, bd);
                    bh[2*p][0] = x0; bh[2*p+1][0] = x1; bh[2*p][1] = x2; bh[2*p+1][1] = x3;
                    ldsm4(x0, x1, x2, x3, bd + TILE_B);
                    bl[2*p][0] = x0; bl[2*p+1][0] = x1; bl[2*p][1] = x2; bl[2*p+1][1] = x3;
                }
                #pragma unroll
                for (int mt = 0; mt < 4; mt++) {
                    #pragma unroll
                    for (int nt = 0; nt < 4; nt++) {
                        float* c = acc[mt][hf * 4 + nt];
                        mma_bf16(c, ah[mt], bh[nt]);
                        mma_bf16(c, ah[mt], bl[nt]);
                        mma_bf16(c, al[mt], bh[nt]);
                    }
                }
            }
        }
        __syncthreads();
    }

    #pragma unroll
    for (int mt = 0; mt < 4; mt++) {
        int r = by * 128 + wm * 64 + mt * 16 + g;
        #pragma unroll
        for (int nt = 0; nt < 8; nt++) {
            int c = bx * 128 + wn * 64 + nt * 8 + 2 * t4;
            if (c < N) {
                *(float2*)&C[(long)r * ldc + c]       = make_float2(acc[mt][nt][0], acc[mt][nt][1]);
                *(float2*)&C[(long)(r + 8) * ldc + c] = make_float2(acc[mt][nt][2], acc[mt][nt][3]);
            }
        }
    }
}

// ============================================================================
// Fused flash attention (unchanged from R6)
// ============================================================================
constexpr int FA_SMEM = 81920;
constexpr int QPL = 10240;
constexpr int VPL = 128 * 272;

__global__ __launch_bounds__(256, 1) void flash_k(
    const __nv_bfloat16* __restrict__ Qh, const __nv_bfloat16* __restrict__ Ql,
    const __nv_bfloat16* __restrict__ Kh, const __nv_bfloat16* __restrict__ Kl,
    const __nv_bfloat16* __restrict__ Vh, const __nv_bfloat16* __restrict__ Vl,
    float* __restrict__ O)
{
    const int qi = gridDim.x - 1 - blockIdx.x;
    const int h  = blockIdx.y;

    extern __shared__ char smem[];
    const uint32_t sb = (uint32_t)__cvta_generic_to_shared(smem);

    const int tid = threadIdx.x, lane = tid & 31, w = tid >> 5;
    const int g = lane >> 2, t4 = lane & 3;
    const int lr  = (lane & 7) + ((lane >> 3) & 1) * 8;
    const int lkb = (lane >> 4) * 16;

    float oacc[32][4];
    #pragma unroll
    for (int i = 0; i < 32; i++)
        #pragma unroll
        for (int c = 0; c < 4; c++) oacc[i][c] = 0.f;
    float m0 = -1e30f, m1 = -1e30f, l0 = 0.f, l1 = 0.f;

    const float scale = 0.0625f;

    for (int j = 0; j <= qi; j++) {
        float sacc[16][4] = {};

        auto load_qk = [&](int i, uint32_t st) {
            const int d = i * 32;
            #pragma unroll
            for (int p = 0; p < 2; p++) {
                int id = tid + p * 256;
                int row = id >> 2, cc = id & 3;
                uint32_t dst = sb + st + (uint32_t)(row * 80 + cc * 16);
                size_t qo = (size_t)(qi * 128 + row) * HDQ + h * DQ + d + cc * 8;
                cp16(dst,           Qh + qo);
                cp16(dst + QPL,     Ql + qo);
                size_t ko = (size_t)(j * 128 + row) * HDQ + h * DQ + d + cc * 8;
                cp16(dst + 2 * QPL, Kh + ko);
                cp16(dst + 3 * QPL, Kl + ko);
            }
        };

        load_qk(0, 0);
        asm volatile("cp.async.commit_group;");
        load_qk(1, 4 * QPL);
        asm volatile("cp.async.commit_group;");

        for (int i = 0; i < 8; i++) {
            asm volatile("cp.async.wait_group 1;");
            __syncthreads();
            const uint32_t st = (uint32_t)((i & 1) * 4 * QPL);
            #pragma unroll
            for (int ks = 0; ks < 2; ks++) {
                uint32_t ah[4], al[4];
                uint32_t ad = sb + st + (uint32_t)((w * 16 + lr) * 80 + lkb + ks * 32);
                ldsm4(ah[0], ah[1], ah[2], ah[3], ad);
                ldsm4(al[0], al[1], al[2], al[3], ad + QPL);
                #pragma unroll
                for (int p = 0; p < 8; p++) {
                    uint32_t bh[2][2], bl[2][2], x0, x1, x2, x3;
                    uint32_t bd = sb + st + (uint32_t)(2 * QPL + (p * 16 + lr) * 80 + lkb + ks * 32);
                    ldsm4(x0, x1, x2, x3, bd);
                    bh[0][0] = x0; bh[1][0] = x1; bh[0][1] = x2; bh[1][1] = x3;
                    ldsm4(x0, x1, x2, x3, bd + QPL);
                    bl[0][0] = x0; bl[1][0] = x1; bl[0][1] = x2; bl[1][1] = x3;
                    #pragma unroll
                    for (int q2 = 0; q2 < 2; q2++) {
                        float* c = sacc[p * 2 + q2];
                        mma_bf16(c, ah, bh[q2]);
                        mma_bf16(c, ah, bl[q2]);
                        mma_bf16(c, al, bh[q2]);
                    }
                }
            }
            __syncthreads();
            if (i + 2 < 8) load_qk(i + 2, st);
            asm volatile("cp.async.commit_group;");
        }
        asm volatile("cp.async.wait_group 0;");

        #pragma unroll
        for (int nt = 0; nt < 16; nt++)
            #pragma unroll
            for (int c = 0; c < 4; c++) sacc[nt][c] *= scale;

        if (j == qi) {
            const int rr0 = w * 16 + g, rr1 = rr0 + 8;
            #pragma unroll
            for (int nt = 0; nt < 16; nt++) {
                int col = nt * 8 + 2 * t4;
                if (col     > rr0) sacc[nt][0] = -1e30f;
                if (col + 1 > rr0) sacc[nt][1] = -1e30f;
                if (col     > rr1) sacc[nt][2] = -1e30f;
                if (col + 1 > rr1) sacc[nt][3] = -1e30f;
            }
        }

        float tm0 = -1e30f, tm1 = -1e30f;
        #pragma unroll
        for (int nt = 0; nt < 16; nt++) {
            tm0 = fmaxf(tm0, fmaxf(sacc[nt][0], sacc[nt][1]));
            tm1 = fmaxf(tm1, fmaxf(sacc[nt][2], sacc[nt][3]));
        }
        tm0 = fmaxf(tm0, __shfl_xor_sync(0xffffffffu, tm0, 1));
        tm0 = fmaxf(tm0, __shfl_xor_sync(0xffffffffu, tm0, 2));
        tm1 = fmaxf(tm1, __shfl_xor_sync(0xffffffffu, tm1, 1));
        tm1 = fmaxf(tm1, __shfl_xor_sync(0xffffffffu, tm1, 2));

        float nm0 = fmaxf(m0, tm0), nm1 = fmaxf(m1, tm1);
        float a0 = expf(m0 - nm0), a1 = expf(m1 - nm1);
        m0 = nm0; m1 = nm1;

        float s0 = 0.f, s1 = 0.f;
        #pragma unroll
        for (int nt = 0; nt < 16; nt++) {
            sacc[nt][0] = expf(sacc[nt][0] - m0); s0 += sacc[nt][0];
            sacc[nt][1] = expf(sacc[nt][1] - m0); s0 += sacc[nt][1];
            sacc[nt][2] = expf(sacc[nt][2] - m1); s1 += sacc[nt][2];
            sacc[nt][3] = expf(sacc[nt][3] - m1); s1 += sacc[nt][3];
        }
        s0 += __shfl_xor_sync(0xffffffffu, s0, 1);
        s0 += __shfl_xor_sync(0xffffffffu, s0, 2);
        s1 += __shfl_xor_sync(0xffffffffu, s1, 1);
        s1 += __shfl_xor_sync(0xffffffffu, s1, 2);
        l0 = l0 * a0 + s0;
        l1 = l1 * a1 + s1;

        #pragma unroll
        for (int i = 0; i < 32; i++) {
            oacc[i][0] *= a0; oacc[i][1] *= a0;
            oacc[i][2] *= a1; oacc[i][3] *= a1;
        }

        uint32_t Pf0[8][4], Pf1[8][4];
        #pragma unroll
        for (int ks = 0; ks < 8; ks++) {
            #pragma unroll
            for (int hf = 0; hf < 2; hf++) {
                const float* c = sacc[2 * ks + hf];
                __nv_bfloat16 ha, la, hb, lb;
                splitf(c[0], ha, la); splitf(c[1], hb, lb);
                Pf0[ks][hf * 2]     = pack2(ha, hb);
                Pf1[ks][hf * 2]     = pack2(la, lb);
                splitf(c[2], ha, la); splitf(c[3], hb, lb);
                Pf0[ks][hf * 2 + 1] = pack2(ha, hb);
                Pf1[ks][hf * 2 + 1] = pack2(la, lb);
            }
        }

        #pragma unroll
        for (int dvc = 0; dvc < 2; dvc++) {
            __syncthreads();
            #pragma unroll
            for (int p = 0; p < 8; p++) {
                int id = tid + p * 256;
                int row = id >> 4, cc = id & 15;
                uint32_t dst = sb + (uint32_t)(row * 272 + cc * 16);
                size_t vo = (size_t)h * DV * T + (size_t)(dvc * 128 + row) * T + j * 128 + cc * 8;
                cp16(dst,       Vh + vo);
                cp16(dst + VPL, Vl + vo);
            }
            asm volatile("cp.async.commit_group;");
            asm volatile("cp.async.wait_group 0;");
            __syncthreads();

            #pragma unroll
            for (int ks = 0; ks < 8; ks++) {
                #pragma unroll
                for (int p = 0; p < 8; p++) {
                    uint32_t vh[2][2], vl[2][2], x0, x1, x2, x3;
                    uint32_t bd = sb + (uint32_t)((p * 16 + lr) * 272 + lkb + ks * 32);
                    ldsm4(x0, x1, x2, x3, bd);
                    vh[0][0] = x0; vh[1][0] = x1; vh[0][1] = x2; vh[1][1] = x3;
                    ldsm4(x0, x1, x2, x3, bd + VPL);
                    vl[0][0] = x0; vl[1][0] = x1; vl[0][1] = x2; vl[1][1] = x3;
                    #pragma unroll
                    for (int q2 = 0; q2 < 2; q2++) {
                        float* c = oacc[dvc * 16 + p * 2 + q2];
                        mma_bf16(c, Pf0[ks], vh[q2]);
                        mma_bf16(c, Pf0[ks], vl[q2]);
                        mma_bf16(c, Pf1[ks], vh[q2]);
                    }
                }
            }
        }
        __syncthreads();
    }

    const float i0 = 1.f / l0, i1 = 1.f / l1;
    const int r0 = qi * 128 + w * 16 + g;
    float* o0 = O + (size_t)r0 * HDQ + h * DV;
    float* o1 = o0 + (size_t)8 * HDQ;
    #pragma unroll
    for (int nt = 0; nt < 32; nt++) {
        int c = nt * 8 + 2 * t4;
        *(float2*)&o0[c] = make_float2(oacc[nt][0] * i0, oacc[nt][1] * i0);
        *(float2*)&o1[c] = make_float2(oacc[nt][2] * i1, oacc[nt][3] * i1);
    }
}

// ---------------- fp32 -> planes ----------------
__global__ void conv_pl_k(const float* __restrict__ x, __nv_bfloat16* __restrict__ h,
                          __nv_bfloat16* __restrict__ l, long n)
{
    long i = (long)blockIdx.x * blockDim.x + threadIdx.x;
    long stride = (long)gridDim.x * blockDim.x;
    for (; i < n; i += stride) {
        __nv_bfloat16 hh, ll;
        splitf(x[i], hh, ll);
        h[i] = hh; l[i] = ll;
    }
}

// ---------------- fp32 [R,C] -> planes transposed [C,R] ----------------
__global__ void conv_tr_k(const float* __restrict__ x, __nv_bfloat16* __restrict__ h,
                          __nv_bfloat16* __restrict__ l, int R, int C)
{
    __shared__ float tile[32][33];
    const int c0 = blockIdx.x * 32, rr0 = blockIdx.y * 32;
    const int tx = threadIdx.x & 31, ty = threadIdx.x >> 5;
    #pragma unroll
    for (int i = 0; i < 4; i++) {
        int r = rr0 + ty + i * 8;
        tile[ty + i * 8][tx] = x[(long)r * C + c0 + tx];
    }
    __syncthreads();
    #pragma unroll
    for (int i = 0; i < 4; i++) {
        int c = c0 + ty + i * 8;
        float v = tile[tx][ty + i * 8];
        long o = (long)c * R + rr0 + tx;
        __nv_bfloat16 hh, ll;
        splitf(v, hh, ll);
        h[o] = hh; l[o] = ll;
    }
}

// ---------------- RMSNorm fp32 -> planes ----------------
__global__ void rmsnorm_pl_k(const float* __restrict__ x, const float* __restrict__ w,
                             __nv_bfloat16* __restrict__ h, __nv_bfloat16* __restrict__ l,
                             int N, int ldin)
{
    const float* p = x + (long)blockIdx.x * ldin;
    __shared__ float red[8];
    __shared__ float bc;
    const int lane = threadIdx.x & 31, wid = threadIdx.x >> 5;

    float s = 0.f;
    for (int j = threadIdx.x; j < N; j += blockDim.x) { float v = p[j]; s += v * v; }
    #pragma unroll
    for (int o = 16; o; o >>= 1) s += __shfl_xor_sync(0xffffffffu, s, o);
    if (lane == 0) red[wid] = s;
    __syncthreads();
    if (threadIdx.x == 0) {
        float v = 0.f;
        for (int wI = 0; wI < 8; wI++) v += red[wI];
        bc = rsqrtf(v / N + 1e-6f);
    }
    __syncthreads();
    float r = bc;
    long ob = (long)blockIdx.x * N;
    for (int j = threadIdx.x; j < N; j += blockDim.x) {
        __nv_bfloat16 hh, ll;
        splitf(p[j] * r * w[j], hh, ll);
        h[ob + j] = hh; l[ob + j] = ll;
    }
}

// ---------------- rope k_pe in-place ----------------
__global__ void rope_kpe_k(float* __restrict__ lat, const int* __restrict__ pos)
{
    const int tt = blockIdx.x, i = threadIdx.x;
    double inv = pow(10000.0, -(double)i / 32.0);
    double sd, cd;
    sincos((double)pos[tt] * inv, &sd, &cd);
    float c = (float)cd, s = (float)sd;
    float* p = lat + (long)tt * LATW + DKV;
    float x1 = p[i], x2 = p[i + 32];
    p[i]      = x1 * c - x2 * s;
    p[i + 32] = x2 * c + x1 * s;
}

// ---------------- q: rope fused + planes ----------------
__global__ void rope_conv_q_k(const float* __restrict__ q, const int* __restrict__ pos,
                              __nv_bfloat16* __restrict__ h, __nv_bfloat16* __restrict__ l)
{
    const int tt = blockIdx.x;
    __shared__ float cs[32], sn[32];
    if (threadIdx.x < 32) {
        double inv = pow(10000.0, -(double)threadIdx.x / 32.0);
        double sd, cd;
        sincos((double)pos[tt] * inv, &sd, &cd);
        cs[threadIdx.x] = (float)cd; sn[threadIdx.x] = (float)sd;
    }
    __syncthreads();
    const float* row = q + (long)tt * HDQ;
    long ob = (long)tt * HDQ;
    for (int x = threadIdx.x; x < HDQ; x += blockDim.x) {
        int d = x & 255;
        float v;
        if (d < DN)            v = row[x];
        else if (d < DN + 32) { int i = d - DN;       v = row[x] * cs[i] - row[x + 32] * sn[i]; }
        else                  { int i = d - DN - 32;  v = row[x] * cs[i] + row[x - 32] * sn[i]; }
        __nv_bfloat16 hh, ll;
        splitf(v, hh, ll);
        h[ob + x] = hh; l[ob + x] = ll;
    }
}

// ---------------- K assembly -> planes ----------------
__global__ void build_K_pl_k(const float* __restrict__ kv, const float* __restrict__ lat,
                             __nv_bfloat16* __restrict__ h, __nv_bfloat16* __restrict__ l)
{
    const int tt = blockIdx.x;
    long ob = (long)tt * HDQ;
    for (int x = threadIdx.x; x < HDQ; x += blockDim.x) {
        int hd = x >> 8, d = x & 255;
        float v = (d < DN) ? kv[(long)tt * KVW + hd * (DN + DV) + d]
                           : lat[(long)tt * LATW + DKV + (d - DN)];
        __nv_bfloat16 hh, ll;
        splitf(v, hh, ll);
        h[ob + x] = hh; l[ob + x] = ll;
    }
}

// ---------------- V transpose per head -> planes [h][DV][T] ----------------
__global__ void transpose_v_pl_k(const float* __restrict__ kv,
                                 __nv_bfloat16* __restrict__ h, __nv_bfloat16* __restrict__ l)
{
    __shared__ float tile[32][33];
    const int d0 = blockIdx.x * 32, t0 = blockIdx.y * 32, hd = blockIdx.z;
    const int tx = threadIdx.x & 31, ty = threadIdx.x >> 5;
    #pragma unroll
    for (int i = 0; i < 4; i++) {
        int tr = t0 + ty + i * 8;
        tile[ty + i * 8][tx] = kv[(long)tr * KVW + hd * (DN + DV) + DN + d0 + tx];
    }
    __syncthreads();
    #pragma unroll
    for (int i = 0; i < 4; i++) {
        int d = d0 + ty + i * 8;
        float v = tile[tx][ty + i * 8];
        long o = (long)hd * DV * T + (long)d * T + t0 + tx;
        __nv_bfloat16 hh, ll;
        splitf(v, hh, ll);
        h[o] = hh; l[o] = ll;
    }
}

// ---------------- launch ----------------
extern "C" void kernel_launch(void* const* d_in, const int* in_sizes, int n_in,
                              void* d_out, int out_size)
{
    (void)in_sizes; (void)n_in; (void)out_size;
    const float* hidden = (const float*)d_in[0];
    const int*   pos    = (const int*)  d_in[1];
    const float* wq_a   = (const float*)d_in[2];
    const float* q_ln   = (const float*)d_in[3];
    const float* wq_b   = (const float*)d_in[4];
    const float* wkv_a  = (const float*)d_in[5];
    const float* kv_ln  = (const float*)d_in[6];
    const float* wkv_b  = (const float*)d_in[7];
    const float* wo     = (const float*)d_in[8];
    float* out = (float*)d_out;

    cudaFuncSetAttribute(tgemm_pl, cudaFuncAttributeMaxDynamicSharedMemorySize, SMEM_GEMM);
    cudaFuncSetAttribute(flash_k,  cudaFuncAttributeMaxDynamicSharedMemorySize, FA_SMEM);

    float *qlora, *latent, *q, *kv, *O;
    cudaGetSymbolAddress((void**)&qlora,  g_qlora);
    cudaGetSymbolAddress((void**)&latent, g_latent);
    cudaGetSymbolAddress((void**)&q,      g_q);
    cudaGetSymbolAddress((void**)&kv,     g_kv);
    cudaGetSymbolAddress((void**)&O,      g_O);

    __nv_bfloat16 *hidp, *wqaT, *wkvaT, *wqbT, *wkvbT, *woT,
                  *qlop, *latp, *qp, *Kcp, *Vtp, *Op;
    cudaGetSymbolAddress((void**)&hidp,  g_hid_p);
    cudaGetSymbolAddress((void**)&wqaT,  g_wqaT);
    cudaGetSymbolAddress((void**)&wkvaT, g_wkvaT);
    cudaGetSymbolAddress((void**)&wqbT,  g_wqbT);
    cudaGetSymbolAddress((void**)&wkvbT, g_wkvbT);
    cudaGetSymbolAddress((void**)&woT,   g_woT);
    cudaGetSymbolAddress((void**)&qlop,  g_qlo_p);
    cudaGetSymbolAddress((void**)&latp,  g_lat_p);
    cudaGetSymbolAddress((void**)&qp,    g_q_p);
    cudaGetSymbolAddress((void**)&Kcp,   g_Kc_p);
    cudaGetSymbolAddress((void**)&Vtp,   g_Vt_p);
    cudaGetSymbolAddress((void**)&Op,    g_O_p);

    #define PL(base, n) (base), ((base) + (size_t)(n))

    const size_t nHid = (size_t)T * HID,    nWqa = (size_t)QLORA * HID;
    const size_t nWkva= (size_t)LATW * HID, nWqb = (size_t)HDQ * QLORA;
    const size_t nWkvb= (size_t)KVW * DKV,  nWo  = (size_t)HID * HDQ;
    const size_t nQlo = (size_t)T * QLORA,  nLat = (size_t)T * DKV;
    const size_t nQ   = (size_t)T * HDQ;
    const size_t nVt  = (size_t)NH * DV * T;

    dim3 blk(256), blkG(128);

    // ---- weight conversion + transpose ----
    conv_tr_k<<<dim3(QLORA/32, HID/32), blk>>>(wq_a,  PL(wqaT,  nWqa), HID, QLORA);
    conv_tr_k<<<dim3(LATW/32,  HID/32), blk>>>(wkv_a, PL(wkvaT, nWkva), HID, LATW);
    conv_tr_k<<<dim3(HDQ/32, QLORA/32), blk>>>(wq_b,  PL(wqbT,  nWqb), QLORA, HDQ);
    conv_tr_k<<<dim3(KVW/32,  DKV/32),  blk>>>(wkv_b, PL(wkvbT, nWkvb), DKV, KVW);
    conv_tr_k<<<dim3(HID/32,  HDQ/32),  blk>>>(wo,    PL(woT,   nWo),  HDQ, HID);
    conv_pl_k<<<2048, 256>>>(hidden, PL(hidp, nHid), (long)nHid);

    // ---- down projections ----
    tgemm_pl<<<dim3(QLORA/128, T/128), blkG, SMEM_GEMM>>>(PL(hidp, nHid), PL(wqaT, nWqa),
        qlora, T, QLORA, HID, HID, HID, QLORA, 0, 0, 0);
    tgemm_pl<<<dim3((LATW+127)/128, T/128), blkG, SMEM_GEMM>>>(PL(hidp, nHid), PL(wkvaT, nWkva),
        latent, T, LATW, HID, HID, HID, LATW, 0, 0, 0);

    // ---- norms + rope(k_pe) ----
    rmsnorm_pl_k<<<T, 256>>>(qlora, q_ln, PL(qlop, nQlo), QLORA, QLORA);
    rope_kpe_k<<<T, 32>>>(latent, pos);
    rmsnorm_pl_k<<<T, 256>>>(latent, kv_ln, PL(latp, nLat), DKV, LATW);

    // ---- up projections ----
    tgemm_pl<<<dim3(HDQ/128, T/128), blkG, SMEM_GEMM>>>(PL(qlop, nQlo), PL(wqbT, nWqb),
        q, T, HDQ, QLORA, QLORA, QLORA, HDQ, 0, 0, 0);
    tgemm_pl<<<dim3(KVW/128, T/128), blkG, SMEM_GEMM>>>(PL(latp, nLat), PL(wkvbT, nWkvb),
        kv, T, KVW, DKV, DKV, DKV, KVW, 0, 0, 0);

    // ---- q rope + planes; K assembly; V transpose ----
    rope_conv_q_k<<<T, 256>>>(q, pos, PL(qp, nQ));
    build_K_pl_k<<<T, 256>>>(kv, latent, PL(Kcp, nQ));
    transpose_v_pl_k<<<dim3(DV/32, T/32, NH), blk>>>(kv, PL(Vtp, nVt));

    // ---- fused flash attention ----
    flash_k<<<dim3(T/128, NH), blk, FA_SMEM>>>(
        PL(qp, nQ), PL(Kcp, nQ), PL(Vtp, nVt), O);

    // ---- O planes + final projection ----
    conv_pl_k<<<2048, 256>>>(O, PL(Op, nQ), (long)nQ);
    tgemm_pl<<<dim3(HID/128, T/128), blkG, SMEM_GEMM>>>(PL(Op, nQ), PL(woT, nWo),
        out, T, HID, HDQ, HDQ, HDQ, HID, 0, 0, 0);

    #undef PL
}

// round 8
// speedup vs baseline: 1.1237x; 1.1237x over previous
#include <cuda_runtime.h>
#include <cuda_bf16.h>
#include <cuda_fp16.h>
#include <math.h>
#include <stdint.h>

// ---------------- problem constants ----------------
constexpr int T    = 2048;
constexpr int HID  = 4096;
constexpr int NH   = 32;
constexpr int DQ   = 256;
constexpr int DN   = 192;
constexpr int DR   = 64;
constexpr int DV   = 256;
constexpr int DKV  = 512;
constexpr int QLORA= 2048;
constexpr int HDQ  = NH * DQ;        // 8192
constexpr int KVW  = NH * (DN + DV); // 14336
constexpr int LATW = DKV + DR;       // 576

// ---------------- fp32 scratch ----------------
__device__ float g_qlora[(size_t)T * QLORA];
__device__ float g_latent[(size_t)T * LATW];
__device__ float g_q[(size_t)T * HDQ];
__device__ float g_kv[(size_t)T * KVW];

// ---------------- split-bf16 planes ----------------
__device__ __nv_bfloat16 g_hid_p [2][(size_t)T * HID];
__device__ __nv_bfloat16 g_wqaT  [2][(size_t)QLORA * HID];
__device__ __nv_bfloat16 g_wkvaT [2][(size_t)LATW * HID];
__device__ __nv_bfloat16 g_wqbT  [2][(size_t)HDQ * QLORA];
__device__ __nv_bfloat16 g_wkvbT [2][(size_t)KVW * DKV];
__device__ __nv_bfloat16 g_qlo_p [2][(size_t)T * QLORA];
__device__ __nv_bfloat16 g_lat_p [2][(size_t)T * DKV];
__device__ __nv_bfloat16 g_q_p   [2][(size_t)T * HDQ];
__device__ __nv_bfloat16 g_Kc_p  [2][(size_t)T * HDQ];
__device__ __nv_bfloat16 g_Vt_p  [2][(size_t)NH * DV * T];

// ---------------- fp16 planes (wo path) ----------------
__device__ __half g_Of  [(size_t)T * HDQ];           // attention out, fp16 (single plane)
__device__ __half g_woTf[2][(size_t)HID * HDQ];      // wo transposed, fp16 hi/lo

// ---------------- helpers ----------------
__device__ __forceinline__ void splitf(float v, __nv_bfloat16& h, __nv_bfloat16& l) {
    h = __float2bfloat16_rn(v);
    l = __float2bfloat16_rn(v - __bfloat162float(h));
}

__device__ __forceinline__ void splith(float v, __half& h, __half& l) {
    h = __float2half_rn(v);
    l = __float2half_rn(v - __half2float(h));
}

__device__ __forceinline__ uint32_t pack2(__nv_bfloat16 a, __nv_bfloat16 b) {
    return ((uint32_t)__bfloat16_as_ushort(b) << 16) | (uint32_t)__bfloat16_as_ushort(a);
}

__device__ __forceinline__ void mma_bf16(float* c, const uint32_t* a, const uint32_t* b) {
    asm volatile(
        "mma.sync.aligned.m16n8k16.row.col.f32.bf16.bf16.f32 "
        "{%0,%1,%2,%3}, {%4,%5,%6,%7}, {%8,%9}, {%0,%1,%2,%3};\n"
        : "+f"(c[0]), "+f"(c[1]), "+f"(c[2]), "+f"(c[3])
        : "r"(a[0]), "r"(a[1]), "r"(a[2]), "r"(a[3]), "r"(b[0]), "r"(b[1]));
}

__device__ __forceinline__ void mma_f16(float* c, const uint32_t* a, const uint32_t* b) {
    asm volatile(
        "mma.sync.aligned.m16n8k16.row.col.f32.f16.f16.f32 "
        "{%0,%1,%2,%3}, {%4,%5,%6,%7}, {%8,%9}, {%0,%1,%2,%3};\n"
        : "+f"(c[0]), "+f"(c[1]), "+f"(c[2]), "+f"(c[3])
        : "r"(a[0]), "r"(a[1]), "r"(a[2]), "r"(a[3]), "r"(b[0]), "r"(b[1]));
}

__device__ __forceinline__ void ldsm4(uint32_t& r0, uint32_t& r1, uint32_t& r2, uint32_t& r3, uint32_t a) {
    asm volatile("ldmatrix.sync.aligned.m8n8.x4.shared.b16 {%0,%1,%2,%3}, [%4];"
        : "=r"(r0), "=r"(r1), "=r"(r2), "=r"(r3) : "r"(a));
}

__device__ __forceinline__ void cp16(uint32_t d, const void* s) {
    asm volatile("cp.async.cg.shared.global [%0], [%1], 16;" :: "r"(d), "l"(s));
}

// ============================================================================
// Split-bf16 GEMM (R6/R3 proven config): C = A @ B^T on hi/lo planes.
// Block 128x128, BK=32, 256 threads (8 warps, 64x32 warp tiles), 2 CTAs/SM.
// ============================================================================
constexpr int TILE_B   = 128 * 80;
constexpr int STAGE_B  = 4 * TILE_B;
constexpr int SMEM_GEMM = 2 * STAGE_B;   // 81920

__global__ __launch_bounds__(256, 2) void tgemm_pl(
    const __nv_bfloat16* __restrict__ Ah, const __nv_bfloat16* __restrict__ Al,
    const __nv_bfloat16* __restrict__ Bh, const __nv_bfloat16* __restrict__ Bl,
    float* __restrict__ C,
    int M, int N, int K, int lda, int ldb, int ldc)
{
    const int bx = blockIdx.x, by = blockIdx.y;

    extern __shared__ char smem[];
    const uint32_t sb = (uint32_t)__cvta_generic_to_shared(smem);

    const int tid = threadIdx.x, lane = tid & 31, warp = tid >> 5;
    const int wm = warp & 1, wn = warp >> 1;
    const int g = lane >> 2, t4 = lane & 3;

    const int r0 = tid >> 2, c4 = tid & 3;
    const int Nm1 = N - 1;

    const int lr  = (lane & 7) + ((lane >> 3) & 1) * 8;
    const int lkb = (lane >> 4) * 16;
    const uint32_t aBase = sb + (uint32_t)((wm * 64 + lr) * 80 + lkb);
    const uint32_t bBase = sb + (uint32_t)(2 * TILE_B + (wn * 32 + lr) * 80 + lkb);

    float acc[4][4][4] = {};
    const int nchunks = K / 32;

    {
        #pragma unroll
        for (int c = 0; c < 2; c++) {
            int row = r0 + c * 64;
            uint32_t ds = sb + (uint32_t)(row * 80 + c4 * 16);
            long aoff = (long)(by * 128 + row) * lda + c4 * 8;
            cp16(ds,              Ah + aoff);
            cp16(ds + TILE_B,     Al + aoff);
            int nr = bx * 128 + row; if (nr > Nm1) nr = Nm1;
            long boff = (long)nr * ldb + c4 * 8;
            cp16(ds + 2 * TILE_B, Bh + boff);
            cp16(ds + 3 * TILE_B, Bl + boff);
        }
        asm volatile("cp.async.commit_group;");
    }

    for (int i = 0; i < nchunks; i++) {
        if (i + 1 < nchunks) {
            const int k0 = (i + 1) * 32;
            const uint32_t st = (uint32_t)(((i + 1) & 1) * STAGE_B);
            #pragma unroll
            for (int c = 0; c < 2; c++) {
                int row = r0 + c * 64;
                uint32_t ds = sb + st + (uint32_t)(row * 80 + c4 * 16);
                long aoff = (long)(by * 128 + row) * lda + k0 + c4 * 8;
                cp16(ds,              Ah + aoff);
                cp16(ds + TILE_B,     Al + aoff);
                int nr = bx * 128 + row; if (nr > Nm1) nr = Nm1;
                long boff = (long)nr * ldb + k0 + c4 * 8;
                cp16(ds + 2 * TILE_B, Bh + boff);
                cp16(ds + 3 * TILE_B, Bl + boff);
            }
        }
        asm volatile("cp.async.commit_group;");
        asm volatile("cp.async.wait_group 1;");
        __syncthreads();

        const uint32_t sof = (uint32_t)((i & 1) * STAGE_B);
        #pragma unroll
        for (int ks = 0; ks < 2; ks++) {
            uint32_t bh[4][2], bl[4][2];
            #pragma unroll
            for (int p = 0; p < 2; p++) {
                uint32_t ad = bBase + sof + (uint32_t)(p * 16 * 80 + ks * 32);
                uint32_t x0, x1, x2, x3;
                ldsm4(x0, x1, x2, x3, ad);
                bh[2*p][0] = x0; bh[2*p+1][0] = x1; bh[2*p][1] = x2; bh[2*p+1][1] = x3;
                ldsm4(x0, x1, x2, x3, ad + TILE_B);
                bl[2*p][0] = x0; bl[2*p+1][0] = x1; bl[2*p][1] = x2; bl[2*p+1][1] = x3;
            }
            #pragma unroll
            for (int mt = 0; mt < 4; mt++) {
                uint32_t ah[4], al[4];
                uint32_t ad = aBase + sof + (uint32_t)(mt * 16 * 80 + ks * 32);
                ldsm4(ah[0], ah[1], ah[2], ah[3], ad);
                ldsm4(al[0], al[1], al[2], al[3], ad + TILE_B);
                #pragma unroll
                for (int nt = 0; nt < 4; nt++) {
                    mma_bf16(acc[mt][nt], ah, bh[nt]);
                    mma_bf16(acc[mt][nt], ah, bl[nt]);
                    mma_bf16(acc[mt][nt], al, bh[nt]);
                }
            }
        }
        __syncthreads();
    }

    #pragma unroll
    for (int mt = 0; mt < 4; mt++) {
        int r = by * 128 + wm * 64 + mt * 16 + g;
        #pragma unroll
        for (int nt = 0; nt < 4; nt++) {
            int c = bx * 128 + wn * 32 + nt * 8 + 2 * t4;
            if (c < N) {
                *(float2*)&C[(long)r * ldc + c]       = make_float2(acc[mt][nt][0], acc[mt][nt][1]);
                *(float2*)&C[(long)(r + 8) * ldc + c] = make_float2(acc[mt][nt][2], acc[mt][nt][3]);
            }
        }
    }
}

// ============================================================================
// 2-pass fp16 GEMM (wo projection): C = Ah @ (Bh + Bl)^T.
// 3 smem planes (Ah, Bh, Bl); same tile/pipe structure; 2 mma passes.
// ============================================================================
constexpr int F_TILE  = 128 * 80;
constexpr int F_STAGE = 3 * F_TILE;      // 30720
constexpr int SMEM_F16 = 2 * F_STAGE;    // 61440

__global__ __launch_bounds__(256, 2) void tgemm_f16(
    const __half* __restrict__ Ah,
    const __half* __restrict__ Bh, const __half* __restrict__ Bl,
    float* __restrict__ C,
    int M, int N, int K, int lda, int ldb, int ldc)
{
    const int bx = blockIdx.x, by = blockIdx.y;

    extern __shared__ char smem[];
    const uint32_t sb = (uint32_t)__cvta_generic_to_shared(smem);

    const int tid = threadIdx.x, lane = tid & 31, warp = tid >> 5;
    const int wm = warp & 1, wn = warp >> 1;
    const int g = lane >> 2, t4 = lane & 3;

    const int r0 = tid >> 2, c4 = tid & 3;
    const int Nm1 = N - 1;

    const int lr  = (lane & 7) + ((lane >> 3) & 1) * 8;
    const int lkb = (lane >> 4) * 16;
    const uint32_t aBase = sb + (uint32_t)((wm * 64 + lr) * 80 + lkb);
    const uint32_t bBase = sb + (uint32_t)(F_TILE + (wn * 32 + lr) * 80 + lkb);

    float acc[4][4][4] = {};
    const int nchunks = K / 32;

    auto load_chunk = [&](int k0, uint32_t st) {
        #pragma unroll
        for (int c = 0; c < 2; c++) {
            int row = r0 + c * 64;
            uint32_t ds = sb + st + (uint32_t)(row * 80 + c4 * 16);
            long aoff = (long)(by * 128 + row) * lda + k0 + c4 * 8;
            cp16(ds, Ah + aoff);
            int nr = bx * 128 + row; if (nr > Nm1) nr = Nm1;
            long boff = (long)nr * ldb + k0 + c4 * 8;
            cp16(ds + F_TILE,     Bh + boff);
            cp16(ds + 2 * F_TILE, Bl + boff);
        }
    };

    load_chunk(0, 0);
    asm volatile("cp.async.commit_group;");

    for (int i = 0; i < nchunks; i++) {
        if (i + 1 < nchunks)
            load_chunk((i + 1) * 32, (uint32_t)(((i + 1) & 1) * F_STAGE));
        asm volatile("cp.async.commit_group;");
        asm volatile("cp.async.wait_group 1;");
        __syncthreads();

        const uint32_t sof = (uint32_t)((i & 1) * F_STAGE);
        #pragma unroll
        for (int ks = 0; ks < 2; ks++) {
            uint32_t bh[4][2], bl[4][2];
            #pragma unroll
            for (int p = 0; p < 2; p++) {
                uint32_t ad = bBase + sof + (uint32_t)(p * 16 * 80 + ks * 32);
                uint32_t x0, x1, x2, x3;
                ldsm4(x0, x1, x2, x3, ad);
                bh[2*p][0] = x0; bh[2*p+1][0] = x1; bh[2*p][1] = x2; bh[2*p+1][1] = x3;
                ldsm4(x0, x1, x2, x3, ad + F_TILE);
                bl[2*p][0] = x0; bl[2*p+1][0] = x1; bl[2*p][1] = x2; bl[2*p+1][1] = x3;
            }
            #pragma unroll
            for (int mt = 0; mt < 4; mt++) {
                uint32_t ah[4];
                uint32_t ad = aBase + sof + (uint32_t)(mt * 16 * 80 + ks * 32);
                ldsm4(ah[0], ah[1], ah[2], ah[3], ad);
                #pragma unroll
                for (int nt = 0; nt < 4; nt++) {
                    mma_f16(acc[mt][nt], ah, bh[nt]);
                    mma_f16(acc[mt][nt], ah, bl[nt]);
                }
            }
        }
        __syncthreads();
    }

    #pragma unroll
    for (int mt = 0; mt < 4; mt++) {
        int r = by * 128 + wm * 64 + mt * 16 + g;
        #pragma unroll
        for (int nt = 0; nt < 4; nt++) {
            int c = bx * 128 + wn * 32 + nt * 8 + 2 * t4;
            if (c < N) {
                *(float2*)&C[(long)r * ldc + c]       = make_float2(acc[mt][nt][0], acc[mt][nt][1]);
                *(float2*)&C[(long)(r + 8) * ldc + c] = make_float2(acc[mt][nt][2], acc[mt][nt][3]);
            }
        }
    }
}

// ============================================================================
// Fused flash attention, V fully prefetched per tile; fp16 O output.
// smem: QK 2 stages x 40960 = 81920; V both dv-chunks at 81920 (4 x 34816).
// ============================================================================
constexpr int QPL  = 10240;
constexpr int VPL  = 34816;
constexpr int VOFF = 81920;
constexpr int FA_SMEM = VOFF + 4 * VPL;   // 221184

__global__ __launch_bounds__(256, 1) void flash_k(
    const __nv_bfloat16* __restrict__ Qh, const __nv_bfloat16* __restrict__ Ql,
    const __nv_bfloat16* __restrict__ Kh, const __nv_bfloat16* __restrict__ Kl,
    const __nv_bfloat16* __restrict__ Vh, const __nv_bfloat16* __restrict__ Vl,
    __half* __restrict__ Of)
{
    const int qi = gridDim.x - 1 - blockIdx.x;   // heavy tiles first
    const int h  = blockIdx.y;

    extern __shared__ char smem[];
    const uint32_t sb = (uint32_t)__cvta_generic_to_shared(smem);

    const int tid = threadIdx.x, lane = tid & 31, w = tid >> 5;
    const int g = lane >> 2, t4 = lane & 3;
    const int lr  = (lane & 7) + ((lane >> 3) & 1) * 8;
    const int lkb = (lane >> 4) * 16;

    float oacc[32][4];
    #pragma unroll
    for (int i = 0; i < 32; i++)
        #pragma unroll
        for (int c = 0; c < 4; c++) oacc[i][c] = 0.f;
    float m0 = -1e30f, m1 = -1e30f, l0 = 0.f, l1 = 0.f;

    const float scale = 0.0625f;

    for (int j = 0; j <= qi; j++) {
        float sacc[16][4] = {};

        auto load_qk = [&](int i, uint32_t st) {
            const int d = i * 32;
            #pragma unroll
            for (int p = 0; p < 2; p++) {
                int id = tid + p * 256;
                int row = id >> 2, cc = id & 3;
                uint32_t dst = sb + st + (uint32_t)(row * 80 + cc * 16);
                size_t qo = (size_t)(qi * 128 + row) * HDQ + h * DQ + d + cc * 8;
                cp16(dst,           Qh + qo);
                cp16(dst + QPL,     Ql + qo);
                size_t ko = (size_t)(j * 128 + row) * HDQ + h * DQ + d + cc * 8;
                cp16(dst + 2 * QPL, Kh + ko);
                cp16(dst + 3 * QPL, Kl + ko);
            }
        };

        load_qk(0, 0);
        asm volatile("cp.async.commit_group;");
        load_qk(1, 4 * QPL);
        asm volatile("cp.async.commit_group;");

        // prefetch BOTH V dv-chunks for this tile (group committed after QK0/QK1)
        #pragma unroll
        for (int dvc = 0; dvc < 2; dvc++) {
            #pragma unroll
            for (int p = 0; p < 8; p++) {
                int id = tid + p * 256;
                int row = id >> 4, cc = id & 15;
                uint32_t dst = sb + (uint32_t)(VOFF + dvc * 2 * VPL + row * 272 + cc * 16);
                size_t vo = (size_t)h * DV * T + (size_t)(dvc * 128 + row) * T + j * 128 + cc * 8;
                cp16(dst,       Vh + vo);
                cp16(dst + VPL, Vl + vo);
            }
        }
        asm volatile("cp.async.commit_group;");

        for (int i = 0; i < 8; i++) {
            asm volatile("cp.async.wait_group 1;");
            __syncthreads();
            const uint32_t st = (uint32_t)((i & 1) * 4 * QPL);
            #pragma unroll
            for (int ks = 0; ks < 2; ks++) {
                uint32_t ah[4], al[4];
                uint32_t ad = sb + st + (uint32_t)((w * 16 + lr) * 80 + lkb + ks * 32);
                ldsm4(ah[0], ah[1], ah[2], ah[3], ad);
                ldsm4(al[0], al[1], al[2], al[3], ad + QPL);
                #pragma unroll
                for (int p = 0; p < 8; p++) {
                    uint32_t bh[2][2], bl[2][2], x0, x1, x2, x3;
                    uint32_t bd = sb + st + (uint32_t)(2 * QPL + (p * 16 + lr) * 80 + lkb + ks * 32);
                    ldsm4(x0, x1, x2, x3, bd);
                    bh[0][0] = x0; bh[1][0] = x1; bh[0][1] = x2; bh[1][1] = x3;
                    ldsm4(x0, x1, x2, x3, bd + QPL);
                    bl[0][0] = x0; bl[1][0] = x1; bl[0][1] = x2; bl[1][1] = x3;
                    #pragma unroll
                    for (int q2 = 0; q2 < 2; q2++) {
                        float* c = sacc[p * 2 + q2];
                        mma_bf16(c, ah, bh[q2]);
                        mma_bf16(c, ah, bl[q2]);
                        mma_bf16(c, al, bh[q2]);
                    }
                }
            }
            __syncthreads();
            if (i + 2 < 8) load_qk(i + 2, st);
            asm volatile("cp.async.commit_group;");
        }
        asm volatile("cp.async.wait_group 0;");

        // ---------------- softmax (registers) ----------------
        #pragma unroll
        for (int nt = 0; nt < 16; nt++)
            #pragma unroll
            for (int c = 0; c < 4; c++) sacc[nt][c] *= scale;

        if (j == qi) {
            const int rr0 = w * 16 + g, rr1 = rr0 + 8;
            #pragma unroll
            for (int nt = 0; nt < 16; nt++) {
                int col = nt * 8 + 2 * t4;
                if (col     > rr0) sacc[nt][0] = -1e30f;
                if (col + 1 > rr0) sacc[nt][1] = -1e30f;
                if (col     > rr1) sacc[nt][2] = -1e30f;
                if (col + 1 > rr1) sacc[nt][3] = -1e30f;
            }
        }

        float tm0 = -1e30f, tm1 = -1e30f;
        #pragma unroll
        for (int nt = 0; nt < 16; nt++) {
            tm0 = fmaxf(tm0, fmaxf(sacc[nt][0], sacc[nt][1]));
            tm1 = fmaxf(tm1, fmaxf(sacc[nt][2], sacc[nt][3]));
        }
        tm0 = fmaxf(tm0, __shfl_xor_sync(0xffffffffu, tm0, 1));
        tm0 = fmaxf(tm0, __shfl_xor_sync(0xffffffffu, tm0, 2));
        tm1 = fmaxf(tm1, __shfl_xor_sync(0xffffffffu, tm1, 1));
        tm1 = fmaxf(tm1, __shfl_xor_sync(0xffffffffu, tm1, 2));

        float nm0 = fmaxf(m0, tm0), nm1 = fmaxf(m1, tm1);
        float a0 = expf(m0 - nm0), a1 = expf(m1 - nm1);
        m0 = nm0; m1 = nm1;

        float s0 = 0.f, s1 = 0.f;
        #pragma unroll
        for (int nt = 0; nt < 16; nt++) {
            sacc[nt][0] = expf(sacc[nt][0] - m0); s0 += sacc[nt][0];
            sacc[nt][1] = expf(sacc[nt][1] - m0); s0 += sacc[nt][1];
            sacc[nt][2] = expf(sacc[nt][2] - m1); s1 += sacc[nt][2];
            sacc[nt][3] = expf(sacc[nt][3] - m1); s1 += sacc[nt][3];
        }
        s0 += __shfl_xor_sync(0xffffffffu, s0, 1);
        s0 += __shfl_xor_sync(0xffffffffu, s0, 2);
        s1 += __shfl_xor_sync(0xffffffffu, s1, 1);
        s1 += __shfl_xor_sync(0xffffffffu, s1, 2);
        l0 = l0 * a0 + s0;
        l1 = l1 * a1 + s1;

        #pragma unroll
        for (int i = 0; i < 32; i++) {
            oacc[i][0] *= a0; oacc[i][1] *= a0;
            oacc[i][2] *= a1; oacc[i][3] *= a1;
        }

        // P fragments (A-operand layout)
        uint32_t Pf0[8][4], Pf1[8][4];
        #pragma unroll
        for (int ks = 0; ks < 8; ks++) {
            #pragma unroll
            for (int hf = 0; hf < 2; hf++) {
                const float* c = sacc[2 * ks + hf];
                __nv_bfloat16 ha, la, hb, lb;
                splitf(c[0], ha, la); splitf(c[1], hb, lb);
                Pf0[ks][hf * 2]     = pack2(ha, hb);
                Pf1[ks][hf * 2]     = pack2(la, lb);
                splitf(c[2], ha, la); splitf(c[3], hb, lb);
                Pf0[ks][hf * 2 + 1] = pack2(ha, hb);
                Pf1[ks][hf * 2 + 1] = pack2(la, lb);
            }
        }

        // ---------------- PV: V already resident ----------------
        __syncthreads();   // V visibility across warps
        #pragma unroll
        for (int dvc = 0; dvc < 2; dvc++) {
            #pragma unroll
            for (int ks = 0; ks < 8; ks++) {
                #pragma unroll
                for (int p = 0; p < 8; p++) {
                    uint32_t vh[2][2], vl[2][2], x0, x1, x2, x3;
                    uint32_t bd = sb + (uint32_t)(VOFF + dvc * 2 * VPL + (p * 16 + lr) * 272 + lkb + ks * 32);
                    ldsm4(x0, x1, x2, x3, bd);
                    vh[0][0] = x0; vh[1][0] = x1; vh[0][1] = x2; vh[1][1] = x3;
                    ldsm4(x0, x1, x2, x3, bd + VPL);
                    vl[0][0] = x0; vl[1][0] = x1; vl[0][1] = x2; vl[1][1] = x3;
                    #pragma unroll
                    for (int q2 = 0; q2 < 2; q2++) {
                        float* c = oacc[dvc * 16 + p * 2 + q2];
                        mma_bf16(c, Pf0[ks], vh[q2]);
                        mma_bf16(c, Pf0[ks], vl[q2]);
                        mma_bf16(c, Pf1[ks], vh[q2]);
                    }
                }
            }
        }
        __syncthreads();   // protect smem before next tile's loads
    }

    // ---------------- epilogue: fp16 O planes ----------------
    const float i0 = 1.f / l0, i1 = 1.f / l1;
    const int r0 = qi * 128 + w * 16 + g;
    __half* o0 = Of + (size_t)r0 * HDQ + h * DV;
    __half* o1 = o0 + (size_t)8 * HDQ;
    #pragma unroll
    for (int nt = 0; nt < 32; nt++) {
        int c = nt * 8 + 2 * t4;
        __half2 v0 = __floats2half2_rn(oacc[nt][0] * i0, oacc[nt][1] * i0);
        __half2 v1 = __floats2half2_rn(oacc[nt][2] * i1, oacc[nt][3] * i1);
        *(__half2*)&o0[c] = v0;
        *(__half2*)&o1[c] = v1;
    }
}

// ---------------- fp32 -> planes ----------------
__global__ void conv_pl_k(const float* __restrict__ x, __nv_bfloat16* __restrict__ h,
                          __nv_bfloat16* __restrict__ l, long n)
{
    long i = (long)blockIdx.x * blockDim.x + threadIdx.x;
    long stride = (long)gridDim.x * blockDim.x;
    for (; i < n; i += stride) {
        __nv_bfloat16 hh, ll;
        splitf(x[i], hh, ll);
        h[i] = hh; l[i] = ll;
    }
}

// ---------------- fp32 [R,C] -> bf16 planes transposed [C,R] ----------------
__global__ void conv_tr_k(const float* __restrict__ x, __nv_bfloat16* __restrict__ h,
                          __nv_bfloat16* __restrict__ l, int R, int C)
{
    __shared__ float tile[32][33];
    const int c0 = blockIdx.x * 32, rr0 = blockIdx.y * 32;
    const int tx = threadIdx.x & 31, ty = threadIdx.x >> 5;
    #pragma unroll
    for (int i = 0; i < 4; i++) {
        int r = rr0 + ty + i * 8;
        tile[ty + i * 8][tx] = x[(long)r * C + c0 + tx];
    }
    __syncthreads();
    #pragma unroll
    for (int i = 0; i < 4; i++) {
        int c = c0 + ty + i * 8;
        float v = tile[tx][ty + i * 8];
        long o = (long)c * R + rr0 + tx;
        __nv_bfloat16 hh, ll;
        splitf(v, hh, ll);
        h[o] = hh; l[o] = ll;
    }
}

// ---------------- fp32 [R,C] -> fp16 planes transposed [C,R] ----------------
__global__ void conv_tr_f16_k(const float* __restrict__ x, __half* __restrict__ h,
                              __half* __restrict__ l, int R, int C)
{
    __shared__ float tile[32][33];
    const int c0 = blockIdx.x * 32, rr0 = blockIdx.y * 32;
    const int tx = threadIdx.x & 31, ty = threadIdx.x >> 5;
    #pragma unroll
    for (int i = 0; i < 4; i++) {
        int r = rr0 + ty + i * 8;
        tile[ty + i * 8][tx] = x[(long)r * C + c0 + tx];
    }
    __syncthreads();
    #pragma unroll
    for (int i = 0; i < 4; i++) {
        int c = c0 + ty + i * 8;
        float v = tile[tx][ty + i * 8];
        long o = (long)c * R + rr0 + tx;
        __half hh, ll;
        splith(v, hh, ll);
        h[o] = hh; l[o] = ll;
    }
}

// ---------------- RMSNorm fp32 -> planes ----------------
__global__ void rmsnorm_pl_k(const float* __restrict__ x, const float* __restrict__ w,
                             __nv_bfloat16* __restrict__ h, __nv_bfloat16* __restrict__ l,
                             int N, int ldin)
{
    const float* p = x + (long)blockIdx.x * ldin;
    __shared__ float red[8];
    __shared__ float bc;
    const int lane = threadIdx.x & 31, wid = threadIdx.x >> 5;

    float s = 0.f;
    for (int j = threadIdx.x; j < N; j += blockDim.x) { float v = p[j]; s += v * v; }
    #pragma unroll
    for (int o = 16; o; o >>= 1) s += __shfl_xor_sync(0xffffffffu, s, o);
    if (lane == 0) red[wid] = s;
    __syncthreads();
    if (threadIdx.x == 0) {
        float v = 0.f;
        for (int wI = 0; wI < 8; wI++) v += red[wI];
        bc = rsqrtf(v / N + 1e-6f);
    }
    __syncthreads();
    float r = bc;
    long ob = (long)blockIdx.x * N;
    for (int j = threadIdx.x; j < N; j += blockDim.x) {
        __nv_bfloat16 hh, ll;
        splitf(p[j] * r * w[j], hh, ll);
        h[ob + j] = hh; l[ob + j] = ll;
    }
}

// ---------------- rope k_pe in-place ----------------
__global__ void rope_kpe_k(float* __restrict__ lat, const int* __restrict__ pos)
{
    const int tt = blockIdx.x, i = threadIdx.x;
    double inv = pow(10000.0, -(double)i / 32.0);
    double sd, cd;
    sincos((double)pos[tt] * inv, &sd, &cd);
    float c = (float)cd, s = (float)sd;
    float* p = lat + (long)tt * LATW + DKV;
    float x1 = p[i], x2 = p[i + 32];
    p[i]      = x1 * c - x2 * s;
    p[i + 32] = x2 * c + x1 * s;
}

// ---------------- q: rope fused + planes ----------------
__global__ void rope_conv_q_k(const float* __restrict__ q, const int* __restrict__ pos,
                              __nv_bfloat16* __restrict__ h, __nv_bfloat16* __restrict__ l)
{
    const int tt = blockIdx.x;
    __shared__ float cs[32], sn[32];
    if (threadIdx.x < 32) {
        double inv = pow(10000.0, -(double)threadIdx.x / 32.0);
        double sd, cd;
        sincos((double)pos[tt] * inv, &sd, &cd);
        cs[threadIdx.x] = (float)cd; sn[threadIdx.x] = (float)sd;
    }
    __syncthreads();
    const float* row = q + (long)tt * HDQ;
    long ob = (long)tt * HDQ;
    for (int x = threadIdx.x; x < HDQ; x += blockDim.x) {
        int d = x & 255;
        float v;
        if (d < DN)            v = row[x];
        else if (d < DN + 32) { int i = d - DN;       v = row[x] * cs[i] - row[x + 32] * sn[i]; }
        else                  { int i = d - DN - 32;  v = row[x] * cs[i] + row[x - 32] * sn[i]; }
        __nv_bfloat16 hh, ll;
        splitf(v, hh, ll);
        h[ob + x] = hh; l[ob + x] = ll;
    }
}

// ---------------- K assembly -> planes ----------------
__global__ void build_K_pl_k(const float* __restrict__ kv, const float* __restrict__ lat,
                             __nv_bfloat16* __restrict__ h, __nv_bfloat16* __restrict__ l)
{
    const int tt = blockIdx.x;
    long ob = (long)tt * HDQ;
    for (int x = threadIdx.x; x < HDQ; x += blockDim.x) {
        int hd = x >> 8, d = x & 255;
        float v = (d < DN) ? kv[(long)tt * KVW + hd * (DN + DV) + d]
                           : lat[(long)tt * LATW + DKV + (d - DN)];
        __nv_bfloat16 hh, ll;
        splitf(v, hh, ll);
        h[ob + x] = hh; l[ob + x] = ll;
    }
}

// ---------------- V transpose per head -> planes [h][DV][T] ----------------
__global__ void transpose_v_pl_k(const float* __restrict__ kv,
                                 __nv_bfloat16* __restrict__ h, __nv_bfloat16* __restrict__ l)
{
    __shared__ float tile[32][33];
    const int d0 = blockIdx.x * 32, t0 = blockIdx.y * 32, hd = blockIdx.z;
    const int tx = threadIdx.x & 31, ty = threadIdx.x >> 5;
    #pragma unroll
    for (int i = 0; i < 4; i++) {
        int tr = t0 + ty + i * 8;
        tile[ty + i * 8][tx] = kv[(long)tr * KVW + hd * (DN + DV) + DN + d0 + tx];
    }
    __syncthreads();
    #pragma unroll
    for (int i = 0; i < 4; i++) {
        int d = d0 + ty + i * 8;
        float v = tile[tx][ty + i * 8];
        long o = (long)hd * DV * T + (long)d * T + t0 + tx;
        __nv_bfloat16 hh, ll;
        splitf(v, hh, ll);
        h[o] = hh; l[o] = ll;
    }
}

// ---------------- launch ----------------
extern "C" void kernel_launch(void* const* d_in, const int* in_sizes, int n_in,
                              void* d_out, int out_size)
{
    (void)in_sizes; (void)n_in; (void)out_size;
    const float* hidden = (const float*)d_in[0];
    const int*   pos    = (const int*)  d_in[1];
    const float* wq_a   = (const float*)d_in[2];
    const float* q_ln   = (const float*)d_in[3];
    const float* wq_b   = (const float*)d_in[4];
    const float* wkv_a  = (const float*)d_in[5];
    const float* kv_ln  = (const float*)d_in[6];
    const float* wkv_b  = (const float*)d_in[7];
    const float* wo     = (const float*)d_in[8];
    float* out = (float*)d_out;

    cudaFuncSetAttribute(tgemm_pl,  cudaFuncAttributeMaxDynamicSharedMemorySize, SMEM_GEMM);
    cudaFuncSetAttribute(tgemm_f16, cudaFuncAttributeMaxDynamicSharedMemorySize, SMEM_F16);
    cudaFuncSetAttribute(flash_k,   cudaFuncAttributeMaxDynamicSharedMemorySize, FA_SMEM);

    float *qlora, *latent, *q, *kv;
    cudaGetSymbolAddress((void**)&qlora,  g_qlora);
    cudaGetSymbolAddress((void**)&latent, g_latent);
    cudaGetSymbolAddress((void**)&q,      g_q);
    cudaGetSymbolAddress((void**)&kv,     g_kv);

    __nv_bfloat16 *hidp, *wqaT, *wkvaT, *wqbT, *wkvbT,
                  *qlop, *latp, *qp, *Kcp, *Vtp;
    cudaGetSymbolAddress((void**)&hidp,  g_hid_p);
    cudaGetSymbolAddress((void**)&wqaT,  g_wqaT);
    cudaGetSymbolAddress((void**)&wkvaT, g_wkvaT);
    cudaGetSymbolAddress((void**)&wqbT,  g_wqbT);
    cudaGetSymbolAddress((void**)&wkvbT, g_wkvbT);
    cudaGetSymbolAddress((void**)&qlop,  g_qlo_p);
    cudaGetSymbolAddress((void**)&latp,  g_lat_p);
    cudaGetSymbolAddress((void**)&qp,    g_q_p);
    cudaGetSymbolAddress((void**)&Kcp,   g_Kc_p);
    cudaGetSymbolAddress((void**)&Vtp,   g_Vt_p);

    __half *Ofp, *woTf;
    cudaGetSymbolAddress((void**)&Ofp,  g_Of);
    cudaGetSymbolAddress((void**)&woTf, g_woTf);

    #define PL(base, n) (base), ((base) + (size_t)(n))

    const size_t nHid = (size_t)T * HID,    nWqa = (size_t)QLORA * HID;
    const size_t nWkva= (size_t)LATW * HID, nWqb = (size_t)HDQ * QLORA;
    const size_t nWkvb= (size_t)KVW * DKV,  nWo  = (size_t)HID * HDQ;
    const size_t nQlo = (size_t)T * QLORA,  nLat = (size_t)T * DKV;
    const size_t nQ   = (size_t)T * HDQ;
    const size_t nVt  = (size_t)NH * DV * T;

    dim3 blk(256);

    // ---- weight conversion + transpose ----
    conv_tr_k<<<dim3(QLORA/32, HID/32), blk>>>(wq_a,  PL(wqaT,  nWqa), HID, QLORA);
    conv_tr_k<<<dim3(LATW/32,  HID/32), blk>>>(wkv_a, PL(wkvaT, nWkva), HID, LATW);
    conv_tr_k<<<dim3(HDQ/32, QLORA/32), blk>>>(wq_b,  PL(wqbT,  nWqb), QLORA, HDQ);
    conv_tr_k<<<dim3(KVW/32,  DKV/32),  blk>>>(wkv_b, PL(wkvbT, nWkvb), DKV, KVW);
    conv_tr_f16_k<<<dim3(HID/32, HDQ/32), blk>>>(wo,  PL(woTf,  nWo),  HDQ, HID);
    conv_pl_k<<<2048, 256>>>(hidden, PL(hidp, nHid), (long)nHid);

    // ---- down projections ----
    tgemm_pl<<<dim3(QLORA/128, T/128), blk, SMEM_GEMM>>>(PL(hidp, nHid), PL(wqaT, nWqa),
        qlora, T, QLORA, HID, HID, HID, QLORA);
    tgemm_pl<<<dim3((LATW+127)/128, T/128), blk, SMEM_GEMM>>>(PL(hidp, nHid), PL(wkvaT, nWkva),
        latent, T, LATW, HID, HID, HID, LATW);

    // ---- norms + rope(k_pe) ----
    rmsnorm_pl_k<<<T, 256>>>(qlora, q_ln, PL(qlop, nQlo), QLORA, QLORA);
    rope_kpe_k<<<T, 32>>>(latent, pos);
    rmsnorm_pl_k<<<T, 256>>>(latent, kv_ln, PL(latp, nLat), DKV, LATW);

    // ---- up projections ----
    tgemm_pl<<<dim3(HDQ/128, T/128), blk, SMEM_GEMM>>>(PL(qlop, nQlo), PL(wqbT, nWqb),
        q, T, HDQ, QLORA, QLORA, QLORA, HDQ);
    tgemm_pl<<<dim3(KVW/128, T/128), blk, SMEM_GEMM>>>(PL(latp, nLat), PL(wkvbT, nWkvb),
        kv, T, KVW, DKV, DKV, DKV, KVW);

    // ---- q rope + planes; K assembly; V transpose ----
    rope_conv_q_k<<<T, 256>>>(q, pos, PL(qp, nQ));
    build_K_pl_k<<<T, 256>>>(kv, latent, PL(Kcp, nQ));
    transpose_v_pl_k<<<dim3(DV/32, T/32, NH), blk>>>(kv, PL(Vtp, nVt));

    // ---- fused flash attention (fp16 O out) ----
    flash_k<<<dim3(T/128, NH), blk, FA_SMEM>>>(
        PL(qp, nQ), PL(Kcp, nQ), PL(Vtp, nVt), Ofp);

    // ---- final projection: 2-pass fp16 ----
    tgemm_f16<<<dim3(HID/128, T/128), blk, SMEM_F16>>>(Ofp, PL(woTf, nWo),
        out, T, HID, HDQ, HDQ, HDQ, HID);

    #undef PL
}

// round 9
// speedup vs baseline: 1.2918x; 1.1496x over previous
#include <cuda_runtime.h>
#include <cuda_bf16.h>
#include <cuda_fp16.h>
#include <math.h>
#include <stdint.h>

// ---------------- problem constants ----------------
constexpr int T    = 2048;
constexpr int HID  = 4096;
constexpr int NH   = 32;
constexpr int DQ   = 256;
constexpr int DN   = 192;
constexpr int DR   = 64;
constexpr int DV   = 256;
constexpr int DKV  = 512;
constexpr int QLORA= 2048;
constexpr int HDQ  = NH * DQ;        // 8192
constexpr int KVW  = NH * (DN + DV); // 14336
constexpr int LATW = DKV + DR;       // 576

// ---------------- fp32 scratch ----------------
__device__ float g_qlora[(size_t)T * QLORA];
__device__ float g_latent[(size_t)T * LATW];
__device__ float g_q[(size_t)T * HDQ];
__device__ float g_kv[(size_t)T * KVW];

// ---------------- bf16 planes (flash inputs, 3-term path) ----------------
__device__ __nv_bfloat16 g_q_p  [2][(size_t)T * HDQ];
__device__ __nv_bfloat16 g_Kc_p [2][(size_t)T * HDQ];
__device__ __nv_bfloat16 g_Vt_p [2][(size_t)NH * DV * T];

// ---------------- fp16 buffers (2-pass GEMM path) ----------------
__device__ __half g_hid_f  [(size_t)T * HID];
__device__ __half g_qlo_f  [(size_t)T * QLORA];
__device__ __half g_lat_f  [(size_t)T * DKV];
__device__ __half g_Of     [(size_t)T * HDQ];
__device__ __half g_wqaTf  [2][(size_t)QLORA * HID];
__device__ __half g_wkvaTf [2][(size_t)LATW * HID];
__device__ __half g_wqbTf  [2][(size_t)HDQ * QLORA];
__device__ __half g_wkvbTf [2][(size_t)KVW * DKV];
__device__ __half g_woTf   [2][(size_t)HID * HDQ];

// ---------------- helpers ----------------
__device__ __forceinline__ void splitf(float v, __nv_bfloat16& h, __nv_bfloat16& l) {
    h = __float2bfloat16_rn(v);
    l = __float2bfloat16_rn(v - __bfloat162float(h));
}

__device__ __forceinline__ void splith(float v, __half& h, __half& l) {
    h = __float2half_rn(v);
    l = __float2half_rn(v - __half2float(h));
}

__device__ __forceinline__ uint32_t pack2(__nv_bfloat16 a, __nv_bfloat16 b) {
    return ((uint32_t)__bfloat16_as_ushort(b) << 16) | (uint32_t)__bfloat16_as_ushort(a);
}

__device__ __forceinline__ void mma_bf16(float* c, const uint32_t* a, const uint32_t* b) {
    asm volatile(
        "mma.sync.aligned.m16n8k16.row.col.f32.bf16.bf16.f32 "
        "{%0,%1,%2,%3}, {%4,%5,%6,%7}, {%8,%9}, {%0,%1,%2,%3};\n"
        : "+f"(c[0]), "+f"(c[1]), "+f"(c[2]), "+f"(c[3])
        : "r"(a[0]), "r"(a[1]), "r"(a[2]), "r"(a[3]), "r"(b[0]), "r"(b[1]));
}

__device__ __forceinline__ void mma_f16(float* c, const uint32_t* a, const uint32_t* b) {
    asm volatile(
        "mma.sync.aligned.m16n8k16.row.col.f32.f16.f16.f32 "
        "{%0,%1,%2,%3}, {%4,%5,%6,%7}, {%8,%9}, {%0,%1,%2,%3};\n"
        : "+f"(c[0]), "+f"(c[1]), "+f"(c[2]), "+f"(c[3])
        : "r"(a[0]), "r"(a[1]), "r"(a[2]), "r"(a[3]), "r"(b[0]), "r"(b[1]));
}

__device__ __forceinline__ void ldsm4(uint32_t& r0, uint32_t& r1, uint32_t& r2, uint32_t& r3, uint32_t a) {
    asm volatile("ldmatrix.sync.aligned.m8n8.x4.shared.b16 {%0,%1,%2,%3}, [%4];"
        : "=r"(r0), "=r"(r1), "=r"(r2), "=r"(r3) : "r"(a));
}

__device__ __forceinline__ void cp16(uint32_t d, const void* s) {
    asm volatile("cp.async.cg.shared.global [%0], [%1], 16;" :: "r"(d), "l"(s));
}

// ============================================================================
// 2-pass fp16 GEMM: C = Ah @ (Bh + Bl)^T.  Block 128x128, BK=32, 256 thr,
// 2 CTAs/SM, cp.async double-buffered, ldmatrix frags (proven R8 kernel).
// ============================================================================
constexpr int F_TILE  = 128 * 80;
constexpr int F_STAGE = 3 * F_TILE;      // 30720
constexpr int SMEM_F16 = 2 * F_STAGE;    // 61440

__global__ __launch_bounds__(256, 2) void tgemm_f16(
    const __half* __restrict__ Ah,
    const __half* __restrict__ Bh, const __half* __restrict__ Bl,
    float* __restrict__ C,
    int M, int N, int K, int lda, int ldb, int ldc)
{
    const int bx = blockIdx.x, by = blockIdx.y;

    extern __shared__ char smem[];
    const uint32_t sb = (uint32_t)__cvta_generic_to_shared(smem);

    const int tid = threadIdx.x, lane = tid & 31, warp = tid >> 5;
    const int wm = warp & 1, wn = warp >> 1;
    const int g = lane >> 2, t4 = lane & 3;

    const int r0 = tid >> 2, c4 = tid & 3;
    const int Nm1 = N - 1;

    const int lr  = (lane & 7) + ((lane >> 3) & 1) * 8;
    const int lkb = (lane >> 4) * 16;
    const uint32_t aBase = sb + (uint32_t)((wm * 64 + lr) * 80 + lkb);
    const uint32_t bBase = sb + (uint32_t)(F_TILE + (wn * 32 + lr) * 80 + lkb);

    float acc[4][4][4] = {};
    const int nchunks = K / 32;

    auto load_chunk = [&](int k0, uint32_t st) {
        #pragma unroll
        for (int c = 0; c < 2; c++) {
            int row = r0 + c * 64;
            uint32_t ds = sb + st + (uint32_t)(row * 80 + c4 * 16);
            long aoff = (long)(by * 128 + row) * lda + k0 + c4 * 8;
            cp16(ds, Ah + aoff);
            int nr = bx * 128 + row; if (nr > Nm1) nr = Nm1;
            long boff = (long)nr * ldb + k0 + c4 * 8;
            cp16(ds + F_TILE,     Bh + boff);
            cp16(ds + 2 * F_TILE, Bl + boff);
        }
    };

    load_chunk(0, 0);
    asm volatile("cp.async.commit_group;");

    for (int i = 0; i < nchunks; i++) {
        if (i + 1 < nchunks)
            load_chunk((i + 1) * 32, (uint32_t)(((i + 1) & 1) * F_STAGE));
        asm volatile("cp.async.commit_group;");
        asm volatile("cp.async.wait_group 1;");
        __syncthreads();

        const uint32_t sof = (uint32_t)((i & 1) * F_STAGE);
        #pragma unroll
        for (int ks = 0; ks < 2; ks++) {
            uint32_t bh[4][2], bl[4][2];
            #pragma unroll
            for (int p = 0; p < 2; p++) {
                uint32_t ad = bBase + sof + (uint32_t)(p * 16 * 80 + ks * 32);
                uint32_t x0, x1, x2, x3;
                ldsm4(x0, x1, x2, x3, ad);
                bh[2*p][0] = x0; bh[2*p+1][0] = x1; bh[2*p][1] = x2; bh[2*p+1][1] = x3;
                ldsm4(x0, x1, x2, x3, ad + F_TILE);
                bl[2*p][0] = x0; bl[2*p+1][0] = x1; bl[2*p][1] = x2; bl[2*p+1][1] = x3;
            }
            #pragma unroll
            for (int mt = 0; mt < 4; mt++) {
                uint32_t ah[4];
                uint32_t ad = aBase + sof + (uint32_t)(mt * 16 * 80 + ks * 32);
                ldsm4(ah[0], ah[1], ah[2], ah[3], ad);
                #pragma unroll
                for (int nt = 0; nt < 4; nt++) {
                    mma_f16(acc[mt][nt], ah, bh[nt]);
                    mma_f16(acc[mt][nt], ah, bl[nt]);
                }
            }
        }
        __syncthreads();
    }

    #pragma unroll
    for (int mt = 0; mt < 4; mt++) {
        int r = by * 128 + wm * 64 + mt * 16 + g;
        #pragma unroll
        for (int nt = 0; nt < 4; nt++) {
            int c = bx * 128 + wn * 32 + nt * 8 + 2 * t4;
            if (c < N) {
                *(float2*)&C[(long)r * ldc + c]       = make_float2(acc[mt][nt][0], acc[mt][nt][1]);
                *(float2*)&C[(long)(r + 8) * ldc + c] = make_float2(acc[mt][nt][2], acc[mt][nt][3]);
            }
        }
    }
}

// ============================================================================
// Fused flash attention (3-term bf16), V fully prefetched; fp16 O output.
// ============================================================================
constexpr int QPL  = 10240;
constexpr int VPL  = 34816;
constexpr int VOFF = 81920;
constexpr int FA_SMEM = VOFF + 4 * VPL;   // 221184

__global__ __launch_bounds__(256, 1) void flash_k(
    const __nv_bfloat16* __restrict__ Qh, const __nv_bfloat16* __restrict__ Ql,
    const __nv_bfloat16* __restrict__ Kh, const __nv_bfloat16* __restrict__ Kl,
    const __nv_bfloat16* __restrict__ Vh, const __nv_bfloat16* __restrict__ Vl,
    __half* __restrict__ Of)
{
    const int qi = gridDim.x - 1 - blockIdx.x;   // heavy tiles first
    const int h  = blockIdx.y;

    extern __shared__ char smem[];
    const uint32_t sb = (uint32_t)__cvta_generic_to_shared(smem);

    const int tid = threadIdx.x, lane = tid & 31, w = tid >> 5;
    const int g = lane >> 2, t4 = lane & 3;
    const int lr  = (lane & 7) + ((lane >> 3) & 1) * 8;
    const int lkb = (lane >> 4) * 16;

    float oacc[32][4];
    #pragma unroll
    for (int i = 0; i < 32; i++)
        #pragma unroll
        for (int c = 0; c < 4; c++) oacc[i][c] = 0.f;
    float m0 = -1e30f, m1 = -1e30f, l0 = 0.f, l1 = 0.f;

    const float scale = 0.0625f;

    for (int j = 0; j <= qi; j++) {
        float sacc[16][4] = {};

        auto load_qk = [&](int i, uint32_t st) {
            const int d = i * 32;
            #pragma unroll
            for (int p = 0; p < 2; p++) {
                int id = tid + p * 256;
                int row = id >> 2, cc = id & 3;
                uint32_t dst = sb + st + (uint32_t)(row * 80 + cc * 16);
                size_t qo = (size_t)(qi * 128 + row) * HDQ + h * DQ + d + cc * 8;
                cp16(dst,           Qh + qo);
                cp16(dst + QPL,     Ql + qo);
                size_t ko = (size_t)(j * 128 + row) * HDQ + h * DQ + d + cc * 8;
                cp16(dst + 2 * QPL, Kh + ko);
                cp16(dst + 3 * QPL, Kl + ko);
            }
        };

        load_qk(0, 0);
        asm volatile("cp.async.commit_group;");
        load_qk(1, 4 * QPL);
        asm volatile("cp.async.commit_group;");

        // prefetch BOTH V dv-chunks
        #pragma unroll
        for (int dvc = 0; dvc < 2; dvc++) {
            #pragma unroll
            for (int p = 0; p < 8; p++) {
                int id = tid + p * 256;
                int row = id >> 4, cc = id & 15;
                uint32_t dst = sb + (uint32_t)(VOFF + dvc * 2 * VPL + row * 272 + cc * 16);
                size_t vo = (size_t)h * DV * T + (size_t)(dvc * 128 + row) * T + j * 128 + cc * 8;
                cp16(dst,       Vh + vo);
                cp16(dst + VPL, Vl + vo);
            }
        }
        asm volatile("cp.async.commit_group;");

        for (int i = 0; i < 8; i++) {
            asm volatile("cp.async.wait_group 1;");
            __syncthreads();
            const uint32_t st = (uint32_t)((i & 1) * 4 * QPL);
            #pragma unroll
            for (int ks = 0; ks < 2; ks++) {
                uint32_t ah[4], al[4];
                uint32_t ad = sb + st + (uint32_t)((w * 16 + lr) * 80 + lkb + ks * 32);
                ldsm4(ah[0], ah[1], ah[2], ah[3], ad);
                ldsm4(al[0], al[1], al[2], al[3], ad + QPL);
                #pragma unroll
                for (int p = 0; p < 8; p++) {
                    uint32_t bh[2][2], bl[2][2], x0, x1, x2, x3;
                    uint32_t bd = sb + st + (uint32_t)(2 * QPL + (p * 16 + lr) * 80 + lkb + ks * 32);
                    ldsm4(x0, x1, x2, x3, bd);
                    bh[0][0] = x0; bh[1][0] = x1; bh[0][1] = x2; bh[1][1] = x3;
                    ldsm4(x0, x1, x2, x3, bd + QPL);
                    bl[0][0] = x0; bl[1][0] = x1; bl[0][1] = x2; bl[1][1] = x3;
                    #pragma unroll
                    for (int q2 = 0; q2 < 2; q2++) {
                        float* c = sacc[p * 2 + q2];
                        mma_bf16(c, ah, bh[q2]);
                        mma_bf16(c, ah, bl[q2]);
                        mma_bf16(c, al, bh[q2]);
                    }
                }
            }
            __syncthreads();
            if (i + 2 < 8) load_qk(i + 2, st);
            asm volatile("cp.async.commit_group;");
        }
        asm volatile("cp.async.wait_group 0;");

        // ---------------- softmax (registers) ----------------
        #pragma unroll
        for (int nt = 0; nt < 16; nt++)
            #pragma unroll
            for (int c = 0; c < 4; c++) sacc[nt][c] *= scale;

        if (j == qi) {
            const int rr0 = w * 16 + g, rr1 = rr0 + 8;
            #pragma unroll
            for (int nt = 0; nt < 16; nt++) {
                int col = nt * 8 + 2 * t4;
                if (col     > rr0) sacc[nt][0] = -1e30f;
                if (col + 1 > rr0) sacc[nt][1] = -1e30f;
                if (col     > rr1) sacc[nt][2] = -1e30f;
                if (col + 1 > rr1) sacc[nt][3] = -1e30f;
            }
        }

        float tm0 = -1e30f, tm1 = -1e30f;
        #pragma unroll
        for (int nt = 0; nt < 16; nt++) {
            tm0 = fmaxf(tm0, fmaxf(sacc[nt][0], sacc[nt][1]));
            tm1 = fmaxf(tm1, fmaxf(sacc[nt][2], sacc[nt][3]));
        }
        tm0 = fmaxf(tm0, __shfl_xor_sync(0xffffffffu, tm0, 1));
        tm0 = fmaxf(tm0, __shfl_xor_sync(0xffffffffu, tm0, 2));
        tm1 = fmaxf(tm1, __shfl_xor_sync(0xffffffffu, tm1, 1));
        tm1 = fmaxf(tm1, __shfl_xor_sync(0xffffffffu, tm1, 2));

        float nm0 = fmaxf(m0, tm0), nm1 = fmaxf(m1, tm1);
        float a0 = expf(m0 - nm0), a1 = expf(m1 - nm1);
        m0 = nm0; m1 = nm1;

        float s0 = 0.f, s1 = 0.f;
        #pragma unroll
        for (int nt = 0; nt < 16; nt++) {
            sacc[nt][0] = expf(sacc[nt][0] - m0); s0 += sacc[nt][0];
            sacc[nt][1] = expf(sacc[nt][1] - m0); s0 += sacc[nt][1];
            sacc[nt][2] = expf(sacc[nt][2] - m1); s1 += sacc[nt][2];
            sacc[nt][3] = expf(sacc[nt][3] - m1); s1 += sacc[nt][3];
        }
        s0 += __shfl_xor_sync(0xffffffffu, s0, 1);
        s0 += __shfl_xor_sync(0xffffffffu, s0, 2);
        s1 += __shfl_xor_sync(0xffffffffu, s1, 1);
        s1 += __shfl_xor_sync(0xffffffffu, s1, 2);
        l0 = l0 * a0 + s0;
        l1 = l1 * a1 + s1;

        #pragma unroll
        for (int i = 0; i < 32; i++) {
            oacc[i][0] *= a0; oacc[i][1] *= a0;
            oacc[i][2] *= a1; oacc[i][3] *= a1;
        }

        // P fragments (A-operand layout)
        uint32_t Pf0[8][4], Pf1[8][4];
        #pragma unroll
        for (int ks = 0; ks < 8; ks++) {
            #pragma unroll
            for (int hf = 0; hf < 2; hf++) {
                const float* c = sacc[2 * ks + hf];
                __nv_bfloat16 ha, la, hb, lb;
                splitf(c[0], ha, la); splitf(c[1], hb, lb);
                Pf0[ks][hf * 2]     = pack2(ha, hb);
                Pf1[ks][hf * 2]     = pack2(la, lb);
                splitf(c[2], ha, la); splitf(c[3], hb, lb);
                Pf0[ks][hf * 2 + 1] = pack2(ha, hb);
                Pf1[ks][hf * 2 + 1] = pack2(la, lb);
            }
        }

        // ---------------- PV: V resident ----------------
        __syncthreads();
        #pragma unroll
        for (int dvc = 0; dvc < 2; dvc++) {
            #pragma unroll
            for (int ks = 0; ks < 8; ks++) {
                #pragma unroll
                for (int p = 0; p < 8; p++) {
                    uint32_t vh[2][2], vl[2][2], x0, x1, x2, x3;
                    uint32_t bd = sb + (uint32_t)(VOFF + dvc * 2 * VPL + (p * 16 + lr) * 272 + lkb + ks * 32);
                    ldsm4(x0, x1, x2, x3, bd);
                    vh[0][0] = x0; vh[1][0] = x1; vh[0][1] = x2; vh[1][1] = x3;
                    ldsm4(x0, x1, x2, x3, bd + VPL);
                    vl[0][0] = x0; vl[1][0] = x1; vl[0][1] = x2; vl[1][1] = x3;
                    #pragma unroll
                    for (int q2 = 0; q2 < 2; q2++) {
                        float* c = oacc[dvc * 16 + p * 2 + q2];
                        mma_bf16(c, Pf0[ks], vh[q2]);
                        mma_bf16(c, Pf0[ks], vl[q2]);
                        mma_bf16(c, Pf1[ks], vh[q2]);
                    }
                }
            }
        }
        __syncthreads();
    }

    // ---------------- epilogue: fp16 O ----------------
    const float i0 = 1.f / l0, i1 = 1.f / l1;
    const int r0 = qi * 128 + w * 16 + g;
    __half* o0 = Of + (size_t)r0 * HDQ + h * DV;
    __half* o1 = o0 + (size_t)8 * HDQ;
    #pragma unroll
    for (int nt = 0; nt < 32; nt++) {
        int c = nt * 8 + 2 * t4;
        __half2 v0 = __floats2half2_rn(oacc[nt][0] * i0, oacc[nt][1] * i0);
        __half2 v1 = __floats2half2_rn(oacc[nt][2] * i1, oacc[nt][3] * i1);
        *(__half2*)&o0[c] = v0;
        *(__half2*)&o1[c] = v1;
    }
}

// ---------------- fp32 -> fp16 (single plane) ----------------
__global__ void conv_f16_k(const float* __restrict__ x, __half* __restrict__ h, long n)
{
    long i = (long)blockIdx.x * blockDim.x + threadIdx.x;
    long stride = (long)gridDim.x * blockDim.x;
    for (; i < n; i += stride) h[i] = __float2half_rn(x[i]);
}

// ---------------- fp32 [R,C] -> fp16 planes transposed [C,R] ----------------
__global__ void conv_tr_f16_k(const float* __restrict__ x, __half* __restrict__ h,
                              __half* __restrict__ l, int R, int C)
{
    __shared__ float tile[32][33];
    const int c0 = blockIdx.x * 32, rr0 = blockIdx.y * 32;
    const int tx = threadIdx.x & 31, ty = threadIdx.x >> 5;
    #pragma unroll
    for (int i = 0; i < 4; i++) {
        int r = rr0 + ty + i * 8;
        tile[ty + i * 8][tx] = x[(long)r * C + c0 + tx];
    }
    __syncthreads();
    #pragma unroll
    for (int i = 0; i < 4; i++) {
        int c = c0 + ty + i * 8;
        float v = tile[tx][ty + i * 8];
        long o = (long)c * R + rr0 + tx;
        __half hh, ll;
        splith(v, hh, ll);
        h[o] = hh; l[o] = ll;
    }
}

// ---------------- RMSNorm fp32 -> fp16 (single plane) ----------------
__global__ void rmsnorm_f16_k(const float* __restrict__ x, const float* __restrict__ w,
                              __half* __restrict__ o, int N, int ldin)
{
    const float* p = x + (long)blockIdx.x * ldin;
    __shared__ float red[8];
    __shared__ float bc;
    const int lane = threadIdx.x & 31, wid = threadIdx.x >> 5;

    float s = 0.f;
    for (int j = threadIdx.x; j < N; j += blockDim.x) { float v = p[j]; s += v * v; }
    #pragma unroll
    for (int of = 16; of; of >>= 1) s += __shfl_xor_sync(0xffffffffu, s, of);
    if (lane == 0) red[wid] = s;
    __syncthreads();
    if (threadIdx.x == 0) {
        float v = 0.f;
        for (int wI = 0; wI < 8; wI++) v += red[wI];
        bc = rsqrtf(v / N + 1e-6f);
    }
    __syncthreads();
    float r = bc;
    long ob = (long)blockIdx.x * N;
    for (int j = threadIdx.x; j < N; j += blockDim.x)
        o[ob + j] = __float2half_rn(p[j] * r * w[j]);
}

// ---------------- rope k_pe in-place ----------------
__global__ void rope_kpe_k(float* __restrict__ lat, const int* __restrict__ pos)
{
    const int tt = blockIdx.x, i = threadIdx.x;
    double inv = pow(10000.0, -(double)i / 32.0);
    double sd, cd;
    sincos((double)pos[tt] * inv, &sd, &cd);
    float c = (float)cd, s = (float)sd;
    float* p = lat + (long)tt * LATW + DKV;
    float x1 = p[i], x2 = p[i + 32];
    p[i]      = x1 * c - x2 * s;
    p[i + 32] = x2 * c + x1 * s;
}

// ---------------- q: rope fused + bf16 planes ----------------
__global__ void rope_conv_q_k(const float* __restrict__ q, const int* __restrict__ pos,
                              __nv_bfloat16* __restrict__ h, __nv_bfloat16* __restrict__ l)
{
    const int tt = blockIdx.x;
    __shared__ float cs[32], sn[32];
    if (threadIdx.x < 32) {
        double inv = pow(10000.0, -(double)threadIdx.x / 32.0);
        double sd, cd;
        sincos((double)pos[tt] * inv, &sd, &cd);
        cs[threadIdx.x] = (float)cd; sn[threadIdx.x] = (float)sd;
    }
    __syncthreads();
    const float* row = q + (long)tt * HDQ;
    long ob = (long)tt * HDQ;
    for (int x = threadIdx.x; x < HDQ; x += blockDim.x) {
        int d = x & 255;
        float v;
        if (d < DN)            v = row[x];
        else if (d < DN + 32) { int i = d - DN;       v = row[x] * cs[i] - row[x + 32] * sn[i]; }
        else                  { int i = d - DN - 32;  v = row[x] * cs[i] + row[x - 32] * sn[i]; }
        __nv_bfloat16 hh, ll;
        splitf(v, hh, ll);
        h[ob + x] = hh; l[ob + x] = ll;
    }
}

// ---------------- K assembly -> bf16 planes ----------------
__global__ void build_K_pl_k(const float* __restrict__ kv, const float* __restrict__ lat,
                             __nv_bfloat16* __restrict__ h, __nv_bfloat16* __restrict__ l)
{
    const int tt = blockIdx.x;
    long ob = (long)tt * HDQ;
    for (int x = threadIdx.x; x < HDQ; x += blockDim.x) {
        int hd = x >> 8, d = x & 255;
        float v = (d < DN) ? kv[(long)tt * KVW + hd * (DN + DV) + d]
                           : lat[(long)tt * LATW + DKV + (d - DN)];
        __nv_bfloat16 hh, ll;
        splitf(v, hh, ll);
        h[ob + x] = hh; l[ob + x] = ll;
    }
}

// ---------------- V transpose per head -> bf16 planes [h][DV][T] ----------------
__global__ void transpose_v_pl_k(const float* __restrict__ kv,
                                 __nv_bfloat16* __restrict__ h, __nv_bfloat16* __restrict__ l)
{
    __shared__ float tile[32][33];
    const int d0 = blockIdx.x * 32, t0 = blockIdx.y * 32, hd = blockIdx.z;
    const int tx = threadIdx.x & 31, ty = threadIdx.x >> 5;
    #pragma unroll
    for (int i = 0; i < 4; i++) {
        int tr = t0 + ty + i * 8;
        tile[ty + i * 8][tx] = kv[(long)tr * KVW + hd * (DN + DV) + DN + d0 + tx];
    }
    __syncthreads();
    #pragma unroll
    for (int i = 0; i < 4; i++) {
        int d = d0 + ty + i * 8;
        float v = tile[tx][ty + i * 8];
        long o = (long)hd * DV * T + (long)d * T + t0 + tx;
        __nv_bfloat16 hh, ll;
        splitf(v, hh, ll);
        h[o] = hh; l[o] = ll;
    }
}

// ---------------- launch ----------------
extern "C" void kernel_launch(void* const* d_in, const int* in_sizes, int n_in,
                              void* d_out, int out_size)
{
    (void)in_sizes; (void)n_in; (void)out_size;
    const float* hidden = (const float*)d_in[0];
    const int*   pos    = (const int*)  d_in[1];
    const float* wq_a   = (const float*)d_in[2];
    const float* q_ln   = (const float*)d_in[3];
    const float* wq_b   = (const float*)d_in[4];
    const float* wkv_a  = (const float*)d_in[5];
    const float* kv_ln  = (const float*)d_in[6];
    const float* wkv_b  = (const float*)d_in[7];
    const float* wo     = (const float*)d_in[8];
    float* out = (float*)d_out;

    cudaFuncSetAttribute(tgemm_f16, cudaFuncAttributeMaxDynamicSharedMemorySize, SMEM_F16);
    cudaFuncSetAttribute(flash_k,   cudaFuncAttributeMaxDynamicSharedMemorySize, FA_SMEM);

    float *qlora, *latent, *q, *kv;
    cudaGetSymbolAddress((void**)&qlora,  g_qlora);
    cudaGetSymbolAddress((void**)&latent, g_latent);
    cudaGetSymbolAddress((void**)&q,      g_q);
    cudaGetSymbolAddress((void**)&kv,     g_kv);

    __nv_bfloat16 *qp, *Kcp, *Vtp;
    cudaGetSymbolAddress((void**)&qp,  g_q_p);
    cudaGetSymbolAddress((void**)&Kcp, g_Kc_p);
    cudaGetSymbolAddress((void**)&Vtp, g_Vt_p);

    __half *hidf, *qlof, *latf, *Ofp, *wqaTf, *wkvaTf, *wqbTf, *wkvbTf, *woTf;
    cudaGetSymbolAddress((void**)&hidf,   g_hid_f);
    cudaGetSymbolAddress((void**)&qlof,   g_qlo_f);
    cudaGetSymbolAddress((void**)&latf,   g_lat_f);
    cudaGetSymbolAddress((void**)&Ofp,    g_Of);
    cudaGetSymbolAddress((void**)&wqaTf,  g_wqaTf);
    cudaGetSymbolAddress((void**)&wkvaTf, g_wkvaTf);
    cudaGetSymbolAddress((void**)&wqbTf,  g_wqbTf);
    cudaGetSymbolAddress((void**)&wkvbTf, g_wkvbTf);
    cudaGetSymbolAddress((void**)&woTf,   g_woTf);

    #define PL(base, n) (base), ((base) + (size_t)(n))

    const size_t nWqa = (size_t)QLORA * HID, nWkva = (size_t)LATW * HID;
    const size_t nWqb = (size_t)HDQ * QLORA, nWkvb = (size_t)KVW * DKV;
    const size_t nWo  = (size_t)HID * HDQ;
    const size_t nQ   = (size_t)T * HDQ;
    const size_t nVt  = (size_t)NH * DV * T;

    dim3 blk(256);

    // ---- conversions ----
    conv_tr_f16_k<<<dim3(QLORA/32, HID/32), blk>>>(wq_a,  PL(wqaTf,  nWqa), HID, QLORA);
    conv_tr_f16_k<<<dim3(LATW/32,  HID/32), blk>>>(wkv_a, PL(wkvaTf, nWkva), HID, LATW);
    conv_tr_f16_k<<<dim3(HDQ/32, QLORA/32), blk>>>(wq_b,  PL(wqbTf,  nWqb), QLORA, HDQ);
    conv_tr_f16_k<<<dim3(KVW/32,  DKV/32),  blk>>>(wkv_b, PL(wkvbTf, nWkvb), DKV, KVW);
    conv_tr_f16_k<<<dim3(HID/32,  HDQ/32),  blk>>>(wo,    PL(woTf,   nWo),  HDQ, HID);
    conv_f16_k<<<2048, 256>>>(hidden, hidf, (long)T * HID);

    // ---- down projections (fp16 2-pass) ----
    tgemm_f16<<<dim3(QLORA/128, T/128), blk, SMEM_F16>>>(hidf, PL(wqaTf, nWqa),
        qlora, T, QLORA, HID, HID, HID, QLORA);
    tgemm_f16<<<dim3((LATW+127)/128, T/128), blk, SMEM_F16>>>(hidf, PL(wkvaTf, nWkva),
        latent, T, LATW, HID, HID, HID, LATW);

    // ---- norms + rope(k_pe) ----
    rmsnorm_f16_k<<<T, 256>>>(qlora, q_ln, qlof, QLORA, QLORA);
    rope_kpe_k<<<T, 32>>>(latent, pos);
    rmsnorm_f16_k<<<T, 256>>>(latent, kv_ln, latf, DKV, LATW);

    // ---- up projections (fp16 2-pass) ----
    tgemm_f16<<<dim3(HDQ/128, T/128), blk, SMEM_F16>>>(qlof, PL(wqbTf, nWqb),
        q, T, HDQ, QLORA, QLORA, QLORA, HDQ);
    tgemm_f16<<<dim3(KVW/128, T/128), blk, SMEM_F16>>>(latf, PL(wkvbTf, nWkvb),
        kv, T, KVW, DKV, DKV, DKV, KVW);

    // ---- q rope + planes; K assembly; V transpose (bf16 3-term flash inputs) ----
    rope_conv_q_k<<<T, 256>>>(q, pos, PL(qp, nQ));
    build_K_pl_k<<<T, 256>>>(kv, latent, PL(Kcp, nQ));
    transpose_v_pl_k<<<dim3(DV/32, T/32, NH), blk>>>(kv, PL(Vtp, nVt));

    // ---- fused flash attention (fp16 O out) ----
    flash_k<<<dim3(T/128, NH), blk, FA_SMEM>>>(
        PL(qp, nQ), PL(Kcp, nQ), PL(Vtp, nVt), Ofp);

    // ---- final projection (fp16 2-pass) ----
    tgemm_f16<<<dim3(HID/128, T/128), blk, SMEM_F16>>>(Ofp, PL(woTf, nWo),
        out, T, HID, HDQ, HDQ, HDQ, HID);

    #undef PL
}

// round 10
// speedup vs baseline: 1.6942x; 1.3115x over previous
#include <cuda_runtime.h>
#include <cuda_bf16.h>
#include <cuda_fp16.h>
#include <math.h>
#include <stdint.h>

// ---------------- problem constants ----------------
constexpr int T    = 2048;
constexpr int HID  = 4096;
constexpr int NH   = 32;
constexpr int DQ   = 256;
constexpr int DN   = 192;
constexpr int DR   = 64;
constexpr int DV   = 256;
constexpr int DKV  = 512;
constexpr int QLORA= 2048;
constexpr int HDQ  = NH * DQ;        // 8192
constexpr int KVW  = NH * (DN + DV); // 14336
constexpr int LATW = DKV + DR;       // 576

// ---------------- fp32 scratch ----------------
__device__ float g_qlora[(size_t)T * QLORA];
__device__ float g_latent[(size_t)T * LATW];
__device__ float g_q[(size_t)T * HDQ];
__device__ float g_kv[(size_t)T * KVW];

// ---------------- fp16 buffers ----------------
__device__ __half g_hid_f  [(size_t)T * HID];
__device__ __half g_qlo_f  [(size_t)T * QLORA];
__device__ __half g_lat_f  [(size_t)T * DKV];
__device__ __half g_Of     [(size_t)T * HDQ];
__device__ __half g_qf     [(size_t)T * HDQ];          // Q single plane
__device__ __half g_Kc_f   [2][(size_t)T * HDQ];       // K hi/lo
__device__ __half g_Vt_f   [2][(size_t)NH * DV * T];   // V^T hi/lo
__device__ __half g_wqaTf  [2][(size_t)QLORA * HID];
__device__ __half g_wkvaTf [2][(size_t)LATW * HID];
__device__ __half g_wqbTf  [2][(size_t)HDQ * QLORA];
__device__ __half g_wkvbTf [2][(size_t)KVW * DKV];
__device__ __half g_woTf   [(size_t)HID * HDQ];        // wo single plane (1-pass)

// ---------------- helpers ----------------
__device__ __forceinline__ void splith(float v, __half& h, __half& l) {
    h = __float2half_rn(v);
    l = __float2half_rn(v - __half2float(h));
}

__device__ __forceinline__ void mma_f16(float* c, const uint32_t* a, const uint32_t* b) {
    asm volatile(
        "mma.sync.aligned.m16n8k16.row.col.f32.f16.f16.f32 "
        "{%0,%1,%2,%3}, {%4,%5,%6,%7}, {%8,%9}, {%0,%1,%2,%3};\n"
        : "+f"(c[0]), "+f"(c[1]), "+f"(c[2]), "+f"(c[3])
        : "r"(a[0]), "r"(a[1]), "r"(a[2]), "r"(a[3]), "r"(b[0]), "r"(b[1]));
}

__device__ __forceinline__ void ldsm4(uint32_t& r0, uint32_t& r1, uint32_t& r2, uint32_t& r3, uint32_t a) {
    asm volatile("ldmatrix.sync.aligned.m8n8.x4.shared.b16 {%0,%1,%2,%3}, [%4];"
        : "=r"(r0), "=r"(r1), "=r"(r2), "=r"(r3) : "r"(a));
}

__device__ __forceinline__ void cp16(uint32_t d, const void* s) {
    asm volatile("cp.async.cg.shared.global [%0], [%1], 16;" :: "r"(d), "l"(s));
}

// ============================================================================
// 2-pass fp16 GEMM: C = Ah @ (Bh + Bl)^T (proven R8/R9 kernel).
// ============================================================================
constexpr int F_TILE  = 128 * 80;
constexpr int F_STAGE = 3 * F_TILE;
constexpr int SMEM_F16 = 2 * F_STAGE;    // 61440

__global__ __launch_bounds__(256, 2) void tgemm_f16(
    const __half* __restrict__ Ah,
    const __half* __restrict__ Bh, const __half* __restrict__ Bl,
    float* __restrict__ C,
    int M, int N, int K, int lda, int ldb, int ldc)
{
    const int bx = blockIdx.x, by = blockIdx.y;

    extern __shared__ char smem[];
    const uint32_t sb = (uint32_t)__cvta_generic_to_shared(smem);

    const int tid = threadIdx.x, lane = tid & 31, warp = tid >> 5;
    const int wm = warp & 1, wn = warp >> 1;
    const int g = lane >> 2, t4 = lane & 3;
    const int r0 = tid >> 2, c4 = tid & 3;
    const int Nm1 = N - 1;

    const int lr  = (lane & 7) + ((lane >> 3) & 1) * 8;
    const int lkb = (lane >> 4) * 16;
    const uint32_t aBase = sb + (uint32_t)((wm * 64 + lr) * 80 + lkb);
    const uint32_t bBase = sb + (uint32_t)(F_TILE + (wn * 32 + lr) * 80 + lkb);

    float acc[4][4][4] = {};
    const int nchunks = K / 32;

    auto load_chunk = [&](int k0, uint32_t st) {
        #pragma unroll
        for (int c = 0; c < 2; c++) {
            int row = r0 + c * 64;
            uint32_t ds = sb + st + (uint32_t)(row * 80 + c4 * 16);
            long aoff = (long)(by * 128 + row) * lda + k0 + c4 * 8;
            cp16(ds, Ah + aoff);
            int nr = bx * 128 + row; if (nr > Nm1) nr = Nm1;
            long boff = (long)nr * ldb + k0 + c4 * 8;
            cp16(ds + F_TILE,     Bh + boff);
            cp16(ds + 2 * F_TILE, Bl + boff);
        }
    };

    load_chunk(0, 0);
    asm volatile("cp.async.commit_group;");

    for (int i = 0; i < nchunks; i++) {
        if (i + 1 < nchunks)
            load_chunk((i + 1) * 32, (uint32_t)(((i + 1) & 1) * F_STAGE));
        asm volatile("cp.async.commit_group;");
        asm volatile("cp.async.wait_group 1;");
        __syncthreads();

        const uint32_t sof = (uint32_t)((i & 1) * F_STAGE);
        #pragma unroll
        for (int ks = 0; ks < 2; ks++) {
            uint32_t bh[4][2], bl[4][2];
            #pragma unroll
            for (int p = 0; p < 2; p++) {
                uint32_t ad = bBase + sof + (uint32_t)(p * 16 * 80 + ks * 32);
                uint32_t x0, x1, x2, x3;
                ldsm4(x0, x1, x2, x3, ad);
                bh[2*p][0] = x0; bh[2*p+1][0] = x1; bh[2*p][1] = x2; bh[2*p+1][1] = x3;
                ldsm4(x0, x1, x2, x3, ad + F_TILE);
                bl[2*p][0] = x0; bl[2*p+1][0] = x1; bl[2*p][1] = x2; bl[2*p+1][1] = x3;
            }
            #pragma unroll
            for (int mt = 0; mt < 4; mt++) {
                uint32_t ah[4];
                uint32_t ad = aBase + sof + (uint32_t)(mt * 16 * 80 + ks * 32);
                ldsm4(ah[0], ah[1], ah[2], ah[3], ad);
                #pragma unroll
                for (int nt = 0; nt < 4; nt++) {
                    mma_f16(acc[mt][nt], ah, bh[nt]);
                    mma_f16(acc[mt][nt], ah, bl[nt]);
                }
            }
        }
        __syncthreads();
    }

    #pragma unroll
    for (int mt = 0; mt < 4; mt++) {
        int r = by * 128 + wm * 64 + mt * 16 + g;
        #pragma unroll
        for (int nt = 0; nt < 4; nt++) {
            int c = bx * 128 + wn * 32 + nt * 8 + 2 * t4;
            if (c < N) {
                *(float2*)&C[(long)r * ldc + c]       = make_float2(acc[mt][nt][0], acc[mt][nt][1]);
                *(float2*)&C[(long)(r + 8) * ldc + c] = make_float2(acc[mt][nt][2], acc[mt][nt][3]);
            }
        }
    }
}

// ============================================================================
// 1-pass fp16 GEMM (wo): C = Ah @ Bh^T.  2 smem planes.
// ============================================================================
constexpr int P_STAGE = 2 * F_TILE;      // 20480
constexpr int SMEM_1P = 2 * P_STAGE;     // 40960

__global__ __launch_bounds__(256, 2) void tgemm_1p(
    const __half* __restrict__ Ah, const __half* __restrict__ Bh,
    float* __restrict__ C,
    int M, int N, int K, int lda, int ldb, int ldc)
{
    const int bx = blockIdx.x, by = blockIdx.y;

    extern __shared__ char smem[];
    const uint32_t sb = (uint32_t)__cvta_generic_to_shared(smem);

    const int tid = threadIdx.x, lane = tid & 31, warp = tid >> 5;
    const int wm = warp & 1, wn = warp >> 1;
    const int g = lane >> 2, t4 = lane & 3;
    const int r0 = tid >> 2, c4 = tid & 3;
    const int Nm1 = N - 1;

    const int lr  = (lane & 7) + ((lane >> 3) & 1) * 8;
    const int lkb = (lane >> 4) * 16;
    const uint32_t aBase = sb + (uint32_t)((wm * 64 + lr) * 80 + lkb);
    const uint32_t bBase = sb + (uint32_t)(F_TILE + (wn * 32 + lr) * 80 + lkb);

    float acc[4][4][4] = {};
    const int nchunks = K / 32;

    auto load_chunk = [&](int k0, uint32_t st) {
        #pragma unroll
        for (int c = 0; c < 2; c++) {
            int row = r0 + c * 64;
            uint32_t ds = sb + st + (uint32_t)(row * 80 + c4 * 16);
            long aoff = (long)(by * 128 + row) * lda + k0 + c4 * 8;
            cp16(ds, Ah + aoff);
            int nr = bx * 128 + row; if (nr > Nm1) nr = Nm1;
            long boff = (long)nr * ldb + k0 + c4 * 8;
            cp16(ds + F_TILE, Bh + boff);
        }
    };

    load_chunk(0, 0);
    asm volatile("cp.async.commit_group;");

    for (int i = 0; i < nchunks; i++) {
        if (i + 1 < nchunks)
            load_chunk((i + 1) * 32, (uint32_t)(((i + 1) & 1) * P_STAGE));
        asm volatile("cp.async.commit_group;");
        asm volatile("cp.async.wait_group 1;");
        __syncthreads();

        const uint32_t sof = (uint32_t)((i & 1) * P_STAGE);
        #pragma unroll
        for (int ks = 0; ks < 2; ks++) {
            uint32_t bh[4][2];
            #pragma unroll
            for (int p = 0; p < 2; p++) {
                uint32_t ad = bBase + sof + (uint32_t)(p * 16 * 80 + ks * 32);
                uint32_t x0, x1, x2, x3;
                ldsm4(x0, x1, x2, x3, ad);
                bh[2*p][0] = x0; bh[2*p+1][0] = x1; bh[2*p][1] = x2; bh[2*p+1][1] = x3;
            }
            #pragma unroll
            for (int mt = 0; mt < 4; mt++) {
                uint32_t ah[4];
                uint32_t ad = aBase + sof + (uint32_t)(mt * 16 * 80 + ks * 32);
                ldsm4(ah[0], ah[1], ah[2], ah[3], ad);
                #pragma unroll
                for (int nt = 0; nt < 4; nt++)
                    mma_f16(acc[mt][nt], ah, bh[nt]);
            }
        }
        __syncthreads();
    }

    #pragma unroll
    for (int mt = 0; mt < 4; mt++) {
        int r = by * 128 + wm * 64 + mt * 16 + g;
        #pragma unroll
        for (int nt = 0; nt < 4; nt++) {
            int c = bx * 128 + wn * 32 + nt * 8 + 2 * t4;
            if (c < N) {
                *(float2*)&C[(long)r * ldc + c]       = make_float2(acc[mt][nt][0], acc[mt][nt][1]);
                *(float2*)&C[(long)(r + 8) * ldc + c] = make_float2(acc[mt][nt][2], acc[mt][nt][3]);
            }
        }
    }
}

// ============================================================================
// Fused flash attention, fp16 2-term: Q single plane, K/V hi+lo planes,
// P single fp16. V fully prefetched; fp16 O output.
// smem: QK 2 stages x 3 planes x 10240 = 61440; V 4 x 34816 at 61440.
// ============================================================================
constexpr int QPL  = 10240;
constexpr int VPL  = 34816;
constexpr int VOFF = 61440;
constexpr int FA_SMEM = VOFF + 4 * VPL;   // 200704

__global__ __launch_bounds__(256, 1) void flash_k(
    const __half* __restrict__ Qf,
    const __half* __restrict__ Kh, const __half* __restrict__ Kl,
    const __half* __restrict__ Vh, const __half* __restrict__ Vl,
    __half* __restrict__ Of)
{
    const int qi = gridDim.x - 1 - blockIdx.x;   // heavy tiles first
    const int h  = blockIdx.y;

    extern __shared__ char smem[];
    const uint32_t sb = (uint32_t)__cvta_generic_to_shared(smem);

    const int tid = threadIdx.x, lane = tid & 31, w = tid >> 5;
    const int g = lane >> 2, t4 = lane & 3;
    const int lr  = (lane & 7) + ((lane >> 3) & 1) * 8;
    const int lkb = (lane >> 4) * 16;

    float oacc[32][4];
    #pragma unroll
    for (int i = 0; i < 32; i++)
        #pragma unroll
        for (int c = 0; c < 4; c++) oacc[i][c] = 0.f;
    float m0 = -1e30f, m1 = -1e30f, l0 = 0.f, l1 = 0.f;

    const float scale = 0.0625f;

    for (int j = 0; j <= qi; j++) {
        float sacc[16][4] = {};

        auto load_qk = [&](int i, uint32_t st) {
            const int d = i * 32;
            #pragma unroll
            for (int p = 0; p < 2; p++) {
                int id = tid + p * 256;
                int row = id >> 2, cc = id & 3;
                uint32_t dst = sb + st + (uint32_t)(row * 80 + cc * 16);
                size_t qo = (size_t)(qi * 128 + row) * HDQ + h * DQ + d + cc * 8;
                cp16(dst, Qf + qo);
                size_t ko = (size_t)(j * 128 + row) * HDQ + h * DQ + d + cc * 8;
                cp16(dst + QPL,     Kh + ko);
                cp16(dst + 2 * QPL, Kl + ko);
            }
        };

        load_qk(0, 0);
        asm volatile("cp.async.commit_group;");
        load_qk(1, 3 * QPL);
        asm volatile("cp.async.commit_group;");

        // prefetch BOTH V dv-chunks (hi+lo)
        #pragma unroll
        for (int dvc = 0; dvc < 2; dvc++) {
            #pragma unroll
            for (int p = 0; p < 8; p++) {
                int id = tid + p * 256;
                int row = id >> 4, cc = id & 15;
                uint32_t dst = sb + (uint32_t)(VOFF + dvc * 2 * VPL + row * 272 + cc * 16);
                size_t vo = (size_t)h * DV * T + (size_t)(dvc * 128 + row) * T + j * 128 + cc * 8;
                cp16(dst,       Vh + vo);
                cp16(dst + VPL, Vl + vo);
            }
        }
        asm volatile("cp.async.commit_group;");

        for (int i = 0; i < 8; i++) {
            asm volatile("cp.async.wait_group 1;");
            __syncthreads();
            const uint32_t st = (uint32_t)((i & 1) * 3 * QPL);
            #pragma unroll
            for (int ks = 0; ks < 2; ks++) {
                uint32_t ah[4];
                uint32_t ad = sb + st + (uint32_t)((w * 16 + lr) * 80 + lkb + ks * 32);
                ldsm4(ah[0], ah[1], ah[2], ah[3], ad);
                #pragma unroll
                for (int p = 0; p < 8; p++) {
                    uint32_t bh[2][2], bl[2][2], x0, x1, x2, x3;
                    uint32_t bd = sb + st + (uint32_t)(QPL + (p * 16 + lr) * 80 + lkb + ks * 32);
                    ldsm4(x0, x1, x2, x3, bd);
                    bh[0][0] = x0; bh[1][0] = x1; bh[0][1] = x2; bh[1][1] = x3;
                    ldsm4(x0, x1, x2, x3, bd + QPL);
                    bl[0][0] = x0; bl[1][0] = x1; bl[0][1] = x2; bl[1][1] = x3;
                    #pragma unroll
                    for (int q2 = 0; q2 < 2; q2++) {
                        float* c = sacc[p * 2 + q2];
                        mma_f16(c, ah, bh[q2]);
                        mma_f16(c, ah, bl[q2]);
                    }
                }
            }
            __syncthreads();
            if (i + 2 < 8) load_qk(i + 2, st);
            asm volatile("cp.async.commit_group;");
        }
        asm volatile("cp.async.wait_group 0;");

        // ---------------- softmax (registers) ----------------
        #pragma unroll
        for (int nt = 0; nt < 16; nt++)
            #pragma unroll
            for (int c = 0; c < 4; c++) sacc[nt][c] *= scale;

        if (j == qi) {
            const int rr0 = w * 16 + g, rr1 = rr0 + 8;
            #pragma unroll
            for (int nt = 0; nt < 16; nt++) {
                int col = nt * 8 + 2 * t4;
                if (col     > rr0) sacc[nt][0] = -1e30f;
                if (col + 1 > rr0) sacc[nt][1] = -1e30f;
                if (col     > rr1) sacc[nt][2] = -1e30f;
                if (col + 1 > rr1) sacc[nt][3] = -1e30f;
            }
        }

        float tm0 = -1e30f, tm1 = -1e30f;
        #pragma unroll
        for (int nt = 0; nt < 16; nt++) {
            tm0 = fmaxf(tm0, fmaxf(sacc[nt][0], sacc[nt][1]));
            tm1 = fmaxf(tm1, fmaxf(sacc[nt][2], sacc[nt][3]));
        }
        tm0 = fmaxf(tm0, __shfl_xor_sync(0xffffffffu, tm0, 1));
        tm0 = fmaxf(tm0, __shfl_xor_sync(0xffffffffu, tm0, 2));
        tm1 = fmaxf(tm1, __shfl_xor_sync(0xffffffffu, tm1, 1));
        tm1 = fmaxf(tm1, __shfl_xor_sync(0xffffffffu, tm1, 2));

        float nm0 = fmaxf(m0, tm0), nm1 = fmaxf(m1, tm1);
        float a0 = expf(m0 - nm0), a1 = expf(m1 - nm1);
        m0 = nm0; m1 = nm1;

        float s0 = 0.f, s1 = 0.f;
        #pragma unroll
        for (int nt = 0; nt < 16; nt++) {
            sacc[nt][0] = expf(sacc[nt][0] - m0); s0 += sacc[nt][0];
            sacc[nt][1] = expf(sacc[nt][1] - m0); s0 += sacc[nt][1];
            sacc[nt][2] = expf(sacc[nt][2] - m1); s1 += sacc[nt][2];
            sacc[nt][3] = expf(sacc[nt][3] - m1); s1 += sacc[nt][3];
        }
        s0 += __shfl_xor_sync(0xffffffffu, s0, 1);
        s0 += __shfl_xor_sync(0xffffffffu, s0, 2);
        s1 += __shfl_xor_sync(0xffffffffu, s1, 1);
        s1 += __shfl_xor_sync(0xffffffffu, s1, 2);
        l0 = l0 * a0 + s0;
        l1 = l1 * a1 + s1;

        #pragma unroll
        for (int i = 0; i < 32; i++) {
            oacc[i][0] *= a0; oacc[i][1] *= a0;
            oacc[i][2] *= a1; oacc[i][3] *= a1;
        }

        // P fragments: single fp16 plane (A-operand layout)
        uint32_t Pf[8][4];
        #pragma unroll
        for (int ks = 0; ks < 8; ks++) {
            #pragma unroll
            for (int hf = 0; hf < 2; hf++) {
                const float* c = sacc[2 * ks + hf];
                __half2 v01 = __floats2half2_rn(c[0], c[1]);
                __half2 v23 = __floats2half2_rn(c[2], c[3]);
                Pf[ks][hf * 2]     = *(uint32_t*)&v01;
                Pf[ks][hf * 2 + 1] = *(uint32_t*)&v23;
            }
        }

        // ---------------- PV (2-term): V resident ----------------
        __syncthreads();
        #pragma unroll
        for (int dvc = 0; dvc < 2; dvc++) {
            #pragma unroll
            for (int ks = 0; ks < 8; ks++) {
                #pragma unroll
                for (int p = 0; p < 8; p++) {
                    uint32_t vh[2][2], vl[2][2], x0, x1, x2, x3;
                    uint32_t bd = sb + (uint32_t)(VOFF + dvc * 2 * VPL + (p * 16 + lr) * 272 + lkb + ks * 32);
                    ldsm4(x0, x1, x2, x3, bd);
                    vh[0][0] = x0; vh[1][0] = x1; vh[0][1] = x2; vh[1][1] = x3;
                    ldsm4(x0, x1, x2, x3, bd + VPL);
                    vl[0][0] = x0; vl[1][0] = x1; vl[0][1] = x2; vl[1][1] = x3;
                    #pragma unroll
                    for (int q2 = 0; q2 < 2; q2++) {
                        float* c = oacc[dvc * 16 + p * 2 + q2];
                        mma_f16(c, Pf[ks], vh[q2]);
                        mma_f16(c, Pf[ks], vl[q2]);
                    }
                }
            }
        }
        __syncthreads();
    }

    // ---------------- epilogue: fp16 O ----------------
    const float i0 = 1.f / l0, i1 = 1.f / l1;
    const int r0 = qi * 128 + w * 16 + g;
    __half* o0 = Of + (size_t)r0 * HDQ + h * DV;
    __half* o1 = o0 + (size_t)8 * HDQ;
    #pragma unroll
    for (int nt = 0; nt < 32; nt++) {
        int c = nt * 8 + 2 * t4;
        __half2 v0 = __floats2half2_rn(oacc[nt][0] * i0, oacc[nt][1] * i0);
        __half2 v1 = __floats2half2_rn(oacc[nt][2] * i1, oacc[nt][3] * i1);
        *(__half2*)&o0[c] = v0;
        *(__half2*)&o1[c] = v1;
    }
}

// ---------------- fp32 -> fp16 (single plane) ----------------
__global__ void conv_f16_k(const float* __restrict__ x, __half* __restrict__ h, long n)
{
    long i = (long)blockIdx.x * blockDim.x + threadIdx.x;
    long stride = (long)gridDim.x * blockDim.x;
    for (; i < n; i += stride) h[i] = __float2half_rn(x[i]);
}

// ---------------- fp32 [R,C] -> fp16 planes transposed [C,R] ----------------
__global__ void conv_tr_f16_k(const float* __restrict__ x, __half* __restrict__ h,
                              __half* __restrict__ l, int R, int C)
{
    __shared__ float tile[32][33];
    const int c0 = blockIdx.x * 32, rr0 = blockIdx.y * 32;
    const int tx = threadIdx.x & 31, ty = threadIdx.x >> 5;
    #pragma unroll
    for (int i = 0; i < 4; i++) {
        int r = rr0 + ty + i * 8;
        tile[ty + i * 8][tx] = x[(long)r * C + c0 + tx];
    }
    __syncthreads();
    #pragma unroll
    for (int i = 0; i < 4; i++) {
        int c = c0 + ty + i * 8;
        float v = tile[tx][ty + i * 8];
        long o = (long)c * R + rr0 + tx;
        __half hh, ll;
        splith(v, hh, ll);
        h[o] = hh;
        if (l) l[o] = ll;
    }
}

// ---------------- RMSNorm fp32 -> fp16 ----------------
__global__ void rmsnorm_f16_k(const float* __restrict__ x, const float* __restrict__ w,
                              __half* __restrict__ o, int N, int ldin)
{
    const float* p = x + (long)blockIdx.x * ldin;
    __shared__ float red[8];
    __shared__ float bc;
    const int lane = threadIdx.x & 31, wid = threadIdx.x >> 5;

    float s = 0.f;
    for (int j = threadIdx.x; j < N; j += blockDim.x) { float v = p[j]; s += v * v; }
    #pragma unroll
    for (int of = 16; of; of >>= 1) s += __shfl_xor_sync(0xffffffffu, s, of);
    if (lane == 0) red[wid] = s;
    __syncthreads();
    if (threadIdx.x == 0) {
        float v = 0.f;
        for (int wI = 0; wI < 8; wI++) v += red[wI];
        bc = rsqrtf(v / N + 1e-6f);
    }
    __syncthreads();
    float r = bc;
    long ob = (long)blockIdx.x * N;
    for (int j = threadIdx.x; j < N; j += blockDim.x)
        o[ob + j] = __float2half_rn(p[j] * r * w[j]);
}

// ---------------- rope k_pe in-place ----------------
__global__ void rope_kpe_k(float* __restrict__ lat, const int* __restrict__ pos)
{
    const int tt = blockIdx.x, i = threadIdx.x;
    double inv = pow(10000.0, -(double)i / 32.0);
    double sd, cd;
    sincos((double)pos[tt] * inv, &sd, &cd);
    float c = (float)cd, s = (float)sd;
    float* p = lat + (long)tt * LATW + DKV;
    float x1 = p[i], x2 = p[i + 32];
    p[i]      = x1 * c - x2 * s;
    p[i + 32] = x2 * c + x1 * s;
}

// ---------------- q: rope fused -> fp16 single plane ----------------
__global__ void rope_conv_q_k(const float* __restrict__ q, const int* __restrict__ pos,
                              __half* __restrict__ o)
{
    const int tt = blockIdx.x;
    __shared__ float cs[32], sn[32];
    if (threadIdx.x < 32) {
        double inv = pow(10000.0, -(double)threadIdx.x / 32.0);
        double sd, cd;
        sincos((double)pos[tt] * inv, &sd, &cd);
        cs[threadIdx.x] = (float)cd; sn[threadIdx.x] = (float)sd;
    }
    __syncthreads();
    const float* row = q + (long)tt * HDQ;
    long ob = (long)tt * HDQ;
    for (int x = threadIdx.x; x < HDQ; x += blockDim.x) {
        int d = x & 255;
        float v;
        if (d < DN)            v = row[x];
        else if (d < DN + 32) { int i = d - DN;       v = row[x] * cs[i] - row[x + 32] * sn[i]; }
        else                  { int i = d - DN - 32;  v = row[x] * cs[i] + row[x - 32] * sn[i]; }
        o[ob + x] = __float2half_rn(v);
    }
}

// ---------------- K assembly -> fp16 hi/lo planes ----------------
__global__ void build_K_f16_k(const float* __restrict__ kv, const float* __restrict__ lat,
                              __half* __restrict__ h, __half* __restrict__ l)
{
    const int tt = blockIdx.x;
    long ob = (long)tt * HDQ;
    for (int x = threadIdx.x; x < HDQ; x += blockDim.x) {
        int hd = x >> 8, d = x & 255;
        float v = (d < DN) ? kv[(long)tt * KVW + hd * (DN + DV) + d]
                           : lat[(long)tt * LATW + DKV + (d - DN)];
        __half hh, ll;
        splith(v, hh, ll);
        h[ob + x] = hh; l[ob + x] = ll;
    }
}

// ---------------- V transpose per head -> fp16 hi/lo [h][DV][T] ----------------
__global__ void transpose_v_f16_k(const float* __restrict__ kv,
                                  __half* __restrict__ h, __half* __restrict__ l)
{
    __shared__ float tile[32][33];
    const int d0 = blockIdx.x * 32, t0 = blockIdx.y * 32, hd = blockIdx.z;
    const int tx = threadIdx.x & 31, ty = threadIdx.x >> 5;
    #pragma unroll
    for (int i = 0; i < 4; i++) {
        int tr = t0 + ty + i * 8;
        tile[ty + i * 8][tx] = kv[(long)tr * KVW + hd * (DN + DV) + DN + d0 + tx];
    }
    __syncthreads();
    #pragma unroll
    for (int i = 0; i < 4; i++) {
        int d = d0 + ty + i * 8;
        float v = tile[tx][ty + i * 8];
        long o = (long)hd * DV * T + (long)d * T + t0 + tx;
        __half hh, ll;
        splith(v, hh, ll);
        h[o] = hh; l[o] = ll;
    }
}

// ---------------- launch ----------------
extern "C" void kernel_launch(void* const* d_in, const int* in_sizes, int n_in,
                              void* d_out, int out_size)
{
    (void)in_sizes; (void)n_in; (void)out_size;
    const float* hidden = (const float*)d_in[0];
    const int*   pos    = (const int*)  d_in[1];
    const float* wq_a   = (const float*)d_in[2];
    const float* q_ln   = (const float*)d_in[3];
    const float* wq_b   = (const float*)d_in[4];
    const float* wkv_a  = (const float*)d_in[5];
    const float* kv_ln  = (const float*)d_in[6];
    const float* wkv_b  = (const float*)d_in[7];
    const float* wo     = (const float*)d_in[8];
    float* out = (float*)d_out;

    cudaFuncSetAttribute(tgemm_f16, cudaFuncAttributeMaxDynamicSharedMemorySize, SMEM_F16);
    cudaFuncSetAttribute(tgemm_1p,  cudaFuncAttributeMaxDynamicSharedMemorySize, SMEM_1P);
    cudaFuncSetAttribute(flash_k,   cudaFuncAttributeMaxDynamicSharedMemorySize, FA_SMEM);

    float *qlora, *latent, *q, *kv;
    cudaGetSymbolAddress((void**)&qlora,  g_qlora);
    cudaGetSymbolAddress((void**)&latent, g_latent);
    cudaGetSymbolAddress((void**)&q,      g_q);
    cudaGetSymbolAddress((void**)&kv,     g_kv);

    __half *hidf, *qlof, *latf, *Ofp, *qf, *Kcf, *Vtf,
           *wqaTf, *wkvaTf, *wqbTf, *wkvbTf, *woTf;
    cudaGetSymbolAddress((void**)&hidf,   g_hid_f);
    cudaGetSymbolAddress((void**)&qlof,   g_qlo_f);
    cudaGetSymbolAddress((void**)&latf,   g_lat_f);
    cudaGetSymbolAddress((void**)&Ofp,    g_Of);
    cudaGetSymbolAddress((void**)&qf,     g_qf);
    cudaGetSymbolAddress((void**)&Kcf,    g_Kc_f);
    cudaGetSymbolAddress((void**)&Vtf,    g_Vt_f);
    cudaGetSymbolAddress((void**)&wqaTf,  g_wqaTf);
    cudaGetSymbolAddress((void**)&wkvaTf, g_wkvaTf);
    cudaGetSymbolAddress((void**)&wqbTf,  g_wqbTf);
    cudaGetSymbolAddress((void**)&wkvbTf, g_wkvbTf);
    cudaGetSymbolAddress((void**)&woTf,   g_woTf);

    #define PL(base, n) (base), ((base) + (size_t)(n))

    const size_t nWqa = (size_t)QLORA * HID, nWkva = (size_t)LATW * HID;
    const size_t nWqb = (size_t)HDQ * QLORA, nWkvb = (size_t)KVW * DKV;
    const size_t nQ   = (size_t)T * HDQ;
    const size_t nVt  = (size_t)NH * DV * T;

    dim3 blk(256);

    // ---- conversions ----
    conv_tr_f16_k<<<dim3(QLORA/32, HID/32), blk>>>(wq_a,  PL(wqaTf,  nWqa), HID, QLORA);
    conv_tr_f16_k<<<dim3(LATW/32,  HID/32), blk>>>(wkv_a, PL(wkvaTf, nWkva), HID, LATW);
    conv_tr_f16_k<<<dim3(HDQ/32, QLORA/32), blk>>>(wq_b,  PL(wqbTf,  nWqb), QLORA, HDQ);
    conv_tr_f16_k<<<dim3(KVW/32,  DKV/32),  blk>>>(wkv_b, PL(wkvbTf, nWkvb), DKV, KVW);
    conv_tr_f16_k<<<dim3(HID/32,  HDQ/32),  blk>>>(wo,    woTf, (__half*)nullptr, HDQ, HID);
    conv_f16_k<<<2048, 256>>>(hidden, hidf, (long)T * HID);

    // ---- down projections (fp16 2-pass) ----
    tgemm_f16<<<dim3(QLORA/128, T/128), blk, SMEM_F16>>>(hidf, PL(wqaTf, nWqa),
        qlora, T, QLORA, HID, HID, HID, QLORA);
    tgemm_f16<<<dim3((LATW+127)/128, T/128), blk, SMEM_F16>>>(hidf, PL(wkvaTf, nWkva),
        latent, T, LATW, HID, HID, HID, LATW);

    // ---- norms + rope(k_pe) ----
    rmsnorm_f16_k<<<T, 256>>>(qlora, q_ln, qlof, QLORA, QLORA);
    rope_kpe_k<<<T, 32>>>(latent, pos);
    rmsnorm_f16_k<<<T, 256>>>(latent, kv_ln, latf, DKV, LATW);

    // ---- up projections (fp16 2-pass) ----
    tgemm_f16<<<dim3(HDQ/128, T/128), blk, SMEM_F16>>>(qlof, PL(wqbTf, nWqb),
        q, T, HDQ, QLORA, QLORA, QLORA, HDQ);
    tgemm_f16<<<dim3(KVW/128, T/128), blk, SMEM_F16>>>(latf, PL(wkvbTf, nWkvb),
        kv, T, KVW, DKV, DKV, DKV, KVW);

    // ---- q rope; K assembly; V transpose (fp16 flash inputs) ----
    rope_conv_q_k<<<T, 256>>>(q, pos, qf);
    build_K_f16_k<<<T, 256>>>(kv, latent, PL(Kcf, nQ));
    transpose_v_f16_k<<<dim3(DV/32, T/32, NH), blk>>>(kv, PL(Vtf, nVt));

    // ---- fused flash attention (fp16 2-term) ----
    flash_k<<<dim3(T/128, NH), blk, FA_SMEM>>>(
        qf, PL(Kcf, nQ), PL(Vtf, nVt), Ofp);

    // ---- final projection (fp16 1-pass) ----
    tgemm_1p<<<dim3(HID/128, T/128), blk, SMEM_1P>>>(Ofp, woTf,
        out, T, HID, HDQ, HDQ, HDQ, HID);

    #undef PL
}

// round 11
// speedup vs baseline: 2.0730x; 1.2236x over previous
#include <cuda_runtime.h>
#include <cuda_fp16.h>
#include <math.h>
#include <stdint.h>

// ---------------- problem constants ----------------
constexpr int T    = 2048;
constexpr int HID  = 4096;
constexpr int NH   = 32;
constexpr int DQ   = 256;
constexpr int DN   = 192;
constexpr int DR   = 64;
constexpr int DV   = 256;
constexpr int DKV  = 512;
constexpr int QLORA= 2048;
constexpr int HDQ  = NH * DQ;        // 8192
constexpr int KVW  = NH * (DN + DV); // 14336
constexpr int LATW = DKV + DR;       // 576

// ---------------- fp32 scratch ----------------
__device__ float g_qlora[(size_t)T * QLORA];
__device__ float g_latent[(size_t)T * LATW];
__device__ float g_q[(size_t)T * HDQ];
__device__ float g_kv[(size_t)T * KVW];

// ---------------- fp16 buffers ----------------
__device__ __half g_hid_f  [(size_t)T * HID];
__device__ __half g_qlo_f  [(size_t)T * QLORA];
__device__ __half g_lat_f  [(size_t)T * DKV];
__device__ __half g_Of     [(size_t)T * HDQ];
__device__ __half g_qf     [(size_t)T * HDQ];          // Q single plane
__device__ __half g_Kc_f   [2][(size_t)T * HDQ];       // K hi/lo
__device__ __half g_Vt_f   [2][(size_t)NH * DV * T];   // V^T hi/lo
__device__ __half g_wqaTf  [(size_t)QLORA * HID];
__device__ __half g_wkvaTf [(size_t)LATW * HID];
__device__ __half g_wqbTf  [(size_t)HDQ * QLORA];
__device__ __half g_wkvbTf [(size_t)KVW * DKV];
__device__ __half g_woTf   [(size_t)HID * HDQ];

// ---------------- helpers ----------------
__device__ __forceinline__ void splith(float v, __half& h, __half& l) {
    h = __float2half_rn(v);
    l = __float2half_rn(v - __half2float(h));
}

__device__ __forceinline__ void mma_f16(float* c, const uint32_t* a, const uint32_t* b) {
    asm volatile(
        "mma.sync.aligned.m16n8k16.row.col.f32.f16.f16.f32 "
        "{%0,%1,%2,%3}, {%4,%5,%6,%7}, {%8,%9}, {%0,%1,%2,%3};\n"
        : "+f"(c[0]), "+f"(c[1]), "+f"(c[2]), "+f"(c[3])
        : "r"(a[0]), "r"(a[1]), "r"(a[2]), "r"(a[3]), "r"(b[0]), "r"(b[1]));
}

__device__ __forceinline__ void ldsm4(uint32_t& r0, uint32_t& r1, uint32_t& r2, uint32_t& r3, uint32_t a) {
    asm volatile("ldmatrix.sync.aligned.m8n8.x4.shared.b16 {%0,%1,%2,%3}, [%4];"
        : "=r"(r0), "=r"(r1), "=r"(r2), "=r"(r3) : "r"(a));
}

__device__ __forceinline__ void cp16(uint32_t d, const void* s) {
    asm volatile("cp.async.cg.shared.global [%0], [%1], 16;" :: "r"(d), "l"(s));
}

// ============================================================================
// 1-pass fp16 GEMM: C = Ah @ Bh^T.  Block 128x128, BK=32, 256 thr, 2 CTAs/SM.
// ============================================================================
constexpr int F_TILE  = 128 * 80;
constexpr int P_STAGE = 2 * F_TILE;      // 20480
constexpr int SMEM_1P = 2 * P_STAGE;     // 40960

__global__ __launch_bounds__(256, 2) void tgemm_1p(
    const __half* __restrict__ Ah, const __half* __restrict__ Bh,
    float* __restrict__ C,
    int M, int N, int K, int lda, int ldb, int ldc)
{
    const int bx = blockIdx.x, by = blockIdx.y;

    extern __shared__ char smem[];
    const uint32_t sb = (uint32_t)__cvta_generic_to_shared(smem);

    const int tid = threadIdx.x, lane = tid & 31, warp = tid >> 5;
    const int wm = warp & 1, wn = warp >> 1;
    const int g = lane >> 2, t4 = lane & 3;
    const int r0 = tid >> 2, c4 = tid & 3;
    const int Nm1 = N - 1;

    const int lr  = (lane & 7) + ((lane >> 3) & 1) * 8;
    const int lkb = (lane >> 4) * 16;
    const uint32_t aBase = sb + (uint32_t)((wm * 64 + lr) * 80 + lkb);
    const uint32_t bBase = sb + (uint32_t)(F_TILE + (wn * 32 + lr) * 80 + lkb);

    float acc[4][4][4] = {};
    const int nchunks = K / 32;

    auto load_chunk = [&](int k0, uint32_t st) {
        #pragma unroll
        for (int c = 0; c < 2; c++) {
            int row = r0 + c * 64;
            uint32_t ds = sb + st + (uint32_t)(row * 80 + c4 * 16);
            long aoff = (long)(by * 128 + row) * lda + k0 + c4 * 8;
            cp16(ds, Ah + aoff);
            int nr = bx * 128 + row; if (nr > Nm1) nr = Nm1;
            long boff = (long)nr * ldb + k0 + c4 * 8;
            cp16(ds + F_TILE, Bh + boff);
        }
    };

    load_chunk(0, 0);
    asm volatile("cp.async.commit_group;");

    for (int i = 0; i < nchunks; i++) {
        if (i + 1 < nchunks)
            load_chunk((i + 1) * 32, (uint32_t)(((i + 1) & 1) * P_STAGE));
        asm volatile("cp.async.commit_group;");
        asm volatile("cp.async.wait_group 1;");
        __syncthreads();

        const uint32_t sof = (uint32_t)((i & 1) * P_STAGE);
        #pragma unroll
        for (int ks = 0; ks < 2; ks++) {
            uint32_t bh[4][2];
            #pragma unroll
            for (int p = 0; p < 2; p++) {
                uint32_t ad = bBase + sof + (uint32_t)(p * 16 * 80 + ks * 32);
                uint32_t x0, x1, x2, x3;
                ldsm4(x0, x1, x2, x3, ad);
                bh[2*p][0] = x0; bh[2*p+1][0] = x1; bh[2*p][1] = x2; bh[2*p+1][1] = x3;
            }
            #pragma unroll
            for (int mt = 0; mt < 4; mt++) {
                uint32_t ah[4];
                uint32_t ad = aBase + sof + (uint32_t)(mt * 16 * 80 + ks * 32);
                ldsm4(ah[0], ah[1], ah[2], ah[3], ad);
                #pragma unroll
                for (int nt = 0; nt < 4; nt++)
                    mma_f16(acc[mt][nt], ah, bh[nt]);
            }
        }
        __syncthreads();
    }

    #pragma unroll
    for (int mt = 0; mt < 4; mt++) {
        int r = by * 128 + wm * 64 + mt * 16 + g;
        #pragma unroll
        for (int nt = 0; nt < 4; nt++) {
            int c = bx * 128 + wn * 32 + nt * 8 + 2 * t4;
            if (c < N) {
                *(float2*)&C[(long)r * ldc + c]       = make_float2(acc[mt][nt][0], acc[mt][nt][1]);
                *(float2*)&C[(long)(r + 8) * ldc + c] = make_float2(acc[mt][nt][2], acc[mt][nt][3]);
            }
        }
    }
}

// ============================================================================
// Fused flash attention, fp16 2-term (unchanged from R10).
// ============================================================================
constexpr int QPL  = 10240;
constexpr int VPL  = 34816;
constexpr int VOFF = 61440;
constexpr int FA_SMEM = VOFF + 4 * VPL;   // 200704

__global__ __launch_bounds__(256, 1) void flash_k(
    const __half* __restrict__ Qf,
    const __half* __restrict__ Kh, const __half* __restrict__ Kl,
    const __half* __restrict__ Vh, const __half* __restrict__ Vl,
    __half* __restrict__ Of)
{
    const int qi = gridDim.x - 1 - blockIdx.x;   // heavy tiles first
    const int h  = blockIdx.y;

    extern __shared__ char smem[];
    const uint32_t sb = (uint32_t)__cvta_generic_to_shared(smem);

    const int tid = threadIdx.x, lane = tid & 31, w = tid >> 5;
    const int g = lane >> 2, t4 = lane & 3;
    const int lr  = (lane & 7) + ((lane >> 3) & 1) * 8;
    const int lkb = (lane >> 4) * 16;

    float oacc[32][4];
    #pragma unroll
    for (int i = 0; i < 32; i++)
        #pragma unroll
        for (int c = 0; c < 4; c++) oacc[i][c] = 0.f;
    float m0 = -1e30f, m1 = -1e30f, l0 = 0.f, l1 = 0.f;

    const float scale = 0.0625f;

    for (int j = 0; j <= qi; j++) {
        float sacc[16][4] = {};

        auto load_qk = [&](int i, uint32_t st) {
            const int d = i * 32;
            #pragma unroll
            for (int p = 0; p < 2; p++) {
                int id = tid + p * 256;
                int row = id >> 2, cc = id & 3;
                uint32_t dst = sb + st + (uint32_t)(row * 80 + cc * 16);
                size_t qo = (size_t)(qi * 128 + row) * HDQ + h * DQ + d + cc * 8;
                cp16(dst, Qf + qo);
                size_t ko = (size_t)(j * 128 + row) * HDQ + h * DQ + d + cc * 8;
                cp16(dst + QPL,     Kh + ko);
                cp16(dst + 2 * QPL, Kl + ko);
            }
        };

        load_qk(0, 0);
        asm volatile("cp.async.commit_group;");
        load_qk(1, 3 * QPL);
        asm volatile("cp.async.commit_group;");

        #pragma unroll
        for (int dvc = 0; dvc < 2; dvc++) {
            #pragma unroll
            for (int p = 0; p < 8; p++) {
                int id = tid + p * 256;
                int row = id >> 4, cc = id & 15;
                uint32_t dst = sb + (uint32_t)(VOFF + dvc * 2 * VPL + row * 272 + cc * 16);
                size_t vo = (size_t)h * DV * T + (size_t)(dvc * 128 + row) * T + j * 128 + cc * 8;
                cp16(dst,       Vh + vo);
                cp16(dst + VPL, Vl + vo);
            }
        }
        asm volatile("cp.async.commit_group;");

        for (int i = 0; i < 8; i++) {
            asm volatile("cp.async.wait_group 1;");
            __syncthreads();
            const uint32_t st = (uint32_t)((i & 1) * 3 * QPL);
            #pragma unroll
            for (int ks = 0; ks < 2; ks++) {
                uint32_t ah[4];
                uint32_t ad = sb + st + (uint32_t)((w * 16 + lr) * 80 + lkb + ks * 32);
                ldsm4(ah[0], ah[1], ah[2], ah[3], ad);
                #pragma unroll
                for (int p = 0; p < 8; p++) {
                    uint32_t bh[2][2], bl[2][2], x0, x1, x2, x3;
                    uint32_t bd = sb + st + (uint32_t)(QPL + (p * 16 + lr) * 80 + lkb + ks * 32);
                    ldsm4(x0, x1, x2, x3, bd);
                    bh[0][0] = x0; bh[1][0] = x1; bh[0][1] = x2; bh[1][1] = x3;
                    ldsm4(x0, x1, x2, x3, bd + QPL);
                    bl[0][0] = x0; bl[1][0] = x1; bl[0][1] = x2; bl[1][1] = x3;
                    #pragma unroll
                    for (int q2 = 0; q2 < 2; q2++) {
                        float* c = sacc[p * 2 + q2];
                        mma_f16(c, ah, bh[q2]);
                        mma_f16(c, ah, bl[q2]);
                    }
                }
            }
            __syncthreads();
            if (i + 2 < 8) load_qk(i + 2, st);
            asm volatile("cp.async.commit_group;");
        }
        asm volatile("cp.async.wait_group 0;");

        // ---------------- softmax (registers) ----------------
        #pragma unroll
        for (int nt = 0; nt < 16; nt++)
            #pragma unroll
            for (int c = 0; c < 4; c++) sacc[nt][c] *= scale;

        if (j == qi) {
            const int rr0 = w * 16 + g, rr1 = rr0 + 8;
            #pragma unroll
            for (int nt = 0; nt < 16; nt++) {
                int col = nt * 8 + 2 * t4;
                if (col     > rr0) sacc[nt][0] = -1e30f;
                if (col + 1 > rr0) sacc[nt][1] = -1e30f;
                if (col     > rr1) sacc[nt][2] = -1e30f;
                if (col + 1 > rr1) sacc[nt][3] = -1e30f;
            }
        }

        float tm0 = -1e30f, tm1 = -1e30f;
        #pragma unroll
        for (int nt = 0; nt < 16; nt++) {
            tm0 = fmaxf(tm0, fmaxf(sacc[nt][0], sacc[nt][1]));
            tm1 = fmaxf(tm1, fmaxf(sacc[nt][2], sacc[nt][3]));
        }
        tm0 = fmaxf(tm0, __shfl_xor_sync(0xffffffffu, tm0, 1));
        tm0 = fmaxf(tm0, __shfl_xor_sync(0xffffffffu, tm0, 2));
        tm1 = fmaxf(tm1, __shfl_xor_sync(0xffffffffu, tm1, 1));
        tm1 = fmaxf(tm1, __shfl_xor_sync(0xffffffffu, tm1, 2));

        float nm0 = fmaxf(m0, tm0), nm1 = fmaxf(m1, tm1);
        float a0 = expf(m0 - nm0), a1 = expf(m1 - nm1);
        m0 = nm0; m1 = nm1;

        float s0 = 0.f, s1 = 0.f;
        #pragma unroll
        for (int nt = 0; nt < 16; nt++) {
            sacc[nt][0] = expf(sacc[nt][0] - m0); s0 += sacc[nt][0];
            sacc[nt][1] = expf(sacc[nt][1] - m0); s0 += sacc[nt][1];
            sacc[nt][2] = expf(sacc[nt][2] - m1); s1 += sacc[nt][2];
            sacc[nt][3] = expf(sacc[nt][3] - m1); s1 += sacc[nt][3];
        }
        s0 += __shfl_xor_sync(0xffffffffu, s0, 1);
        s0 += __shfl_xor_sync(0xffffffffu, s0, 2);
        s1 += __shfl_xor_sync(0xffffffffu, s1, 1);
        s1 += __shfl_xor_sync(0xffffffffu, s1, 2);
        l0 = l0 * a0 + s0;
        l1 = l1 * a1 + s1;

        #pragma unroll
        for (int i = 0; i < 32; i++) {
            oacc[i][0] *= a0; oacc[i][1] *= a0;
            oacc[i][2] *= a1; oacc[i][3] *= a1;
        }

        uint32_t Pf[8][4];
        #pragma unroll
        for (int ks = 0; ks < 8; ks++) {
            #pragma unroll
            for (int hf = 0; hf < 2; hf++) {
                const float* c = sacc[2 * ks + hf];
                __half2 v01 = __floats2half2_rn(c[0], c[1]);
                __half2 v23 = __floats2half2_rn(c[2], c[3]);
                Pf[ks][hf * 2]     = *(uint32_t*)&v01;
                Pf[ks][hf * 2 + 1] = *(uint32_t*)&v23;
            }
        }

        __syncthreads();
        #pragma unroll
        for (int dvc = 0; dvc < 2; dvc++) {
            #pragma unroll
            for (int ks = 0; ks < 8; ks++) {
                #pragma unroll
                for (int p = 0; p < 8; p++) {
                    uint32_t vh[2][2], vl[2][2], x0, x1, x2, x3;
                    uint32_t bd = sb + (uint32_t)(VOFF + dvc * 2 * VPL + (p * 16 + lr) * 272 + lkb + ks * 32);
                    ldsm4(x0, x1, x2, x3, bd);
                    vh[0][0] = x0; vh[1][0] = x1; vh[0][1] = x2; vh[1][1] = x3;
                    ldsm4(x0, x1, x2, x3, bd + VPL);
                    vl[0][0] = x0; vl[1][0] = x1; vl[0][1] = x2; vl[1][1] = x3;
                    #pragma unroll
                    for (int q2 = 0; q2 < 2; q2++) {
                        float* c = oacc[dvc * 16 + p * 2 + q2];
                        mma_f16(c, Pf[ks], vh[q2]);
                        mma_f16(c, Pf[ks], vl[q2]);
                    }
                }
            }
        }
        __syncthreads();
    }

    const float i0 = 1.f / l0, i1 = 1.f / l1;
    const int r0 = qi * 128 + w * 16 + g;
    __half* o0 = Of + (size_t)r0 * HDQ + h * DV;
    __half* o1 = o0 + (size_t)8 * HDQ;
    #pragma unroll
    for (int nt = 0; nt < 32; nt++) {
        int c = nt * 8 + 2 * t4;
        __half2 v0 = __floats2half2_rn(oacc[nt][0] * i0, oacc[nt][1] * i0);
        __half2 v1 = __floats2half2_rn(oacc[nt][2] * i1, oacc[nt][3] * i1);
        *(__half2*)&o0[c] = v0;
        *(__half2*)&o1[c] = v1;
    }
}

// ---------------- fp32 -> fp16 ----------------
__global__ void conv_f16_k(const float* __restrict__ x, __half* __restrict__ h, long n)
{
    long i = (long)blockIdx.x * blockDim.x + threadIdx.x;
    long stride = (long)gridDim.x * blockDim.x;
    for (; i < n; i += stride) h[i] = __float2half_rn(x[i]);
}

// ---------------- fp32 [R,C] -> fp16 transposed [C,R] (single plane) ----------------
__global__ void conv_tr_f16_k(const float* __restrict__ x, __half* __restrict__ h, int R, int C)
{
    __shared__ float tile[32][33];
    const int c0 = blockIdx.x * 32, rr0 = blockIdx.y * 32;
    const int tx = threadIdx.x & 31, ty = threadIdx.x >> 5;
    #pragma unroll
    for (int i = 0; i < 4; i++) {
        int r = rr0 + ty + i * 8;
        tile[ty + i * 8][tx] = x[(long)r * C + c0 + tx];
    }
    __syncthreads();
    #pragma unroll
    for (int i = 0; i < 4; i++) {
        int c = c0 + ty + i * 8;
        long o = (long)c * R + rr0 + tx;
        h[o] = __float2half_rn(tile[tx][ty + i * 8]);
    }
}

// ---------------- RMSNorm fp32 -> fp16 ----------------
__global__ void rmsnorm_f16_k(const float* __restrict__ x, const float* __restrict__ w,
                              __half* __restrict__ o, int N, int ldin)
{
    const float* p = x + (long)blockIdx.x * ldin;
    __shared__ float red[8];
    __shared__ float bc;
    const int lane = threadIdx.x & 31, wid = threadIdx.x >> 5;

    float s = 0.f;
    for (int j = threadIdx.x; j < N; j += blockDim.x) { float v = p[j]; s += v * v; }
    #pragma unroll
    for (int of = 16; of; of >>= 1) s += __shfl_xor_sync(0xffffffffu, s, of);
    if (lane == 0) red[wid] = s;
    __syncthreads();
    if (threadIdx.x == 0) {
        float v = 0.f;
        for (int wI = 0; wI < 8; wI++) v += red[wI];
        bc = rsqrtf(v / N + 1e-6f);
    }
    __syncthreads();
    float r = bc;
    long ob = (long)blockIdx.x * N;
    for (int j = threadIdx.x; j < N; j += blockDim.x)
        o[ob + j] = __float2half_rn(p[j] * r * w[j]);
}

// ---------------- rope k_pe in-place ----------------
__global__ void rope_kpe_k(float* __restrict__ lat, const int* __restrict__ pos)
{
    const int tt = blockIdx.x, i = threadIdx.x;
    double inv = pow(10000.0, -(double)i / 32.0);
    double sd, cd;
    sincos((double)pos[tt] * inv, &sd, &cd);
    float c = (float)cd, s = (float)sd;
    float* p = lat + (long)tt * LATW + DKV;
    float x1 = p[i], x2 = p[i + 32];
    p[i]      = x1 * c - x2 * s;
    p[i + 32] = x2 * c + x1 * s;
}

// ---------------- q: rope fused -> fp16 single plane ----------------
__global__ void rope_conv_q_k(const float* __restrict__ q, const int* __restrict__ pos,
                              __half* __restrict__ o)
{
    const int tt = blockIdx.x;
    __shared__ float cs[32], sn[32];
    if (threadIdx.x < 32) {
        double inv = pow(10000.0, -(double)threadIdx.x / 32.0);
        double sd, cd;
        sincos((double)pos[tt] * inv, &sd, &cd);
        cs[threadIdx.x] = (float)cd; sn[threadIdx.x] = (float)sd;
    }
    __syncthreads();
    const float* row = q + (long)tt * HDQ;
    long ob = (long)tt * HDQ;
    for (int x = threadIdx.x; x < HDQ; x += blockDim.x) {
        int d = x & 255;
        float v;
        if (d < DN)            v = row[x];
        else if (d < DN + 32) { int i = d - DN;       v = row[x] * cs[i] - row[x + 32] * sn[i]; }
        else                  { int i = d - DN - 32;  v = row[x] * cs[i] + row[x - 32] * sn[i]; }
        o[ob + x] = __float2half_rn(v);
    }
}

// ---------------- K assembly -> fp16 hi/lo ----------------
__global__ void build_K_f16_k(const float* __restrict__ kv, const float* __restrict__ lat,
                              __half* __restrict__ h, __half* __restrict__ l)
{
    const int tt = blockIdx.x;
    long ob = (long)tt * HDQ;
    for (int x = threadIdx.x; x < HDQ; x += blockDim.x) {
        int hd = x >> 8, d = x & 255;
        float v = (d < DN) ? kv[(long)tt * KVW + hd * (DN + DV) + d]
                           : lat[(long)tt * LATW + DKV + (d - DN)];
        __half hh, ll;
        splith(v, hh, ll);
        h[ob + x] = hh; l[ob + x] = ll;
    }
}

// ---------------- V transpose per head -> fp16 hi/lo [h][DV][T] ----------------
__global__ void transpose_v_f16_k(const float* __restrict__ kv,
                                  __half* __restrict__ h, __half* __restrict__ l)
{
    __shared__ float tile[32][33];
    const int d0 = blockIdx.x * 32, t0 = blockIdx.y * 32, hd = blockIdx.z;
    const int tx = threadIdx.x & 31, ty = threadIdx.x >> 5;
    #pragma unroll
    for (int i = 0; i < 4; i++) {
        int tr = t0 + ty + i * 8;
        tile[ty + i * 8][tx] = kv[(long)tr * KVW + hd * (DN + DV) + DN + d0 + tx];
    }
    __syncthreads();
    #pragma unroll
    for (int i = 0; i < 4; i++) {
        int d = d0 + ty + i * 8;
        float v = tile[tx][ty + i * 8];
        long o = (long)hd * DV * T + (long)d * T + t0 + tx;
        __half hh, ll;
        splith(v, hh, ll);
        h[o] = hh; l[o] = ll;
    }
}

// ---------------- launch ----------------
extern "C" void kernel_launch(void* const* d_in, const int* in_sizes, int n_in,
                              void* d_out, int out_size)
{
    (void)in_sizes; (void)n_in; (void)out_size;
    const float* hidden = (const float*)d_in[0];
    const int*   pos    = (const int*)  d_in[1];
    const float* wq_a   = (const float*)d_in[2];
    const float* q_ln   = (const float*)d_in[3];
    const float* wq_b   = (const float*)d_in[4];
    const float* wkv_a  = (const float*)d_in[5];
    const float* kv_ln  = (const float*)d_in[6];
    const float* wkv_b  = (const float*)d_in[7];
    const float* wo     = (const float*)d_in[8];
    float* out = (float*)d_out;

    cudaFuncSetAttribute(tgemm_1p, cudaFuncAttributeMaxDynamicSharedMemorySize, SMEM_1P);
    cudaFuncSetAttribute(flash_k,  cudaFuncAttributeMaxDynamicSharedMemorySize, FA_SMEM);

    float *qlora, *latent, *q, *kv;
    cudaGetSymbolAddress((void**)&qlora,  g_qlora);
    cudaGetSymbolAddress((void**)&latent, g_latent);
    cudaGetSymbolAddress((void**)&q,      g_q);
    cudaGetSymbolAddress((void**)&kv,     g_kv);

    __half *hidf, *qlof, *latf, *Ofp, *qf, *Kcf, *Vtf,
           *wqaTf, *wkvaTf, *wqbTf, *wkvbTf, *woTf;
    cudaGetSymbolAddress((void**)&hidf,   g_hid_f);
    cudaGetSymbolAddress((void**)&qlof,   g_qlo_f);
    cudaGetSymbolAddress((void**)&latf,   g_lat_f);
    cudaGetSymbolAddress((void**)&Ofp,    g_Of);
    cudaGetSymbolAddress((void**)&qf,     g_qf);
    cudaGetSymbolAddress((void**)&Kcf,    g_Kc_f);
    cudaGetSymbolAddress((void**)&Vtf,    g_Vt_f);
    cudaGetSymbolAddress((void**)&wqaTf,  g_wqaTf);
    cudaGetSymbolAddress((void**)&wkvaTf, g_wkvaTf);
    cudaGetSymbolAddress((void**)&wqbTf,  g_wqbTf);
    cudaGetSymbolAddress((void**)&wkvbTf, g_wkvbTf);
    cudaGetSymbolAddress((void**)&woTf,   g_woTf);

    #define PL(base, n) (base), ((base) + (size_t)(n))

    const size_t nQ  = (size_t)T * HDQ;
    const size_t nVt = (size_t)NH * DV * T;

    dim3 blk(256);

    // ---- weight conversions (single fp16 plane each) ----
    conv_tr_f16_k<<<dim3(QLORA/32, HID/32), blk>>>(wq_a,  wqaTf,  HID, QLORA);
    conv_tr_f16_k<<<dim3(LATW/32,  HID/32), blk>>>(wkv_a, wkvaTf, HID, LATW);
    conv_tr_f16_k<<<dim3(HDQ/32, QLORA/32), blk>>>(wq_b,  wqbTf,  QLORA, HDQ);
    conv_tr_f16_k<<<dim3(KVW/32,  DKV/32),  blk>>>(wkv_b, wkvbTf, DKV, KVW);
    conv_tr_f16_k<<<dim3(HID/32,  HDQ/32),  blk>>>(wo,    woTf,   HDQ, HID);
    conv_f16_k<<<2048, 256>>>(hidden, hidf, (long)T * HID);

    // ---- down projections ----
    tgemm_1p<<<dim3(QLORA/128, T/128), blk, SMEM_1P>>>(hidf, wqaTf,
        qlora, T, QLORA, HID, HID, HID, QLORA);
    tgemm_1p<<<dim3((LATW+127)/128, T/128), blk, SMEM_1P>>>(hidf, wkvaTf,
        latent, T, LATW, HID, HID, HID, LATW);

    // ---- norms + rope(k_pe) ----
    rmsnorm_f16_k<<<T, 256>>>(qlora, q_ln, qlof, QLORA, QLORA);
    rope_kpe_k<<<T, 32>>>(latent, pos);
    rmsnorm_f16_k<<<T, 256>>>(latent, kv_ln, latf, DKV, LATW);

    // ---- up projections ----
    tgemm_1p<<<dim3(HDQ/128, T/128), blk, SMEM_1P>>>(qlof, wqbTf,
        q, T, HDQ, QLORA, QLORA, QLORA, HDQ);
    tgemm_1p<<<dim3(KVW/128, T/128), blk, SMEM_1P>>>(latf, wkvbTf,
        kv, T, KVW, DKV, DKV, DKV, KVW);

    // ---- q rope; K assembly; V transpose ----
    rope_conv_q_k<<<T, 256>>>(q, pos, qf);
    build_K_f16_k<<<T, 256>>>(kv, latent, PL(Kcf, nQ));
    transpose_v_f16_k<<<dim3(DV/32, T/32, NH), blk>>>(kv, PL(Vtf, nVt));

    // ---- fused flash attention (fp16 2-term) ----
    flash_k<<<dim3(T/128, NH), blk, FA_SMEM>>>(
        qf, PL(Kcf, nQ), PL(Vtf, nVt), Ofp);

    // ---- final projection ----
    tgemm_1p<<<dim3(HID/128, T/128), blk, SMEM_1P>>>(Ofp, woTf,
        out, T, HID, HDQ, HDQ, HDQ, HID);

    #undef PL
}

// round 12
// speedup vs baseline: 2.3883x; 1.1521x over previous
#include <cuda_runtime.h>
#include <cuda_fp16.h>
#include <math.h>
#include <stdint.h>

// ---------------- problem constants ----------------
constexpr int T    = 2048;
constexpr int HID  = 4096;
constexpr int NH   = 32;
constexpr int DQ   = 256;
constexpr int DN   = 192;
constexpr int DR   = 64;
constexpr int DV   = 256;
constexpr int DKV  = 512;
constexpr int QLORA= 2048;
constexpr int HDQ  = NH * DQ;        // 8192
constexpr int KVW  = NH * (DN + DV); // 14336
constexpr int LATW = DKV + DR;       // 576

// ---------------- fp32 scratch ----------------
__device__ float g_qlora[(size_t)T * QLORA];
__device__ float g_latent[(size_t)T * LATW];
__device__ float g_q[(size_t)T * HDQ];
__device__ float g_kv[(size_t)T * KVW];

// ---------------- fp16 buffers ----------------
__device__ __half g_hid_f  [(size_t)T * HID];
__device__ __half g_qlo_f  [(size_t)T * QLORA];
__device__ __half g_lat_f  [(size_t)T * DKV];
__device__ __half g_Of     [(size_t)T * HDQ];
__device__ __half g_qf     [(size_t)T * HDQ];          // Q single plane
__device__ __half g_Kc_f   [(size_t)T * HDQ];          // K single plane
__device__ __half g_Vt_f   [(size_t)NH * DV * T];      // V^T single plane
__device__ __half g_wqaTf  [(size_t)QLORA * HID];
__device__ __half g_wkvaTf [(size_t)LATW * HID];
__device__ __half g_wqbTf  [(size_t)HDQ * QLORA];
__device__ __half g_wkvbTf [(size_t)KVW * DKV];
__device__ __half g_woTf   [(size_t)HID * HDQ];

// ---------------- helpers ----------------
__device__ __forceinline__ void mma_f16(float* c, const uint32_t* a, const uint32_t* b) {
    asm volatile(
        "mma.sync.aligned.m16n8k16.row.col.f32.f16.f16.f32 "
        "{%0,%1,%2,%3}, {%4,%5,%6,%7}, {%8,%9}, {%0,%1,%2,%3};\n"
        : "+f"(c[0]), "+f"(c[1]), "+f"(c[2]), "+f"(c[3])
        : "r"(a[0]), "r"(a[1]), "r"(a[2]), "r"(a[3]), "r"(b[0]), "r"(b[1]));
}

__device__ __forceinline__ void ldsm4(uint32_t& r0, uint32_t& r1, uint32_t& r2, uint32_t& r3, uint32_t a) {
    asm volatile("ldmatrix.sync.aligned.m8n8.x4.shared.b16 {%0,%1,%2,%3}, [%4];"
        : "=r"(r0), "=r"(r1), "=r"(r2), "=r"(r3) : "r"(a));
}

__device__ __forceinline__ void cp16(uint32_t d, const void* s) {
    asm volatile("cp.async.cg.shared.global [%0], [%1], 16;" :: "r"(d), "l"(s));
}

// ============================================================================
// 1-pass fp16 GEMM: C = Ah @ Bh^T.  Block 128x128, BK=32, 256 thr, 2 CTAs/SM.
// ============================================================================
constexpr int F_TILE  = 128 * 80;
constexpr int P_STAGE = 2 * F_TILE;      // 20480
constexpr int SMEM_1P = 2 * P_STAGE;     // 40960

__global__ __launch_bounds__(256, 2) void tgemm_1p(
    const __half* __restrict__ Ah, const __half* __restrict__ Bh,
    float* __restrict__ C,
    int M, int N, int K, int lda, int ldb, int ldc)
{
    const int bx = blockIdx.x, by = blockIdx.y;

    extern __shared__ char smem[];
    const uint32_t sb = (uint32_t)__cvta_generic_to_shared(smem);

    const int tid = threadIdx.x, lane = tid & 31, warp = tid >> 5;
    const int wm = warp & 1, wn = warp >> 1;
    const int g = lane >> 2, t4 = lane & 3;
    const int r0 = tid >> 2, c4 = tid & 3;
    const int Nm1 = N - 1;

    const int lr  = (lane & 7) + ((lane >> 3) & 1) * 8;
    const int lkb = (lane >> 4) * 16;
    const uint32_t aBase = sb + (uint32_t)((wm * 64 + lr) * 80 + lkb);
    const uint32_t bBase = sb + (uint32_t)(F_TILE + (wn * 32 + lr) * 80 + lkb);

    float acc[4][4][4] = {};
    const int nchunks = K / 32;

    auto load_chunk = [&](int k0, uint32_t st) {
        #pragma unroll
        for (int c = 0; c < 2; c++) {
            int row = r0 + c * 64;
            uint32_t ds = sb + st + (uint32_t)(row * 80 + c4 * 16);
            long aoff = (long)(by * 128 + row) * lda + k0 + c4 * 8;
            cp16(ds, Ah + aoff);
            int nr = bx * 128 + row; if (nr > Nm1) nr = Nm1;
            long boff = (long)nr * ldb + k0 + c4 * 8;
            cp16(ds + F_TILE, Bh + boff);
        }
    };

    load_chunk(0, 0);
    asm volatile("cp.async.commit_group;");

    for (int i = 0; i < nchunks; i++) {
        if (i + 1 < nchunks)
            load_chunk((i + 1) * 32, (uint32_t)(((i + 1) & 1) * P_STAGE));
        asm volatile("cp.async.commit_group;");
        asm volatile("cp.async.wait_group 1;");
        __syncthreads();

        const uint32_t sof = (uint32_t)((i & 1) * P_STAGE);
        #pragma unroll
        for (int ks = 0; ks < 2; ks++) {
            uint32_t bh[4][2];
            #pragma unroll
            for (int p = 0; p < 2; p++) {
                uint32_t ad = bBase + sof + (uint32_t)(p * 16 * 80 + ks * 32);
                uint32_t x0, x1, x2, x3;
                ldsm4(x0, x1, x2, x3, ad);
                bh[2*p][0] = x0; bh[2*p+1][0] = x1; bh[2*p][1] = x2; bh[2*p+1][1] = x3;
            }
            #pragma unroll
            for (int mt = 0; mt < 4; mt++) {
                uint32_t ah[4];
                uint32_t ad = aBase + sof + (uint32_t)(mt * 16 * 80 + ks * 32);
                ldsm4(ah[0], ah[1], ah[2], ah[3], ad);
                #pragma unroll
                for (int nt = 0; nt < 4; nt++)
                    mma_f16(acc[mt][nt], ah, bh[nt]);
            }
        }
        __syncthreads();
    }

    #pragma unroll
    for (int mt = 0; mt < 4; mt++) {
        int r = by * 128 + wm * 64 + mt * 16 + g;
        #pragma unroll
        for (int nt = 0; nt < 4; nt++) {
            int c = bx * 128 + wn * 32 + nt * 8 + 2 * t4;
            if (c < N) {
                *(float2*)&C[(long)r * ldc + c]       = make_float2(acc[mt][nt][0], acc[mt][nt][1]);
                *(float2*)&C[(long)(r + 8) * ldc + c] = make_float2(acc[mt][nt][2], acc[mt][nt][3]);
            }
        }
    }
}

// ============================================================================
// Fused flash attention, pure fp16 1-term: Q/K/V single planes.
// smem: QK 2 stages x 2 planes x 10240 = 40960; V 2 chunks x 34816 at 40960.
// ============================================================================
constexpr int QPL  = 10240;
constexpr int VPL  = 34816;
constexpr int VOFF = 40960;
constexpr int FA_SMEM = VOFF + 2 * VPL;   // 110592

__global__ __launch_bounds__(256, 1) void flash_k(
    const __half* __restrict__ Qf, const __half* __restrict__ Kf,
    const __half* __restrict__ Vf, __half* __restrict__ Of)
{
    const int qi = gridDim.x - 1 - blockIdx.x;   // heavy tiles first
    const int h  = blockIdx.y;

    extern __shared__ char smem[];
    const uint32_t sb = (uint32_t)__cvta_generic_to_shared(smem);

    const int tid = threadIdx.x, lane = tid & 31, w = tid >> 5;
    const int g = lane >> 2, t4 = lane & 3;
    const int lr  = (lane & 7) + ((lane >> 3) & 1) * 8;
    const int lkb = (lane >> 4) * 16;

    float oacc[32][4];
    #pragma unroll
    for (int i = 0; i < 32; i++)
        #pragma unroll
        for (int c = 0; c < 4; c++) oacc[i][c] = 0.f;
    float m0 = -1e30f, m1 = -1e30f, l0 = 0.f, l1 = 0.f;

    const float scale = 0.0625f;

    for (int j = 0; j <= qi; j++) {
        float sacc[16][4] = {};

        auto load_qk = [&](int i, uint32_t st) {
            const int d = i * 32;
            #pragma unroll
            for (int p = 0; p < 2; p++) {
                int id = tid + p * 256;
                int row = id >> 2, cc = id & 3;
                uint32_t dst = sb + st + (uint32_t)(row * 80 + cc * 16);
                size_t qo = (size_t)(qi * 128 + row) * HDQ + h * DQ + d + cc * 8;
                cp16(dst, Qf + qo);
                size_t ko = (size_t)(j * 128 + row) * HDQ + h * DQ + d + cc * 8;
                cp16(dst + QPL, Kf + ko);
            }
        };

        load_qk(0, 0);
        asm volatile("cp.async.commit_group;");
        load_qk(1, 2 * QPL);
        asm volatile("cp.async.commit_group;");

        // prefetch BOTH V dv-chunks (single plane)
        #pragma unroll
        for (int dvc = 0; dvc < 2; dvc++) {
            #pragma unroll
            for (int p = 0; p < 4; p++) {
                int id = tid + p * 256;
                int row = id >> 3, cc = id & 7;
                uint32_t dst = sb + (uint32_t)(VOFF + dvc * VPL + row * 272 + cc * 32);
                size_t vo = (size_t)h * DV * T + (size_t)(dvc * 128 + row) * T + j * 128 + cc * 16;
                cp16(dst,      Vf + vo);
                cp16(dst + 16, Vf + vo + 8);
            }
        }
        asm volatile("cp.async.commit_group;");

        for (int i = 0; i < 8; i++) {
            asm volatile("cp.async.wait_group 1;");
            __syncthreads();
            const uint32_t st = (uint32_t)((i & 1) * 2 * QPL);
            #pragma unroll
            for (int ks = 0; ks < 2; ks++) {
                uint32_t ah[4];
                uint32_t ad = sb + st + (uint32_t)((w * 16 + lr) * 80 + lkb + ks * 32);
                ldsm4(ah[0], ah[1], ah[2], ah[3], ad);
                #pragma unroll
                for (int p = 0; p < 8; p++) {
                    uint32_t bh[2][2], x0, x1, x2, x3;
                    uint32_t bd = sb + st + (uint32_t)(QPL + (p * 16 + lr) * 80 + lkb + ks * 32);
                    ldsm4(x0, x1, x2, x3, bd);
                    bh[0][0] = x0; bh[1][0] = x1; bh[0][1] = x2; bh[1][1] = x3;
                    #pragma unroll
                    for (int q2 = 0; q2 < 2; q2++)
                        mma_f16(sacc[p * 2 + q2], ah, bh[q2]);
                }
            }
            __syncthreads();
            if (i + 2 < 8) load_qk(i + 2, st);
            asm volatile("cp.async.commit_group;");
        }
        asm volatile("cp.async.wait_group 0;");

        // ---------------- softmax (registers) ----------------
        #pragma unroll
        for (int nt = 0; nt < 16; nt++)
            #pragma unroll
            for (int c = 0; c < 4; c++) sacc[nt][c] *= scale;

        if (j == qi) {
            const int rr0 = w * 16 + g, rr1 = rr0 + 8;
            #pragma unroll
            for (int nt = 0; nt < 16; nt++) {
                int col = nt * 8 + 2 * t4;
                if (col     > rr0) sacc[nt][0] = -1e30f;
                if (col + 1 > rr0) sacc[nt][1] = -1e30f;
                if (col     > rr1) sacc[nt][2] = -1e30f;
                if (col + 1 > rr1) sacc[nt][3] = -1e30f;
            }
        }

        float tm0 = -1e30f, tm1 = -1e30f;
        #pragma unroll
        for (int nt = 0; nt < 16; nt++) {
            tm0 = fmaxf(tm0, fmaxf(sacc[nt][0], sacc[nt][1]));
            tm1 = fmaxf(tm1, fmaxf(sacc[nt][2], sacc[nt][3]));
        }
        tm0 = fmaxf(tm0, __shfl_xor_sync(0xffffffffu, tm0, 1));
        tm0 = fmaxf(tm0, __shfl_xor_sync(0xffffffffu, tm0, 2));
        tm1 = fmaxf(tm1, __shfl_xor_sync(0xffffffffu, tm1, 1));
        tm1 = fmaxf(tm1, __shfl_xor_sync(0xffffffffu, tm1, 2));

        float nm0 = fmaxf(m0, tm0), nm1 = fmaxf(m1, tm1);
        float a0 = expf(m0 - nm0), a1 = expf(m1 - nm1);
        m0 = nm0; m1 = nm1;

        float s0 = 0.f, s1 = 0.f;
        #pragma unroll
        for (int nt = 0; nt < 16; nt++) {
            sacc[nt][0] = expf(sacc[nt][0] - m0); s0 += sacc[nt][0];
            sacc[nt][1] = expf(sacc[nt][1] - m0); s0 += sacc[nt][1];
            sacc[nt][2] = expf(sacc[nt][2] - m1); s1 += sacc[nt][2];
            sacc[nt][3] = expf(sacc[nt][3] - m1); s1 += sacc[nt][3];
        }
        s0 += __shfl_xor_sync(0xffffffffu, s0, 1);
        s0 += __shfl_xor_sync(0xffffffffu, s0, 2);
        s1 += __shfl_xor_sync(0xffffffffu, s1, 1);
        s1 += __shfl_xor_sync(0xffffffffu, s1, 2);
        l0 = l0 * a0 + s0;
        l1 = l1 * a1 + s1;

        #pragma unroll
        for (int i = 0; i < 32; i++) {
            oacc[i][0] *= a0; oacc[i][1] *= a0;
            oacc[i][2] *= a1; oacc[i][3] *= a1;
        }

        uint32_t Pf[8][4];
        #pragma unroll
        for (int ks = 0; ks < 8; ks++) {
            #pragma unroll
            for (int hf = 0; hf < 2; hf++) {
                const float* c = sacc[2 * ks + hf];
                __half2 v01 = __floats2half2_rn(c[0], c[1]);
                __half2 v23 = __floats2half2_rn(c[2], c[3]);
                Pf[ks][hf * 2]     = *(uint32_t*)&v01;
                Pf[ks][hf * 2 + 1] = *(uint32_t*)&v23;
            }
        }

        // ---------------- PV (1-term): V resident ----------------
        __syncthreads();
        #pragma unroll
        for (int dvc = 0; dvc < 2; dvc++) {
            #pragma unroll
            for (int ks = 0; ks < 8; ks++) {
                #pragma unroll
                for (int p = 0; p < 8; p++) {
                    uint32_t vh[2][2], x0, x1, x2, x3;
                    uint32_t bd = sb + (uint32_t)(VOFF + dvc * VPL + (p * 16 + lr) * 272 + lkb + ks * 32);
                    ldsm4(x0, x1, x2, x3, bd);
                    vh[0][0] = x0; vh[1][0] = x1; vh[0][1] = x2; vh[1][1] = x3;
                    #pragma unroll
                    for (int q2 = 0; q2 < 2; q2++)
                        mma_f16(oacc[dvc * 16 + p * 2 + q2], Pf[ks], vh[q2]);
                }
            }
        }
        __syncthreads();
    }

    const float i0 = 1.f / l0, i1 = 1.f / l1;
    const int r0 = qi * 128 + w * 16 + g;
    __half* o0 = Of + (size_t)r0 * HDQ + h * DV;
    __half* o1 = o0 + (size_t)8 * HDQ;
    #pragma unroll
    for (int nt = 0; nt < 32; nt++) {
        int c = nt * 8 + 2 * t4;
        __half2 v0 = __floats2half2_rn(oacc[nt][0] * i0, oacc[nt][1] * i0);
        __half2 v1 = __floats2half2_rn(oacc[nt][2] * i1, oacc[nt][3] * i1);
        *(__half2*)&o0[c] = v0;
        *(__half2*)&o1[c] = v1;
    }
}

// ---------------- fp32 -> fp16 ----------------
__global__ void conv_f16_k(const float* __restrict__ x, __half* __restrict__ h, long n)
{
    long i = (long)blockIdx.x * blockDim.x + threadIdx.x;
    long stride = (long)gridDim.x * blockDim.x;
    for (; i < n; i += stride) h[i] = __float2half_rn(x[i]);
}

// ---------------- fp32 [R,C] -> fp16 transposed [C,R] ----------------
__global__ void conv_tr_f16_k(const float* __restrict__ x, __half* __restrict__ h, int R, int C)
{
    __shared__ float tile[32][33];
    const int c0 = blockIdx.x * 32, rr0 = blockIdx.y * 32;
    const int tx = threadIdx.x & 31, ty = threadIdx.x >> 5;
    #pragma unroll
    for (int i = 0; i < 4; i++) {
        int r = rr0 + ty + i * 8;
        tile[ty + i * 8][tx] = x[(long)r * C + c0 + tx];
    }
    __syncthreads();
    #pragma unroll
    for (int i = 0; i < 4; i++) {
        int c = c0 + ty + i * 8;
        long o = (long)c * R + rr0 + tx;
        h[o] = __float2half_rn(tile[tx][ty + i * 8]);
    }
}

// ---------------- RMSNorm fp32 -> fp16 ----------------
__global__ void rmsnorm_f16_k(const float* __restrict__ x, const float* __restrict__ w,
                              __half* __restrict__ o, int N, int ldin)
{
    const float* p = x + (long)blockIdx.x * ldin;
    __shared__ float red[8];
    __shared__ float bc;
    const int lane = threadIdx.x & 31, wid = threadIdx.x >> 5;

    float s = 0.f;
    for (int j = threadIdx.x; j < N; j += blockDim.x) { float v = p[j]; s += v * v; }
    #pragma unroll
    for (int of = 16; of; of >>= 1) s += __shfl_xor_sync(0xffffffffu, s, of);
    if (lane == 0) red[wid] = s;
    __syncthreads();
    if (threadIdx.x == 0) {
        float v = 0.f;
        for (int wI = 0; wI < 8; wI++) v += red[wI];
        bc = rsqrtf(v / N + 1e-6f);
    }
    __syncthreads();
    float r = bc;
    long ob = (long)blockIdx.x * N;
    for (int j = threadIdx.x; j < N; j += blockDim.x)
        o[ob + j] = __float2half_rn(p[j] * r * w[j]);
}

// ---------------- rope k_pe in-place ----------------
__global__ void rope_kpe_k(float* __restrict__ lat, const int* __restrict__ pos)
{
    const int tt = blockIdx.x, i = threadIdx.x;
    double inv = pow(10000.0, -(double)i / 32.0);
    double sd, cd;
    sincos((double)pos[tt] * inv, &sd, &cd);
    float c = (float)cd, s = (float)sd;
    float* p = lat + (long)tt * LATW + DKV;
    float x1 = p[i], x2 = p[i + 32];
    p[i]      = x1 * c - x2 * s;
    p[i + 32] = x2 * c + x1 * s;
}

// ---------------- q: rope fused -> fp16 ----------------
__global__ void rope_conv_q_k(const float* __restrict__ q, const int* __restrict__ pos,
                              __half* __restrict__ o)
{
    const int tt = blockIdx.x;
    __shared__ float cs[32], sn[32];
    if (threadIdx.x < 32) {
        double inv = pow(10000.0, -(double)threadIdx.x / 32.0);
        double sd, cd;
        sincos((double)pos[tt] * inv, &sd, &cd);
        cs[threadIdx.x] = (float)cd; sn[threadIdx.x] = (float)sd;
    }
    __syncthreads();
    const float* row = q + (long)tt * HDQ;
    long ob = (long)tt * HDQ;
    for (int x = threadIdx.x; x < HDQ; x += blockDim.x) {
        int d = x & 255;
        float v;
        if (d < DN)            v = row[x];
        else if (d < DN + 32) { int i = d - DN;       v = row[x] * cs[i] - row[x + 32] * sn[i]; }
        else                  { int i = d - DN - 32;  v = row[x] * cs[i] + row[x - 32] * sn[i]; }
        o[ob + x] = __float2half_rn(v);
    }
}

// ---------------- K assembly -> fp16 single plane ----------------
__global__ void build_K_f16_k(const float* __restrict__ kv, const float* __restrict__ lat,
                              __half* __restrict__ h)
{
    const int tt = blockIdx.x;
    long ob = (long)tt * HDQ;
    for (int x = threadIdx.x; x < HDQ; x += blockDim.x) {
        int hd = x >> 8, d = x & 255;
        float v = (d < DN) ? kv[(long)tt * KVW + hd * (DN + DV) + d]
                           : lat[(long)tt * LATW + DKV + (d - DN)];
        h[ob + x] = __float2half_rn(v);
    }
}

// ---------------- V transpose per head -> fp16 [h][DV][T] ----------------
__global__ void transpose_v_f16_k(const float* __restrict__ kv, __half* __restrict__ h)
{
    __shared__ float tile[32][33];
    const int d0 = blockIdx.x * 32, t0 = blockIdx.y * 32, hd = blockIdx.z;
    const int tx = threadIdx.x & 31, ty = threadIdx.x >> 5;
    #pragma unroll
    for (int i = 0; i < 4; i++) {
        int tr = t0 + ty + i * 8;
        tile[ty + i * 8][tx] = kv[(long)tr * KVW + hd * (DN + DV) + DN + d0 + tx];
    }
    __syncthreads();
    #pragma unroll
    for (int i = 0; i < 4; i++) {
        int d = d0 + ty + i * 8;
        long o = (long)hd * DV * T + (long)d * T + t0 + tx;
        h[o] = __float2half_rn(tile[tx][ty + i * 8]);
    }
}

// ---------------- launch ----------------
extern "C" void kernel_launch(void* const* d_in, const int* in_sizes, int n_in,
                              void* d_out, int out_size)
{
    (void)in_sizes; (void)n_in; (void)out_size;
    const float* hidden = (const float*)d_in[0];
    const int*   pos    = (const int*)  d_in[1];
    const float* wq_a   = (const float*)d_in[2];
    const float* q_ln   = (const float*)d_in[3];
    const float* wq_b   = (const float*)d_in[4];
    const float* wkv_a  = (const float*)d_in[5];
    const float* kv_ln  = (const float*)d_in[6];
    const float* wkv_b  = (const float*)d_in[7];
    const float* wo     = (const float*)d_in[8];
    float* out = (float*)d_out;

    cudaFuncSetAttribute(tgemm_1p, cudaFuncAttributeMaxDynamicSharedMemorySize, SMEM_1P);
    cudaFuncSetAttribute(flash_k,  cudaFuncAttributeMaxDynamicSharedMemorySize, FA_SMEM);

    float *qlora, *latent, *q, *kv;
    cudaGetSymbolAddress((void**)&qlora,  g_qlora);
    cudaGetSymbolAddress((void**)&latent, g_latent);
    cudaGetSymbolAddress((void**)&q,      g_q);
    cudaGetSymbolAddress((void**)&kv,     g_kv);

    __half *hidf, *qlof, *latf, *Ofp, *qf, *Kcf, *Vtf,
           *wqaTf, *wkvaTf, *wqbTf, *wkvbTf, *woTf;
    cudaGetSymbolAddress((void**)&hidf,   g_hid_f);
    cudaGetSymbolAddress((void**)&qlof,   g_qlo_f);
    cudaGetSymbolAddress((void**)&latf,   g_lat_f);
    cudaGetSymbolAddress((void**)&Ofp,    g_Of);
    cudaGetSymbolAddress((void**)&qf,     g_qf);
    cudaGetSymbolAddress((void**)&Kcf,    g_Kc_f);
    cudaGetSymbolAddress((void**)&Vtf,    g_Vt_f);
    cudaGetSymbolAddress((void**)&wqaTf,  g_wqaTf);
    cudaGetSymbolAddress((void**)&wkvaTf, g_wkvaTf);
    cudaGetSymbolAddress((void**)&wqbTf,  g_wqbTf);
    cudaGetSymbolAddress((void**)&wkvbTf, g_wkvbTf);
    cudaGetSymbolAddress((void**)&woTf,   g_woTf);

    dim3 blk(256);

    // ---- weight conversions ----
    conv_tr_f16_k<<<dim3(QLORA/32, HID/32), blk>>>(wq_a,  wqaTf,  HID, QLORA);
    conv_tr_f16_k<<<dim3(LATW/32,  HID/32), blk>>>(wkv_a, wkvaTf, HID, LATW);
    conv_tr_f16_k<<<dim3(HDQ/32, QLORA/32), blk>>>(wq_b,  wqbTf,  QLORA, HDQ);
    conv_tr_f16_k<<<dim3(KVW/32,  DKV/32),  blk>>>(wkv_b, wkvbTf, DKV, KVW);
    conv_tr_f16_k<<<dim3(HID/32,  HDQ/32),  blk>>>(wo,    woTf,   HDQ, HID);
    conv_f16_k<<<2048, 256>>>(hidden, hidf, (long)T * HID);

    // ---- down projections ----
    tgemm_1p<<<dim3(QLORA/128, T/128), blk, SMEM_1P>>>(hidf, wqaTf,
        qlora, T, QLORA, HID, HID, HID, QLORA);
    tgemm_1p<<<dim3((LATW+127)/128, T/128), blk, SMEM_1P>>>(hidf, wkvaTf,
        latent, T, LATW, HID, HID, HID, LATW);

    // ---- norms + rope(k_pe) ----
    rmsnorm_f16_k<<<T, 256>>>(qlora, q_ln, qlof, QLORA, QLORA);
    rope_kpe_k<<<T, 32>>>(latent, pos);
    rmsnorm_f16_k<<<T, 256>>>(latent, kv_ln, latf, DKV, LATW);

    // ---- up projections ----
    tgemm_1p<<<dim3(HDQ/128, T/128), blk, SMEM_1P>>>(qlof, wqbTf,
        q, T, HDQ, QLORA, QLORA, QLORA, HDQ);
    tgemm_1p<<<dim3(KVW/128, T/128), blk, SMEM_1P>>>(latf, wkvbTf,
        kv, T, KVW, DKV, DKV, DKV, KVW);

    // ---- q rope; K assembly; V transpose ----
    rope_conv_q_k<<<T, 256>>>(q, pos, qf);
    build_K_f16_k<<<T, 256>>>(kv, latent, Kcf);
    transpose_v_f16_k<<<dim3(DV/32, T/32, NH), blk>>>(kv, Vtf);

    // ---- fused flash attention (fp16 1-term) ----
    flash_k<<<dim3(T/128, NH), blk, FA_SMEM>>>(qf, Kcf, Vtf, Ofp);

    // ---- final projection ----
    tgemm_1p<<<dim3(HID/128, T/128), blk, SMEM_1P>>>(Ofp, woTf,
        out, T, HID, HDQ, HDQ, HDQ, HID);
}

// round 13
// speedup vs baseline: 2.4972x; 1.0456x over previous
#include <cuda_runtime.h>
#include <cuda_fp16.h>
#include <math.h>
#include <stdint.h>

// ---------------- problem constants ----------------
constexpr int T    = 2048;
constexpr int HID  = 4096;
constexpr int NH   = 32;
constexpr int DQ   = 256;
constexpr int DN   = 192;
constexpr int DR   = 64;
constexpr int DV   = 256;
constexpr int DKV  = 512;
constexpr int QLORA= 2048;
constexpr int HDQ  = NH * DQ;        // 8192
constexpr int KVW  = NH * (DN + DV); // 14336
constexpr int LATW = DKV + DR;       // 576
constexpr int DPW  = QLORA + LATW;   // 2624 (merged down-proj width)

// ---------------- fp16 buffers ----------------
__device__ __half g_hid_f  [(size_t)T * HID];
__device__ __half g_dproj  [(size_t)T * DPW];      // [qlora | kv_a | k_pe]
__device__ __half g_qlo_f  [(size_t)T * QLORA];
__device__ __half g_lat_f  [(size_t)T * DKV];
__device__ __half g_qf     [(size_t)T * HDQ];      // q (roped in place)
__device__ __half g_kv16   [(size_t)T * KVW];
__device__ __half g_Of     [(size_t)T * HDQ];
__device__ __half g_Kc_f   [(size_t)T * HDQ];
__device__ __half g_Vt_f   [(size_t)NH * DV * T];
__device__ __half g_wdTf   [(size_t)DPW * HID];    // [wq_a ; wkv_a] transposed
__device__ __half g_wqbTf  [(size_t)HDQ * QLORA];
__device__ __half g_wkvbTf [(size_t)KVW * DKV];
__device__ __half g_woTf   [(size_t)HID * HDQ];

// ---------------- helpers ----------------
__device__ __forceinline__ void mma_f16(float* c, const uint32_t* a, const uint32_t* b) {
    asm volatile(
        "mma.sync.aligned.m16n8k16.row.col.f32.f16.f16.f32 "
        "{%0,%1,%2,%3}, {%4,%5,%6,%7}, {%8,%9}, {%0,%1,%2,%3};\n"
        : "+f"(c[0]), "+f"(c[1]), "+f"(c[2]), "+f"(c[3])
        : "r"(a[0]), "r"(a[1]), "r"(a[2]), "r"(a[3]), "r"(b[0]), "r"(b[1]));
}

__device__ __forceinline__ void ldsm4(uint32_t& r0, uint32_t& r1, uint32_t& r2, uint32_t& r3, uint32_t a) {
    asm volatile("ldmatrix.sync.aligned.m8n8.x4.shared.b16 {%0,%1,%2,%3}, [%4];"
        : "=r"(r0), "=r"(r1), "=r"(r2), "=r"(r3) : "r"(a));
}

__device__ __forceinline__ void cp16(uint32_t d, const void* s) {
    asm volatile("cp.async.cg.shared.global [%0], [%1], 16;" :: "r"(d), "l"(s));
}

// ============================================================================
// 1-pass fp16 GEMM: C = Ah @ Bh^T, templated output (fp16 or fp32).
// Block 128x128, BK=32, 256 thr, 2 CTAs/SM (proven config).
// ============================================================================
constexpr int F_TILE  = 128 * 80;
constexpr int P_STAGE = 2 * F_TILE;
constexpr int SMEM_1P = 2 * P_STAGE;     // 40960

template <typename OutT>
__global__ __launch_bounds__(256, 2) void tgemm_1p(
    const __half* __restrict__ Ah, const __half* __restrict__ Bh,
    OutT* __restrict__ C,
    int M, int N, int K, int lda, int ldb, int ldc)
{
    const int bx = blockIdx.x, by = blockIdx.y;

    extern __shared__ char smem[];
    const uint32_t sb = (uint32_t)__cvta_generic_to_shared(smem);

    const int tid = threadIdx.x, lane = tid & 31, warp = tid >> 5;
    const int wm = warp & 1, wn = warp >> 1;
    const int g = lane >> 2, t4 = lane & 3;
    const int r0 = tid >> 2, c4 = tid & 3;
    const int Nm1 = N - 1;

    const int lr  = (lane & 7) + ((lane >> 3) & 1) * 8;
    const int lkb = (lane >> 4) * 16;
    const uint32_t aBase = sb + (uint32_t)((wm * 64 + lr) * 80 + lkb);
    const uint32_t bBase = sb + (uint32_t)(F_TILE + (wn * 32 + lr) * 80 + lkb);

    float acc[4][4][4] = {};
    const int nchunks = K / 32;

    auto load_chunk = [&](int k0, uint32_t st) {
        #pragma unroll
        for (int c = 0; c < 2; c++) {
            int row = r0 + c * 64;
            uint32_t ds = sb + st + (uint32_t)(row * 80 + c4 * 16);
            long aoff = (long)(by * 128 + row) * lda + k0 + c4 * 8;
            cp16(ds, Ah + aoff);
            int nr = bx * 128 + row; if (nr > Nm1) nr = Nm1;
            long boff = (long)nr * ldb + k0 + c4 * 8;
            cp16(ds + F_TILE, Bh + boff);
        }
    };

    load_chunk(0, 0);
    asm volatile("cp.async.commit_group;");

    for (int i = 0; i < nchunks; i++) {
        if (i + 1 < nchunks)
            load_chunk((i + 1) * 32, (uint32_t)(((i + 1) & 1) * P_STAGE));
        asm volatile("cp.async.commit_group;");
        asm volatile("cp.async.wait_group 1;");
        __syncthreads();

        const uint32_t sof = (uint32_t)((i & 1) * P_STAGE);
        #pragma unroll
        for (int ks = 0; ks < 2; ks++) {
            uint32_t bh[4][2];
            #pragma unroll
            for (int p = 0; p < 2; p++) {
                uint32_t ad = bBase + sof + (uint32_t)(p * 16 * 80 + ks * 32);
                uint32_t x0, x1, x2, x3;
                ldsm4(x0, x1, x2, x3, ad);
                bh[2*p][0] = x0; bh[2*p+1][0] = x1; bh[2*p][1] = x2; bh[2*p+1][1] = x3;
            }
            #pragma unroll
            for (int mt = 0; mt < 4; mt++) {
                uint32_t ah[4];
                uint32_t ad = aBase + sof + (uint32_t)(mt * 16 * 80 + ks * 32);
                ldsm4(ah[0], ah[1], ah[2], ah[3], ad);
                #pragma unroll
                for (int nt = 0; nt < 4; nt++)
                    mma_f16(acc[mt][nt], ah, bh[nt]);
            }
        }
        __syncthreads();
    }

    #pragma unroll
    for (int mt = 0; mt < 4; mt++) {
        int r = by * 128 + wm * 64 + mt * 16 + g;
        #pragma unroll
        for (int nt = 0; nt < 4; nt++) {
            int c = bx * 128 + wn * 32 + nt * 8 + 2 * t4;
            if (c < N) {
                if (sizeof(OutT) == 4) {
                    float* Cf = (float*)C;
                    *(float2*)&Cf[(long)r * ldc + c]       = make_float2(acc[mt][nt][0], acc[mt][nt][1]);
                    *(float2*)&Cf[(long)(r + 8) * ldc + c] = make_float2(acc[mt][nt][2], acc[mt][nt][3]);
                } else {
                    __half* Ch = (__half*)C;
                    *(__half2*)&Ch[(long)r * ldc + c]       = __floats2half2_rn(acc[mt][nt][0], acc[mt][nt][1]);
                    *(__half2*)&Ch[(long)(r + 8) * ldc + c] = __floats2half2_rn(acc[mt][nt][2], acc[mt][nt][3]);
                }
            }
        }
    }
}

// ============================================================================
// Fused flash attention, fp16 1-term, Q smem-resident.
// smem: Q 8x10240 = 81920; K 2x10240 at 81920; V 2x34816 at 102400. Total 172032.
// ============================================================================
constexpr int QPL  = 10240;
constexpr int KOFF = 8 * QPL;            // 81920
constexpr int VPL  = 34816;
constexpr int VOFF = KOFF + 2 * QPL;     // 102400
constexpr int FA_SMEM = VOFF + 2 * VPL;  // 172032

__global__ __launch_bounds__(256, 1) void flash_k(
    const __half* __restrict__ Qf, const __half* __restrict__ Kf,
    const __half* __restrict__ Vf, __half* __restrict__ Of)
{
    const int qi = gridDim.x - 1 - blockIdx.x;   // heavy tiles first
    const int h  = blockIdx.y;

    extern __shared__ char smem[];
    const uint32_t sb = (uint32_t)__cvta_generic_to_shared(smem);

    const int tid = threadIdx.x, lane = tid & 31, w = tid >> 5;
    const int g = lane >> 2, t4 = lane & 3;
    const int lr  = (lane & 7) + ((lane >> 3) & 1) * 8;
    const int lkb = (lane >> 4) * 16;

    // ---- load Q resident (once per block) ----
    #pragma unroll
    for (int p = 0; p < 16; p++) {
        int id = tid + p * 256;
        int chunk = id >> 9, wi = id & 511;
        int row = wi >> 2, cc = wi & 3;
        uint32_t dst = sb + (uint32_t)(chunk * QPL + row * 80 + cc * 16);
        size_t qo = (size_t)(qi * 128 + row) * HDQ + h * DQ + chunk * 32 + cc * 8;
        cp16(dst, Qf + qo);
    }
    asm volatile("cp.async.commit_group;");

    float oacc[32][4];
    #pragma unroll
    for (int i = 0; i < 32; i++)
        #pragma unroll
        for (int c = 0; c < 4; c++) oacc[i][c] = 0.f;
    float m0 = -1e30f, m1 = -1e30f, l0 = 0.f, l1 = 0.f;

    const float scale = 0.0625f;

    for (int j = 0; j <= qi; j++) {
        float sacc[16][4] = {};

        auto load_kc = [&](int i, uint32_t st) {
            const int d = i * 32;
            #pragma unroll
            for (int p = 0; p < 2; p++) {
                int id = tid + p * 256;
                int row = id >> 2, cc = id & 3;
                uint32_t dst = sb + st + (uint32_t)(row * 80 + cc * 16);
                size_t ko = (size_t)(j * 128 + row) * HDQ + h * DQ + d + cc * 8;
                cp16(dst, Kf + ko);
            }
        };

        load_kc(0, KOFF);
        asm volatile("cp.async.commit_group;");
        load_kc(1, KOFF + QPL);
        asm volatile("cp.async.commit_group;");

        // prefetch BOTH V dv-chunks
        #pragma unroll
        for (int dvc = 0; dvc < 2; dvc++) {
            #pragma unroll
            for (int p = 0; p < 4; p++) {
                int id = tid + p * 256;
                int row = id >> 3, cc = id & 7;
                uint32_t dst = sb + (uint32_t)(VOFF + dvc * VPL + row * 272 + cc * 32);
                size_t vo = (size_t)h * DV * T + (size_t)(dvc * 128 + row) * T + j * 128 + cc * 16;
                cp16(dst,      Vf + vo);
                cp16(dst + 16, Vf + vo + 8);
            }
        }
        asm volatile("cp.async.commit_group;");

        for (int i = 0; i < 8; i++) {
            asm volatile("cp.async.wait_group 1;");
            __syncthreads();
            const uint32_t st = (uint32_t)(KOFF + (i & 1) * QPL);
            const uint32_t qBase = sb + (uint32_t)(i * QPL + (w * 16 + lr) * 80 + lkb);
            #pragma unroll
            for (int ks = 0; ks < 2; ks++) {
                uint32_t ah[4];
                ldsm4(ah[0], ah[1], ah[2], ah[3], qBase + ks * 32);
                #pragma unroll
                for (int p = 0; p < 8; p++) {
                    uint32_t bh[2][2], x0, x1, x2, x3;
                    uint32_t bd = sb + st + (uint32_t)((p * 16 + lr) * 80 + lkb + ks * 32);
                    ldsm4(x0, x1, x2, x3, bd);
                    bh[0][0] = x0; bh[1][0] = x1; bh[0][1] = x2; bh[1][1] = x3;
                    #pragma unroll
                    for (int q2 = 0; q2 < 2; q2++)
                        mma_f16(sacc[p * 2 + q2], ah, bh[q2]);
                }
            }
            __syncthreads();
            if (i + 2 < 8) load_kc(i + 2, st);
            asm volatile("cp.async.commit_group;");
        }
        asm volatile("cp.async.wait_group 0;");

        // ---------------- softmax (registers) ----------------
        #pragma unroll
        for (int nt = 0; nt < 16; nt++)
            #pragma unroll
            for (int c = 0; c < 4; c++) sacc[nt][c] *= scale;

        if (j == qi) {
            const int rr0 = w * 16 + g, rr1 = rr0 + 8;
            #pragma unroll
            for (int nt = 0; nt < 16; nt++) {
                int col = nt * 8 + 2 * t4;
                if (col     > rr0) sacc[nt][0] = -1e30f;
                if (col + 1 > rr0) sacc[nt][1] = -1e30f;
                if (col     > rr1) sacc[nt][2] = -1e30f;
                if (col + 1 > rr1) sacc[nt][3] = -1e30f;
            }
        }

        float tm0 = -1e30f, tm1 = -1e30f;
        #pragma unroll
        for (int nt = 0; nt < 16; nt++) {
            tm0 = fmaxf(tm0, fmaxf(sacc[nt][0], sacc[nt][1]));
            tm1 = fmaxf(tm1, fmaxf(sacc[nt][2], sacc[nt][3]));
        }
        tm0 = fmaxf(tm0, __shfl_xor_sync(0xffffffffu, tm0, 1));
        tm0 = fmaxf(tm0, __shfl_xor_sync(0xffffffffu, tm0, 2));
        tm1 = fmaxf(tm1, __shfl_xor_sync(0xffffffffu, tm1, 1));
        tm1 = fmaxf(tm1, __shfl_xor_sync(0xffffffffu, tm1, 2));

        float nm0 = fmaxf(m0, tm0), nm1 = fmaxf(m1, tm1);
        float a0 = expf(m0 - nm0), a1 = expf(m1 - nm1);
        m0 = nm0; m1 = nm1;

        float s0 = 0.f, s1 = 0.f;
        #pragma unroll
        for (int nt = 0; nt < 16; nt++) {
            sacc[nt][0] = expf(sacc[nt][0] - m0); s0 += sacc[nt][0];
            sacc[nt][1] = expf(sacc[nt][1] - m0); s0 += sacc[nt][1];
            sacc[nt][2] = expf(sacc[nt][2] - m1); s1 += sacc[nt][2];
            sacc[nt][3] = expf(sacc[nt][3] - m1); s1 += sacc[nt][3];
        }
        s0 += __shfl_xor_sync(0xffffffffu, s0, 1);
        s0 += __shfl_xor_sync(0xffffffffu, s0, 2);
        s1 += __shfl_xor_sync(0xffffffffu, s1, 1);
        s1 += __shfl_xor_sync(0xffffffffu, s1, 2);
        l0 = l0 * a0 + s0;
        l1 = l1 * a1 + s1;

        #pragma unroll
        for (int i = 0; i < 32; i++) {
            oacc[i][0] *= a0; oacc[i][1] *= a0;
            oacc[i][2] *= a1; oacc[i][3] *= a1;
        }

        uint32_t Pf[8][4];
        #pragma unroll
        for (int ks = 0; ks < 8; ks++) {
            #pragma unroll
            for (int hf = 0; hf < 2; hf++) {
                const float* c = sacc[2 * ks + hf];
                __half2 v01 = __floats2half2_rn(c[0], c[1]);
                __half2 v23 = __floats2half2_rn(c[2], c[3]);
                Pf[ks][hf * 2]     = *(uint32_t*)&v01;
                Pf[ks][hf * 2 + 1] = *(uint32_t*)&v23;
            }
        }

        // ---------------- PV: V resident ----------------
        __syncthreads();
        #pragma unroll
        for (int dvc = 0; dvc < 2; dvc++) {
            #pragma unroll
            for (int ks = 0; ks < 8; ks++) {
                #pragma unroll
                for (int p = 0; p < 8; p++) {
                    uint32_t vh[2][2], x0, x1, x2, x3;
                    uint32_t bd = sb + (uint32_t)(VOFF + dvc * VPL + (p * 16 + lr) * 272 + lkb + ks * 32);
                    ldsm4(x0, x1, x2, x3, bd);
                    vh[0][0] = x0; vh[1][0] = x1; vh[0][1] = x2; vh[1][1] = x3;
                    #pragma unroll
                    for (int q2 = 0; q2 < 2; q2++)
                        mma_f16(oacc[dvc * 16 + p * 2 + q2], Pf[ks], vh[q2]);
                }
            }
        }
        __syncthreads();
    }

    const float i0 = 1.f / l0, i1 = 1.f / l1;
    const int r0 = qi * 128 + w * 16 + g;
    __half* o0 = Of + (size_t)r0 * HDQ + h * DV;
    __half* o1 = o0 + (size_t)8 * HDQ;
    #pragma unroll
    for (int nt = 0; nt < 32; nt++) {
        int c = nt * 8 + 2 * t4;
        __half2 v0 = __floats2half2_rn(oacc[nt][0] * i0, oacc[nt][1] * i0);
        __half2 v1 = __floats2half2_rn(oacc[nt][2] * i1, oacc[nt][3] * i1);
        *(__half2*)&o0[c] = v0;
        *(__half2*)&o1[c] = v1;
    }
}

// ---------------- fp32 -> fp16 ----------------
__global__ void conv_f16_k(const float* __restrict__ x, __half* __restrict__ h, long n)
{
    long i = (long)blockIdx.x * blockDim.x + threadIdx.x;
    long stride = (long)gridDim.x * blockDim.x;
    for (; i < n; i += stride) h[i] = __float2half_rn(x[i]);
}

// ---------------- fp32 [R,C] -> fp16 transposed [C,R] ----------------
__global__ void conv_tr_f16_k(const float* __restrict__ x, __half* __restrict__ h, int R, int C)
{
    __shared__ float tile[32][33];
    const int c0 = blockIdx.x * 32, rr0 = blockIdx.y * 32;
    const int tx = threadIdx.x & 31, ty = threadIdx.x >> 5;
    #pragma unroll
    for (int i = 0; i < 4; i++) {
        int r = rr0 + ty + i * 8;
        tile[ty + i * 8][tx] = x[(long)r * C + c0 + tx];
    }
    __syncthreads();
    #pragma unroll
    for (int i = 0; i < 4; i++) {
        int c = c0 + ty + i * 8;
        long o = (long)c * R + rr0 + tx;
        h[o] = __float2half_rn(tile[tx][ty + i * 8]);
    }
}

// ---------------- RMSNorm fp16 in -> fp16 out ----------------
__global__ void rmsnorm_h_k(const __half* __restrict__ x, const float* __restrict__ w,
                            __half* __restrict__ o, int N, int ldin)
{
    const __half* p = x + (long)blockIdx.x * ldin;
    __shared__ float red[8];
    __shared__ float bc;
    const int lane = threadIdx.x & 31, wid = threadIdx.x >> 5;

    float s = 0.f;
    for (int j = threadIdx.x; j < N; j += blockDim.x) { float v = __half2float(p[j]); s += v * v; }
    #pragma unroll
    for (int of = 16; of; of >>= 1) s += __shfl_xor_sync(0xffffffffu, s, of);
    if (lane == 0) red[wid] = s;
    __syncthreads();
    if (threadIdx.x == 0) {
        float v = 0.f;
        for (int wI = 0; wI < 8; wI++) v += red[wI];
        bc = rsqrtf(v / N + 1e-6f);
    }
    __syncthreads();
    float r = bc;
    long ob = (long)blockIdx.x * N;
    for (int j = threadIdx.x; j < N; j += blockDim.x)
        o[ob + j] = __float2half_rn(__half2float(p[j]) * r * w[j]);
}

// ---------------- rope k_pe in-place on dproj (fp16) ----------------
__global__ void rope_kpe_k(__half* __restrict__ dp, const int* __restrict__ pos)
{
    const int tt = blockIdx.x, i = threadIdx.x;
    double inv = pow(10000.0, -(double)i / 32.0);
    double sd, cd;
    sincos((double)pos[tt] * inv, &sd, &cd);
    float c = (float)cd, s = (float)sd;
    __half* p = dp + (size_t)tt * DPW + QLORA + DKV;
    float x1 = __half2float(p[i]), x2 = __half2float(p[i + 32]);
    p[i]      = __float2half_rn(x1 * c - x2 * s);
    p[i + 32] = __float2half_rn(x2 * c + x1 * s);
}

// ---------------- rope q in-place (fp16, rope dims only) ----------------
__global__ void rope_q_inpl_k(__half* __restrict__ q, const int* __restrict__ pos)
{
    const int tt = blockIdx.x, h = blockIdx.y, i = threadIdx.x;
    double inv = pow(10000.0, -(double)i / 32.0);
    double sd, cd;
    sincos((double)pos[tt] * inv, &sd, &cd);
    float c = (float)cd, s = (float)sd;
    __half* p = q + (size_t)tt * HDQ + h * DQ + DN;
    float x1 = __half2float(p[i]), x2 = __half2float(p[i + 32]);
    p[i]      = __float2half_rn(x1 * c - x2 * s);
    p[i + 32] = __float2half_rn(x2 * c + x1 * s);
}

// ---------------- K assembly (fp16 in/out) ----------------
__global__ void build_K_h_k(const __half* __restrict__ kv, const __half* __restrict__ dp,
                            __half* __restrict__ Kc)
{
    const int tt = blockIdx.x;
    long ob = (long)tt * HDQ;
    for (int x = threadIdx.x; x < HDQ; x += blockDim.x) {
        int hd = x >> 8, d = x & 255;
        __half v = (d < DN) ? kv[(size_t)tt * KVW + hd * (DN + DV) + d]
                            : dp[(size_t)tt * DPW + QLORA + DKV + (d - DN)];
        Kc[ob + x] = v;
    }
}

// ---------------- V transpose per head (fp16) -> [h][DV][T] ----------------
__global__ void transpose_v_h_k(const __half* __restrict__ kv, __half* __restrict__ h)
{
    __shared__ __half tile[32][34];
    const int d0 = blockIdx.x * 32, t0 = blockIdx.y * 32, hd = blockIdx.z;
    const int tx = threadIdx.x & 31, ty = threadIdx.x >> 5;
    #pragma unroll
    for (int i = 0; i < 4; i++) {
        int tr = t0 + ty + i * 8;
        tile[ty + i * 8][tx] = kv[(size_t)tr * KVW + hd * (DN + DV) + DN + d0 + tx];
    }
    __syncthreads();
    #pragma unroll
    for (int i = 0; i < 4; i++) {
        int d = d0 + ty + i * 8;
        long o = (long)hd * DV * T + (long)d * T + t0 + tx;
        h[o] = tile[tx][ty + i * 8];
    }
}

// ---------------- launch ----------------
extern "C" void kernel_launch(void* const* d_in, const int* in_sizes, int n_in,
                              void* d_out, int out_size)
{
    (void)in_sizes; (void)n_in; (void)out_size;
    const float* hidden = (const float*)d_in[0];
    const int*   pos    = (const int*)  d_in[1];
    const float* wq_a   = (const float*)d_in[2];
    const float* q_ln   = (const float*)d_in[3];
    const float* wq_b   = (const float*)d_in[4];
    const float* wkv_a  = (const float*)d_in[5];
    const float* kv_ln  = (const float*)d_in[6];
    const float* wkv_b  = (const float*)d_in[7];
    const float* wo     = (const float*)d_in[8];
    float* out = (float*)d_out;

    cudaFuncSetAttribute(tgemm_1p<__half>, cudaFuncAttributeMaxDynamicSharedMemorySize, SMEM_1P);
    cudaFuncSetAttribute(tgemm_1p<float>,  cudaFuncAttributeMaxDynamicSharedMemorySize, SMEM_1P);
    cudaFuncSetAttribute(flash_k,          cudaFuncAttributeMaxDynamicSharedMemorySize, FA_SMEM);

    __half *hidf, *dproj, *qlof, *latf, *qf, *kv16, *Ofp, *Kcf, *Vtf,
           *wdTf, *wqbTf, *wkvbTf, *woTf;
    cudaGetSymbolAddress((void**)&hidf,   g_hid_f);
    cudaGetSymbolAddress((void**)&dproj,  g_dproj);
    cudaGetSymbolAddress((void**)&qlof,   g_qlo_f);
    cudaGetSymbolAddress((void**)&latf,   g_lat_f);
    cudaGetSymbolAddress((void**)&qf,     g_qf);
    cudaGetSymbolAddress((void**)&kv16,   g_kv16);
    cudaGetSymbolAddress((void**)&Ofp,    g_Of);
    cudaGetSymbolAddress((void**)&Kcf,    g_Kc_f);
    cudaGetSymbolAddress((void**)&Vtf,    g_Vt_f);
    cudaGetSymbolAddress((void**)&wdTf,   g_wdTf);
    cudaGetSymbolAddress((void**)&wqbTf,  g_wqbTf);
    cudaGetSymbolAddress((void**)&wkvbTf, g_wkvbTf);
    cudaGetSymbolAddress((void**)&woTf,   g_woTf);

    dim3 blk(256);

    // ---- weight conversions (wq_a and wkv_a pack into one buffer) ----
    conv_tr_f16_k<<<dim3(QLORA/32, HID/32), blk>>>(wq_a,  wdTf,                      HID, QLORA);
    conv_tr_f16_k<<<dim3(LATW/32,  HID/32), blk>>>(wkv_a, wdTf + (size_t)QLORA*HID,  HID, LATW);
    conv_tr_f16_k<<<dim3(HDQ/32, QLORA/32), blk>>>(wq_b,  wqbTf,  QLORA, HDQ);
    conv_tr_f16_k<<<dim3(KVW/32,  DKV/32),  blk>>>(wkv_b, wkvbTf, DKV, KVW);
    conv_tr_f16_k<<<dim3(HID/32,  HDQ/32),  blk>>>(wo,    woTf,   HDQ, HID);
    conv_f16_k<<<2048, 256>>>(hidden, hidf, (long)T * HID);

    // ---- merged down projection (fp16 out) ----
    tgemm_1p<__half><<<dim3((DPW + 127)/128, T/128), blk, SMEM_1P>>>(hidf, wdTf,
        dproj, T, DPW, HID, HID, HID, DPW);

    // ---- rope(k_pe) + norms ----
    rope_kpe_k<<<T, 32>>>(dproj, pos);
    rmsnorm_h_k<<<T, 256>>>(dproj,         q_ln,  qlof, QLORA, DPW);
    rmsnorm_h_k<<<T, 256>>>(dproj + QLORA, kv_ln, latf, DKV,   DPW);

    // ---- up projections (fp16 out) ----
    tgemm_1p<__half><<<dim3(HDQ/128, T/128), blk, SMEM_1P>>>(qlof, wqbTf,
        qf, T, HDQ, QLORA, QLORA, QLORA, HDQ);
    tgemm_1p<__half><<<dim3(KVW/128, T/128), blk, SMEM_1P>>>(latf, wkvbTf,
        kv16, T, KVW, DKV, DKV, DKV, KVW);

    // ---- q rope in place; K assembly; V transpose ----
    rope_q_inpl_k<<<dim3(T, NH), 32>>>(qf, pos);
    build_K_h_k<<<T, 256>>>(kv16, dproj, Kcf);
    transpose_v_h_k<<<dim3(DV/32, T/32, NH), blk>>>(kv16, Vtf);

    // ---- fused flash attention (Q resident) ----
    flash_k<<<dim3(T/128, NH), blk, FA_SMEM>>>(qf, Kcf, Vtf, Ofp);

    // ---- final projection (fp32 out) ----
    tgemm_1p<float><<<dim3(HID/128, T/128), blk, SMEM_1P>>>(Ofp, woTf,
        out, T, HID, HDQ, HDQ, HDQ, HID);
}

// round 14
// speedup vs baseline: 2.6611x; 1.0656x over previous
#include <cuda_runtime.h>
#include <cuda_fp16.h>
#include <math.h>
#include <stdint.h>

// ---------------- problem constants ----------------
constexpr int T    = 2048;
constexpr int HID  = 4096;
constexpr int NH   = 32;
constexpr int DQ   = 256;
constexpr int DN   = 192;
constexpr int DR   = 64;
constexpr int DV   = 256;
constexpr int DKV  = 512;
constexpr int QLORA= 2048;
constexpr int HDQ  = NH * DQ;        // 8192
constexpr int KVW  = NH * (DN + DV); // 14336
constexpr int LATW = DKV + DR;       // 576
constexpr int DPW  = QLORA + LATW;   // 2624

// ---------------- buffers ----------------
__device__ float  g_dp_part [2][(size_t)T * DPW];   // down-proj split-K partials
__device__ float  g_out_part[4][(size_t)T * HID];   // wo split-K partials
__device__ __half g_hid_f  [(size_t)T * HID];
__device__ __half g_qlo_f  [(size_t)T * QLORA];
__device__ __half g_lat_f  [(size_t)T * DKV];
__device__ __half g_kpe    [(size_t)T * DR];
__device__ __half g_qf     [(size_t)T * HDQ];
__device__ __half g_kv16   [(size_t)T * KVW];
__device__ __half g_Of     [(size_t)T * HDQ];
__device__ __half g_Kc_f   [(size_t)T * HDQ];
__device__ __half g_Vt_f   [(size_t)NH * DV * T];
__device__ __half g_wdTf   [(size_t)DPW * HID];
__device__ __half g_wqbTf  [(size_t)HDQ * QLORA];
__device__ __half g_wkvbTf [(size_t)KVW * DKV];
__device__ __half g_woTf   [(size_t)HID * HDQ];

// ---------------- helpers ----------------
__device__ __forceinline__ void mma_f16(float* c, const uint32_t* a, const uint32_t* b) {
    asm volatile(
        "mma.sync.aligned.m16n8k16.row.col.f32.f16.f16.f32 "
        "{%0,%1,%2,%3}, {%4,%5,%6,%7}, {%8,%9}, {%0,%1,%2,%3};\n"
        : "+f"(c[0]), "+f"(c[1]), "+f"(c[2]), "+f"(c[3])
        : "r"(a[0]), "r"(a[1]), "r"(a[2]), "r"(a[3]), "r"(b[0]), "r"(b[1]));
}

__device__ __forceinline__ void ldsm4(uint32_t& r0, uint32_t& r1, uint32_t& r2, uint32_t& r3, uint32_t a) {
    asm volatile("ldmatrix.sync.aligned.m8n8.x4.shared.b16 {%0,%1,%2,%3}, [%4];"
        : "=r"(r0), "=r"(r1), "=r"(r2), "=r"(r3) : "r"(a));
}

__device__ __forceinline__ void cp16(uint32_t d, const void* s) {
    asm volatile("cp.async.cg.shared.global [%0], [%1], 16;" :: "r"(d), "l"(s));
}

// ============================================================================
// 1-pass fp16 GEMM with optional split-K (blockIdx.z = k-slice).
// C = A[:, z*K:(z+1)*K] @ B[:, z*K:(z+1)*K]^T  written to C + z*sC.
// Block 128x128, BK=32, 256 thr, 2 CTAs/SM.
// ============================================================================
constexpr int F_TILE  = 128 * 80;
constexpr int P_STAGE = 2 * F_TILE;
constexpr int SMEM_1P = 2 * P_STAGE;     // 40960

template <typename OutT>
__global__ __launch_bounds__(256, 2) void tgemm_1p(
    const __half* __restrict__ Ah, const __half* __restrict__ Bh,
    OutT* __restrict__ C,
    int M, int N, int K, int lda, int ldb, int ldc, long sC)
{
    const int bx = blockIdx.x, by = blockIdx.y;
    Ah += (long)blockIdx.z * K;
    Bh += (long)blockIdx.z * K;
    C  += (long)blockIdx.z * sC;

    extern __shared__ char smem[];
    const uint32_t sb = (uint32_t)__cvta_generic_to_shared(smem);

    const int tid = threadIdx.x, lane = tid & 31, warp = tid >> 5;
    const int wm = warp & 1, wn = warp >> 1;
    const int g = lane >> 2, t4 = lane & 3;
    const int r0 = tid >> 2, c4 = tid & 3;
    const int Nm1 = N - 1;

    const int lr  = (lane & 7) + ((lane >> 3) & 1) * 8;
    const int lkb = (lane >> 4) * 16;
    const uint32_t aBase = sb + (uint32_t)((wm * 64 + lr) * 80 + lkb);
    const uint32_t bBase = sb + (uint32_t)(F_TILE + (wn * 32 + lr) * 80 + lkb);

    float acc[4][4][4] = {};
    const int nchunks = K / 32;

    auto load_chunk = [&](int k0, uint32_t st) {
        #pragma unroll
        for (int c = 0; c < 2; c++) {
            int row = r0 + c * 64;
            uint32_t ds = sb + st + (uint32_t)(row * 80 + c4 * 16);
            long aoff = (long)(by * 128 + row) * lda + k0 + c4 * 8;
            cp16(ds, Ah + aoff);
            int nr = bx * 128 + row; if (nr > Nm1) nr = Nm1;
            long boff = (long)nr * ldb + k0 + c4 * 8;
            cp16(ds + F_TILE, Bh + boff);
        }
    };

    load_chunk(0, 0);
    asm volatile("cp.async.commit_group;");

    for (int i = 0; i < nchunks; i++) {
        if (i + 1 < nchunks)
            load_chunk((i + 1) * 32, (uint32_t)(((i + 1) & 1) * P_STAGE));
        asm volatile("cp.async.commit_group;");
        asm volatile("cp.async.wait_group 1;");
        __syncthreads();

        const uint32_t sof = (uint32_t)((i & 1) * P_STAGE);
        #pragma unroll
        for (int ks = 0; ks < 2; ks++) {
            uint32_t bh[4][2];
            #pragma unroll
            for (int p = 0; p < 2; p++) {
                uint32_t ad = bBase + sof + (uint32_t)(p * 16 * 80 + ks * 32);
                uint32_t x0, x1, x2, x3;
                ldsm4(x0, x1, x2, x3, ad);
                bh[2*p][0] = x0; bh[2*p+1][0] = x1; bh[2*p][1] = x2; bh[2*p+1][1] = x3;
            }
            #pragma unroll
            for (int mt = 0; mt < 4; mt++) {
                uint32_t ah[4];
                uint32_t ad = aBase + sof + (uint32_t)(mt * 16 * 80 + ks * 32);
                ldsm4(ah[0], ah[1], ah[2], ah[3], ad);
                #pragma unroll
                for (int nt = 0; nt < 4; nt++)
                    mma_f16(acc[mt][nt], ah, bh[nt]);
            }
        }
        __syncthreads();
    }

    #pragma unroll
    for (int mt = 0; mt < 4; mt++) {
        int r = by * 128 + wm * 64 + mt * 16 + g;
        #pragma unroll
        for (int nt = 0; nt < 4; nt++) {
            int c = bx * 128 + wn * 32 + nt * 8 + 2 * t4;
            if (c < N) {
                if (sizeof(OutT) == 4) {
                    float* Cf = (float*)C;
                    *(float2*)&Cf[(long)r * ldc + c]       = make_float2(acc[mt][nt][0], acc[mt][nt][1]);
                    *(float2*)&Cf[(long)(r + 8) * ldc + c] = make_float2(acc[mt][nt][2], acc[mt][nt][3]);
                } else {
                    __half* Ch = (__half*)C;
                    *(__half2*)&Ch[(long)r * ldc + c]       = __floats2half2_rn(acc[mt][nt][0], acc[mt][nt][1]);
                    *(__half2*)&Ch[(long)(r + 8) * ldc + c] = __floats2half2_rn(acc[mt][nt][2], acc[mt][nt][3]);
                }
            }
        }
    }
}

// ============================================================================
// Fused flash attention, fp16 1-term, Q smem-resident (unchanged from R13).
// ============================================================================
constexpr int QPL  = 10240;
constexpr int KOFF = 8 * QPL;
constexpr int VPL  = 34816;
constexpr int VOFF = KOFF + 2 * QPL;
constexpr int FA_SMEM = VOFF + 2 * VPL;  // 172032

__global__ __launch_bounds__(256, 1) void flash_k(
    const __half* __restrict__ Qf, const __half* __restrict__ Kf,
    const __half* __restrict__ Vf, __half* __restrict__ Of)
{
    const int qi = gridDim.x - 1 - blockIdx.x;
    const int h  = blockIdx.y;

    extern __shared__ char smem[];
    const uint32_t sb = (uint32_t)__cvta_generic_to_shared(smem);

    const int tid = threadIdx.x, lane = tid & 31, w = tid >> 5;
    const int g = lane >> 2, t4 = lane & 3;
    const int lr  = (lane & 7) + ((lane >> 3) & 1) * 8;
    const int lkb = (lane >> 4) * 16;

    #pragma unroll
    for (int p = 0; p < 16; p++) {
        int id = tid + p * 256;
        int chunk = id >> 9, wi = id & 511;
        int row = wi >> 2, cc = wi & 3;
        uint32_t dst = sb + (uint32_t)(chunk * QPL + row * 80 + cc * 16);
        size_t qo = (size_t)(qi * 128 + row) * HDQ + h * DQ + chunk * 32 + cc * 8;
        cp16(dst, Qf + qo);
    }
    asm volatile("cp.async.commit_group;");

    float oacc[32][4];
    #pragma unroll
    for (int i = 0; i < 32; i++)
        #pragma unroll
        for (int c = 0; c < 4; c++) oacc[i][c] = 0.f;
    float m0 = -1e30f, m1 = -1e30f, l0 = 0.f, l1 = 0.f;

    const float scale = 0.0625f;

    for (int j = 0; j <= qi; j++) {
        float sacc[16][4] = {};

        auto load_kc = [&](int i, uint32_t st) {
            const int d = i * 32;
            #pragma unroll
            for (int p = 0; p < 2; p++) {
                int id = tid + p * 256;
                int row = id >> 2, cc = id & 3;
                uint32_t dst = sb + st + (uint32_t)(row * 80 + cc * 16);
                size_t ko = (size_t)(j * 128 + row) * HDQ + h * DQ + d + cc * 8;
                cp16(dst, Kf + ko);
            }
        };

        load_kc(0, KOFF);
        asm volatile("cp.async.commit_group;");
        load_kc(1, KOFF + QPL);
        asm volatile("cp.async.commit_group;");

        #pragma unroll
        for (int dvc = 0; dvc < 2; dvc++) {
            #pragma unroll
            for (int p = 0; p < 4; p++) {
                int id = tid + p * 256;
                int row = id >> 3, cc = id & 7;
                uint32_t dst = sb + (uint32_t)(VOFF + dvc * VPL + row * 272 + cc * 32);
                size_t vo = (size_t)h * DV * T + (size_t)(dvc * 128 + row) * T + j * 128 + cc * 16;
                cp16(dst,      Vf + vo);
                cp16(dst + 16, Vf + vo + 8);
            }
        }
        asm volatile("cp.async.commit_group;");

        for (int i = 0; i < 8; i++) {
            asm volatile("cp.async.wait_group 1;");
            __syncthreads();
            const uint32_t st = (uint32_t)(KOFF + (i & 1) * QPL);
            const uint32_t qBase = sb + (uint32_t)(i * QPL + (w * 16 + lr) * 80 + lkb);
            #pragma unroll
            for (int ks = 0; ks < 2; ks++) {
                uint32_t ah[4];
                ldsm4(ah[0], ah[1], ah[2], ah[3], qBase + ks * 32);
                #pragma unroll
                for (int p = 0; p < 8; p++) {
                    uint32_t bh[2][2], x0, x1, x2, x3;
                    uint32_t bd = sb + st + (uint32_t)((p * 16 + lr) * 80 + lkb + ks * 32);
                    ldsm4(x0, x1, x2, x3, bd);
                    bh[0][0] = x0; bh[1][0] = x1; bh[0][1] = x2; bh[1][1] = x3;
                    #pragma unroll
                    for (int q2 = 0; q2 < 2; q2++)
                        mma_f16(sacc[p * 2 + q2], ah, bh[q2]);
                }
            }
            __syncthreads();
            if (i + 2 < 8) load_kc(i + 2, st);
            asm volatile("cp.async.commit_group;");
        }
        asm volatile("cp.async.wait_group 0;");

        #pragma unroll
        for (int nt = 0; nt < 16; nt++)
            #pragma unroll
            for (int c = 0; c < 4; c++) sacc[nt][c] *= scale;

        if (j == qi) {
            const int rr0 = w * 16 + g, rr1 = rr0 + 8;
            #pragma unroll
            for (int nt = 0; nt < 16; nt++) {
                int col = nt * 8 + 2 * t4;
                if (col     > rr0) sacc[nt][0] = -1e30f;
                if (col + 1 > rr0) sacc[nt][1] = -1e30f;
                if (col     > rr1) sacc[nt][2] = -1e30f;
                if (col + 1 > rr1) sacc[nt][3] = -1e30f;
            }
        }

        float tm0 = -1e30f, tm1 = -1e30f;
        #pragma unroll
        for (int nt = 0; nt < 16; nt++) {
            tm0 = fmaxf(tm0, fmaxf(sacc[nt][0], sacc[nt][1]));
            tm1 = fmaxf(tm1, fmaxf(sacc[nt][2], sacc[nt][3]));
        }
        tm0 = fmaxf(tm0, __shfl_xor_sync(0xffffffffu, tm0, 1));
        tm0 = fmaxf(tm0, __shfl_xor_sync(0xffffffffu, tm0, 2));
        tm1 = fmaxf(tm1, __shfl_xor_sync(0xffffffffu, tm1, 1));
        tm1 = fmaxf(tm1, __shfl_xor_sync(0xffffffffu, tm1, 2));

        float nm0 = fmaxf(m0, tm0), nm1 = fmaxf(m1, tm1);
        float a0 = expf(m0 - nm0), a1 = expf(m1 - nm1);
        m0 = nm0; m1 = nm1;

        float s0 = 0.f, s1 = 0.f;
        #pragma unroll
        for (int nt = 0; nt < 16; nt++) {
            sacc[nt][0] = expf(sacc[nt][0] - m0); s0 += sacc[nt][0];
            sacc[nt][1] = expf(sacc[nt][1] - m0); s0 += sacc[nt][1];
            sacc[nt][2] = expf(sacc[nt][2] - m1); s1 += sacc[nt][2];
            sacc[nt][3] = expf(sacc[nt][3] - m1); s1 += sacc[nt][3];
        }
        s0 += __shfl_xor_sync(0xffffffffu, s0, 1);
        s0 += __shfl_xor_sync(0xffffffffu, s0, 2);
        s1 += __shfl_xor_sync(0xffffffffu, s1, 1);
        s1 += __shfl_xor_sync(0xffffffffu, s1, 2);
        l0 = l0 * a0 + s0;
        l1 = l1 * a1 + s1;

        #pragma unroll
        for (int i = 0; i < 32; i++) {
            oacc[i][0] *= a0; oacc[i][1] *= a0;
            oacc[i][2] *= a1; oacc[i][3] *= a1;
        }

        uint32_t Pf[8][4];
        #pragma unroll
        for (int ks = 0; ks < 8; ks++) {
            #pragma unroll
            for (int hf = 0; hf < 2; hf++) {
                const float* c = sacc[2 * ks + hf];
                __half2 v01 = __floats2half2_rn(c[0], c[1]);
                __half2 v23 = __floats2half2_rn(c[2], c[3]);
                Pf[ks][hf * 2]     = *(uint32_t*)&v01;
                Pf[ks][hf * 2 + 1] = *(uint32_t*)&v23;
            }
        }

        __syncthreads();
        #pragma unroll
        for (int dvc = 0; dvc < 2; dvc++) {
            #pragma unroll
            for (int ks = 0; ks < 8; ks++) {
                #pragma unroll
                for (int p = 0; p < 8; p++) {
                    uint32_t vh[2][2], x0, x1, x2, x3;
                    uint32_t bd = sb + (uint32_t)(VOFF + dvc * VPL + (p * 16 + lr) * 272 + lkb + ks * 32);
                    ldsm4(x0, x1, x2, x3, bd);
                    vh[0][0] = x0; vh[1][0] = x1; vh[0][1] = x2; vh[1][1] = x3;
                    #pragma unroll
                    for (int q2 = 0; q2 < 2; q2++)
                        mma_f16(oacc[dvc * 16 + p * 2 + q2], Pf[ks], vh[q2]);
                }
            }
        }
        __syncthreads();
    }

    const float i0 = 1.f / l0, i1 = 1.f / l1;
    const int r0 = qi * 128 + w * 16 + g;
    __half* o0 = Of + (size_t)r0 * HDQ + h * DV;
    __half* o1 = o0 + (size_t)8 * HDQ;
    #pragma unroll
    for (int nt = 0; nt < 32; nt++) {
        int c = nt * 8 + 2 * t4;
        __half2 v0 = __floats2half2_rn(oacc[nt][0] * i0, oacc[nt][1] * i0);
        __half2 v1 = __floats2half2_rn(oacc[nt][2] * i1, oacc[nt][3] * i1);
        *(__half2*)&o0[c] = v0;
        *(__half2*)&o1[c] = v1;
    }
}

// ---------------- fp32 -> fp16 ----------------
__global__ void conv_f16_k(const float* __restrict__ x, __half* __restrict__ h, long n)
{
    long i = (long)blockIdx.x * blockDim.x + threadIdx.x;
    long stride = (long)gridDim.x * blockDim.x;
    for (; i < n; i += stride) h[i] = __float2half_rn(x[i]);
}

// ---------------- fp32 [R,C] -> fp16 transposed [C,R] ----------------
__global__ void conv_tr_f16_k(const float* __restrict__ x, __half* __restrict__ h, int R, int C)
{
    __shared__ float tile[32][33];
    const int c0 = blockIdx.x * 32, rr0 = blockIdx.y * 32;
    const int tx = threadIdx.x & 31, ty = threadIdx.x >> 5;
    #pragma unroll
    for (int i = 0; i < 4; i++) {
        int r = rr0 + ty + i * 8;
        tile[ty + i * 8][tx] = x[(long)r * C + c0 + tx];
    }
    __syncthreads();
    #pragma unroll
    for (int i = 0; i < 4; i++) {
        int c = c0 + ty + i * 8;
        long o = (long)c * R + rr0 + tx;
        h[o] = __float2half_rn(tile[tx][ty + i * 8]);
    }
}

// ---------------- RMSNorm from 2 fp32 partials -> fp16 ----------------
__global__ void rmsnorm_2p_k(const float* __restrict__ p0, const float* __restrict__ p1,
                             const float* __restrict__ w, __half* __restrict__ o,
                             int N, int ldin)
{
    long rb = (long)blockIdx.x * ldin;
    __shared__ float red[8];
    __shared__ float bc;
    const int lane = threadIdx.x & 31, wid = threadIdx.x >> 5;

    float s = 0.f;
    for (int j = threadIdx.x; j < N; j += blockDim.x) {
        float v = p0[rb + j] + p1[rb + j];
        s += v * v;
    }
    #pragma unroll
    for (int of = 16; of; of >>= 1) s += __shfl_xor_sync(0xffffffffu, s, of);
    if (lane == 0) red[wid] = s;
    __syncthreads();
    if (threadIdx.x == 0) {
        float v = 0.f;
        for (int wI = 0; wI < 8; wI++) v += red[wI];
        bc = rsqrtf(v / N + 1e-6f);
    }
    __syncthreads();
    float r = bc;
    long ob = (long)blockIdx.x * N;
    for (int j = threadIdx.x; j < N; j += blockDim.x) {
        float v = p0[rb + j] + p1[rb + j];
        o[ob + j] = __float2half_rn(v * r * w[j]);
    }
}

// ---------------- rope k_pe from 2 fp32 partials -> fp16 kpe ----------------
__global__ void rope_kpe_2p_k(const float* __restrict__ p0, const float* __restrict__ p1,
                              const int* __restrict__ pos, __half* __restrict__ kpe)
{
    const int tt = blockIdx.x, i = threadIdx.x;
    double inv = pow(10000.0, -(double)i / 32.0);
    double sd, cd;
    sincos((double)pos[tt] * inv, &sd, &cd);
    float c = (float)cd, s = (float)sd;
    long rb = (long)tt * DPW + QLORA + DKV;
    float x1 = p0[rb + i]      + p1[rb + i];
    float x2 = p0[rb + i + 32] + p1[rb + i + 32];
    kpe[(long)tt * DR + i]      = __float2half_rn(x1 * c - x2 * s);
    kpe[(long)tt * DR + i + 32] = __float2half_rn(x2 * c + x1 * s);
}

// ---------------- rope q in-place (one block per token, 8 warps over heads) ----
__global__ void rope_q_inpl_k(__half* __restrict__ q, const int* __restrict__ pos)
{
    const int tt = blockIdx.x;
    const int i = threadIdx.x & 31, wg = threadIdx.x >> 5;
    double inv = pow(10000.0, -(double)i / 32.0);
    double sd, cd;
    sincos((double)pos[tt] * inv, &sd, &cd);
    float c = (float)cd, s = (float)sd;
    for (int h = wg; h < NH; h += 8) {
        __half* p = q + (size_t)tt * HDQ + h * DQ + DN;
        float x1 = __half2float(p[i]), x2 = __half2float(p[i + 32]);
        p[i]      = __float2half_rn(x1 * c - x2 * s);
        p[i + 32] = __float2half_rn(x2 * c + x1 * s);
    }
}

// ---------------- K assembly ----------------
__global__ void build_K_h_k(const __half* __restrict__ kv, const __half* __restrict__ kpe,
                            __half* __restrict__ Kc)
{
    const int tt = blockIdx.x;
    long ob = (long)tt * HDQ;
    for (int x = threadIdx.x; x < HDQ; x += blockDim.x) {
        int hd = x >> 8, d = x & 255;
        __half v = (d < DN) ? kv[(size_t)tt * KVW + hd * (DN + DV) + d]
                            : kpe[(long)tt * DR + (d - DN)];
        Kc[ob + x] = v;
    }
}

// ---------------- V transpose per head -> [h][DV][T] ----------------
__global__ void transpose_v_h_k(const __half* __restrict__ kv, __half* __restrict__ h)
{
    __shared__ __half tile[32][34];
    const int d0 = blockIdx.x * 32, t0 = blockIdx.y * 32, hd = blockIdx.z;
    const int tx = threadIdx.x & 31, ty = threadIdx.x >> 5;
    #pragma unroll
    for (int i = 0; i < 4; i++) {
        int tr = t0 + ty + i * 8;
        tile[ty + i * 8][tx] = kv[(size_t)tr * KVW + hd * (DN + DV) + DN + d0 + tx];
    }
    __syncthreads();
    #pragma unroll
    for (int i = 0; i < 4; i++) {
        int d = d0 + ty + i * 8;
        long o = (long)hd * DV * T + (long)d * T + t0 + tx;
        h[o] = tile[tx][ty + i * 8];
    }
}

// ---------------- 4-way fp32 reduction (wo partials -> out) ----------------
__global__ void reduce4_k(const float* __restrict__ p0, const float* __restrict__ p1,
                          const float* __restrict__ p2, const float* __restrict__ p3,
                          float* __restrict__ o, long n4)
{
    long i = (long)blockIdx.x * blockDim.x + threadIdx.x;
    long stride = (long)gridDim.x * blockDim.x;
    for (; i < n4; i += stride) {
        float4 a = ((const float4*)p0)[i];
        float4 b = ((const float4*)p1)[i];
        float4 c = ((const float4*)p2)[i];
        float4 d = ((const float4*)p3)[i];
        ((float4*)o)[i] = make_float4(a.x + b.x + c.x + d.x, a.y + b.y + c.y + d.y,
                                      a.z + b.z + c.z + d.z, a.w + b.w + c.w + d.w);
    }
}

// ---------------- launch ----------------
extern "C" void kernel_launch(void* const* d_in, const int* in_sizes, int n_in,
                              void* d_out, int out_size)
{
    (void)in_sizes; (void)n_in; (void)out_size;
    const float* hidden = (const float*)d_in[0];
    const int*   pos    = (const int*)  d_in[1];
    const float* wq_a   = (const float*)d_in[2];
    const float* q_ln   = (const float*)d_in[3];
    const float* wq_b   = (const float*)d_in[4];
    const float* wkv_a  = (const float*)d_in[5];
    const float* kv_ln  = (const float*)d_in[6];
    const float* wkv_b  = (const float*)d_in[7];
    const float* wo     = (const float*)d_in[8];
    float* out = (float*)d_out;

    cudaFuncSetAttribute(tgemm_1p<__half>, cudaFuncAttributeMaxDynamicSharedMemorySize, SMEM_1P);
    cudaFuncSetAttribute(tgemm_1p<float>,  cudaFuncAttributeMaxDynamicSharedMemorySize, SMEM_1P);
    cudaFuncSetAttribute(flash_k,          cudaFuncAttributeMaxDynamicSharedMemorySize, FA_SMEM);

    float *dpp, *outp;
    cudaGetSymbolAddress((void**)&dpp,  g_dp_part);
    cudaGetSymbolAddress((void**)&outp, g_out_part);

    __half *hidf, *qlof, *latf, *kpe, *qf, *kv16, *Ofp, *Kcf, *Vtf,
           *wdTf, *wqbTf, *wkvbTf, *woTf;
    cudaGetSymbolAddress((void**)&hidf,   g_hid_f);
    cudaGetSymbolAddress((void**)&qlof,   g_qlo_f);
    cudaGetSymbolAddress((void**)&latf,   g_lat_f);
    cudaGetSymbolAddress((void**)&kpe,    g_kpe);
    cudaGetSymbolAddress((void**)&qf,     g_qf);
    cudaGetSymbolAddress((void**)&kv16,   g_kv16);
    cudaGetSymbolAddress((void**)&Ofp,    g_Of);
    cudaGetSymbolAddress((void**)&Kcf,    g_Kc_f);
    cudaGetSymbolAddress((void**)&Vtf,    g_Vt_f);
    cudaGetSymbolAddress((void**)&wdTf,   g_wdTf);
    cudaGetSymbolAddress((void**)&wqbTf,  g_wqbTf);
    cudaGetSymbolAddress((void**)&wkvbTf, g_wkvbTf);
    cudaGetSymbolAddress((void**)&woTf,   g_woTf);

    const size_t nDP  = (size_t)T * DPW;
    const size_t nOut = (size_t)T * HID;

    dim3 blk(256);

    // ---- weight conversions ----
    conv_tr_f16_k<<<dim3(QLORA/32, HID/32), blk>>>(wq_a,  wdTf,                     HID, QLORA);
    conv_tr_f16_k<<<dim3(LATW/32,  HID/32), blk>>>(wkv_a, wdTf + (size_t)QLORA*HID, HID, LATW);
    conv_tr_f16_k<<<dim3(HDQ/32, QLORA/32), blk>>>(wq_b,  wqbTf,  QLORA, HDQ);
    conv_tr_f16_k<<<dim3(KVW/32,  DKV/32),  blk>>>(wkv_b, wkvbTf, DKV, KVW);
    conv_tr_f16_k<<<dim3(HID/32,  HDQ/32),  blk>>>(wo,    woTf,   HDQ, HID);
    conv_f16_k<<<2048, 256>>>(hidden, hidf, (long)T * HID);

    // ---- merged down projection, split-K=2 (fp32 partials) ----
    tgemm_1p<float><<<dim3((DPW + 127)/128, T/128, 2), blk, SMEM_1P>>>(hidf, wdTf,
        dpp, T, DPW, HID / 2, HID, HID, DPW, (long)nDP);

    // ---- rope(k_pe) + norms, consuming partials directly ----
    rope_kpe_2p_k<<<T, 32>>>(dpp, dpp + nDP, pos, kpe);
    rmsnorm_2p_k<<<T, 256>>>(dpp,         dpp + nDP,         q_ln,  qlof, QLORA, DPW);
    rmsnorm_2p_k<<<T, 256>>>(dpp + QLORA, dpp + nDP + QLORA, kv_ln, latf, DKV,   DPW);

    // ---- up projections (fp16 out) ----
    tgemm_1p<__half><<<dim3(HDQ/128, T/128), blk, SMEM_1P>>>(qlof, wqbTf,
        qf, T, HDQ, QLORA, QLORA, QLORA, HDQ, 0);
    tgemm_1p<__half><<<dim3(KVW/128, T/128), blk, SMEM_1P>>>(latf, wkvbTf,
        kv16, T, KVW, DKV, DKV, DKV, KVW, 0);

    // ---- q rope in place; K assembly; V transpose ----
    rope_q_inpl_k<<<T, 256>>>(qf, pos);
    build_K_h_k<<<T, 256>>>(kv16, kpe, Kcf);
    transpose_v_h_k<<<dim3(DV/32, T/32, NH), blk>>>(kv16, Vtf);

    // ---- fused flash attention ----
    flash_k<<<dim3(T/128, NH), blk, FA_SMEM>>>(qf, Kcf, Vtf, Ofp);

    // ---- final projection, split-K=4 + reduction ----
    tgemm_1p<float><<<dim3(HID/128, T/128, 4), blk, SMEM_1P>>>(Ofp, woTf,
        outp, T, HID, HDQ / 4, HDQ, HDQ, HID, (long)nOut);
    reduce4_k<<<1024, 256>>>(outp, outp + nOut, outp + 2 * nOut, outp + 3 * nOut,
        out, (long)(nOut / 4));
}